// round 3
// baseline (speedup 1.0000x reference)
#include <cuda_runtime.h>

// Problem constants
#define PB 4
#define PS 2048
#define PE 1024
#define PH 16
#define PD 64
#define PM (PB * PS)   // 8192

// Scratch (device globals: allocation-free)
__device__ float g_Q[PB * PH * PS * PD];
__device__ float g_K[PB * PH * PS * PD];
__device__ float g_V[PB * PH * PS * PD];
__device__ float g_Ctx[PB * PS * PE];

// ---------------------------------------------------------------------------
// GEMM (NT): C[m,n] = sum_k A[m,k] * W[n,k],  M=8192, N=1024, K=1024
// 128x128 tile, BK=16, 256 threads, 8x8 per thread, float4 smem reads.
// DST: 0->g_Q, 1->g_K, 2->g_V, 3->Cparam (plain row-major)
// SRCCTX: use g_Ctx as A
// DST<3 scatters C[m,n] into [b,h,s,d] layout.
// ---------------------------------------------------------------------------
template <int DST, bool SRCCTX>
__global__ __launch_bounds__(256) void gemm_nt_kernel(
    const float* __restrict__ Aparam,
    const float* __restrict__ W,
    float* __restrict__ Cparam)
{
    constexpr int K = PE;
    constexpr int N = PE;
    __shared__ float As[16][132];
    __shared__ float Ws[16][132];

    const float* A = SRCCTX ? (const float*)g_Ctx : Aparam;

    const int tid = threadIdx.x;
    const int bm = blockIdx.y;
    const int bn = blockIdx.x;
    const int tx = tid & 15;
    const int ty = tid >> 4;

    float acc[8][8];
#pragma unroll
    for (int i = 0; i < 8; i++)
#pragma unroll
        for (int j = 0; j < 8; j++) acc[i][j] = 0.0f;

    for (int kt = 0; kt < K; kt += 16) {
#pragma unroll
        for (int it = 0; it < 2; it++) {
            int f = tid + it * 256;            // 0..511 float4 slots
            int row = f >> 2;                  // 0..127
            int q = (f & 3) * 4;               // 0,4,8,12
            float4 av = *(const float4*)&A[(size_t)(bm * 128 + row) * K + kt + q];
            As[q + 0][row] = av.x; As[q + 1][row] = av.y;
            As[q + 2][row] = av.z; As[q + 3][row] = av.w;
            float4 wv = *(const float4*)&W[(size_t)(bn * 128 + row) * K + kt + q];
            Ws[q + 0][row] = wv.x; Ws[q + 1][row] = wv.y;
            Ws[q + 2][row] = wv.z; Ws[q + 3][row] = wv.w;
        }
        __syncthreads();

#pragma unroll
        for (int kk = 0; kk < 16; kk++) {
            float a[8], b[8];
            *(float4*)&a[0] = *(const float4*)&As[kk][ty * 8];
            *(float4*)&a[4] = *(const float4*)&As[kk][ty * 8 + 4];
            *(float4*)&b[0] = *(const float4*)&Ws[kk][tx * 8];
            *(float4*)&b[4] = *(const float4*)&Ws[kk][tx * 8 + 4];
#pragma unroll
            for (int i = 0; i < 8; i++)
#pragma unroll
                for (int j = 0; j < 8; j++)
                    acc[i][j] += a[i] * b[j];
        }
        __syncthreads();
    }

    // Epilogue
    if (DST < 3) {
        float* C = (DST == 0) ? g_Q : (DST == 1) ? g_K : g_V;
#pragma unroll
        for (int i = 0; i < 8; i++) {
            int m = bm * 128 + ty * 8 + i;
            int bb = m >> 11;          // / PS
            int s = m & (PS - 1);
#pragma unroll
            for (int jv = 0; jv < 2; jv++) {
                int n = bn * 128 + tx * 8 + jv * 4;
                int h = n >> 6;
                int d = n & 63;
                float4 v = make_float4(acc[i][jv * 4 + 0], acc[i][jv * 4 + 1],
                                       acc[i][jv * 4 + 2], acc[i][jv * 4 + 3]);
                *(float4*)&C[((size_t)(bb * PH + h) * PS + s) * PD + d] = v;
            }
        }
    } else {
#pragma unroll
        for (int i = 0; i < 8; i++) {
            int m = bm * 128 + ty * 8 + i;
#pragma unroll
            for (int jv = 0; jv < 2; jv++) {
                int n = bn * 128 + tx * 8 + jv * 4;
                float4 v = make_float4(acc[i][jv * 4 + 0], acc[i][jv * 4 + 1],
                                       acc[i][jv * 4 + 2], acc[i][jv * 4 + 3]);
                *(float4*)&Cparam[(size_t)m * N + n] = v;
            }
        }
    }
}

// ---------------------------------------------------------------------------
// Flash attention: per block (q-tile of 64, head, batch). 256 threads.
// Smem: Qs[64x64] + KPs[64x64] (K transposed, later reused for P) + Vs[64x64]
//       = exactly 48 KB.
// Thread (ty,tx) owns rows 4*ty+i, cols 4*tx+j (4x4).
// Writes context * gamma into g_Ctx in [b, s, h*D+d] layout.
// ---------------------------------------------------------------------------
__global__ __launch_bounds__(256) void attn_kernel(
    const unsigned char* __restrict__ mask,
    const float* __restrict__ gamma)
{
    __shared__ float Qs[64 * 64];
    __shared__ float KPs[64 * 64];
    __shared__ float Vs[64 * 64];

    const int tid = threadIdx.x;
    const int qt = blockIdx.x;
    const int h  = blockIdx.y;
    const int b  = blockIdx.z;
    const int tx = tid & 15;
    const int ty = tid >> 4;

    const size_t headBase = (size_t)(b * PH + h) * PS * PD;
    const float* Qg = g_Q + headBase + (size_t)qt * 64 * PD;

#pragma unroll
    for (int it = 0; it < 4; it++) {
        int f = tid + it * 256;
        ((float4*)Qs)[f] = ((const float4*)Qg)[f];
    }

    float m_i[4], l_i[4], o[4][4];
#pragma unroll
    for (int i = 0; i < 4; i++) {
        m_i[i] = -3.0e38f;
        l_i[i] = 0.0f;
#pragma unroll
        for (int j = 0; j < 4; j++) o[i][j] = 0.0f;
    }

    const unsigned char* mrow = mask + (size_t)b * PS;

    for (int kt = 0; kt < PS / 64; kt++) {
        const float* Kg = g_K + headBase + (size_t)kt * 64 * PD;
        const float* Vg = g_V + headBase + (size_t)kt * 64 * PD;

        __syncthreads();  // previous iteration done with KPs/Vs (and Q visible on iter 0 path)
#pragma unroll
        for (int it = 0; it < 4; it++) {
            int f = tid + it * 256;
            int kk = f >> 4;
            int dq = (f & 15) * 4;
            float4 kv = ((const float4*)Kg)[f];
            KPs[(dq + 0) * 64 + kk] = kv.x;
            KPs[(dq + 1) * 64 + kk] = kv.y;
            KPs[(dq + 2) * 64 + kk] = kv.z;
            KPs[(dq + 3) * 64 + kk] = kv.w;
            ((float4*)Vs)[f] = ((const float4*)Vg)[f];
        }
        __syncthreads();

        // scores S = Q Kt  (64x64x64)
        float s[4][4];
#pragma unroll
        for (int i = 0; i < 4; i++)
#pragma unroll
            for (int j = 0; j < 4; j++) s[i][j] = 0.0f;

#pragma unroll 8
        for (int d = 0; d < 64; d++) {
            float a0 = Qs[(ty * 4 + 0) * 64 + d];
            float a1 = Qs[(ty * 4 + 1) * 64 + d];
            float a2 = Qs[(ty * 4 + 2) * 64 + d];
            float a3 = Qs[(ty * 4 + 3) * 64 + d];
            float4 bv = *(const float4*)&KPs[d * 64 + tx * 4];
            s[0][0] += a0 * bv.x; s[0][1] += a0 * bv.y; s[0][2] += a0 * bv.z; s[0][3] += a0 * bv.w;
            s[1][0] += a1 * bv.x; s[1][1] += a1 * bv.y; s[1][2] += a1 * bv.z; s[1][3] += a1 * bv.w;
            s[2][0] += a2 * bv.x; s[2][1] += a2 * bv.y; s[2][2] += a2 * bv.z; s[2][3] += a2 * bv.w;
            s[3][0] += a3 * bv.x; s[3][1] += a3 * bv.y; s[3][2] += a3 * bv.z; s[3][3] += a3 * bv.w;
        }

        // scale + padding mask
        uchar4 mv = *(const uchar4*)&mrow[kt * 64 + tx * 4];
        float mb[4];
        mb[0] = mv.x ? 1.0f : 0.0f;
        mb[1] = mv.y ? 1.0f : 0.0f;
        mb[2] = mv.z ? 1.0f : 0.0f;
        mb[3] = mv.w ? 1.0f : 0.0f;
#pragma unroll
        for (int i = 0; i < 4; i++)
#pragma unroll
            for (int j = 0; j < 4; j++) {
                float v = s[i][j] * 0.125f;   // 1/sqrt(64)
                s[i][j] = (mb[j] != 0.0f) ? -3.0e38f : v;
            }

        // online softmax (rows reduced across 16 lanes)
        float tm[4];
#pragma unroll
        for (int i = 0; i < 4; i++) {
            tm[i] = fmaxf(fmaxf(s[i][0], s[i][1]), fmaxf(s[i][2], s[i][3]));
#pragma unroll
            for (int off = 8; off >= 1; off >>= 1)
                tm[i] = fmaxf(tm[i], __shfl_xor_sync(0xffffffffu, tm[i], off, 16));
        }

        float p[4][4], rs[4], csc[4];
#pragma unroll
        for (int i = 0; i < 4; i++) {
            float mn = fmaxf(m_i[i], tm[i]);
            csc[i] = __expf(m_i[i] - mn);
            m_i[i] = mn;
            float acc = 0.0f;
#pragma unroll
            for (int j = 0; j < 4; j++) {
                p[i][j] = __expf(s[i][j] - mn);
                acc += p[i][j];
            }
            rs[i] = acc;
#pragma unroll
            for (int off = 8; off >= 1; off >>= 1)
                rs[i] += __shfl_xor_sync(0xffffffffu, rs[i], off, 16);
            l_i[i] = l_i[i] * csc[i] + rs[i];
#pragma unroll
            for (int j = 0; j < 4; j++) o[i][j] *= csc[i];
        }

        __syncthreads();  // all threads done reading KPs as K
#pragma unroll
        for (int i = 0; i < 4; i++)
            *(float4*)&KPs[(ty * 4 + i) * 64 + tx * 4] =
                make_float4(p[i][0], p[i][1], p[i][2], p[i][3]);
        __syncthreads();

        // O += P V  (64x64x64)
#pragma unroll 8
        for (int k = 0; k < 64; k++) {
            float p0 = KPs[(ty * 4 + 0) * 64 + k];
            float p1 = KPs[(ty * 4 + 1) * 64 + k];
            float p2 = KPs[(ty * 4 + 2) * 64 + k];
            float p3 = KPs[(ty * 4 + 3) * 64 + k];
            float4 vv = *(const float4*)&Vs[k * 64 + tx * 4];
            o[0][0] += p0 * vv.x; o[0][1] += p0 * vv.y; o[0][2] += p0 * vv.z; o[0][3] += p0 * vv.w;
            o[1][0] += p1 * vv.x; o[1][1] += p1 * vv.y; o[1][2] += p1 * vv.z; o[1][3] += p1 * vv.w;
            o[2][0] += p2 * vv.x; o[2][1] += p2 * vv.y; o[2][2] += p2 * vv.z; o[2][3] += p2 * vv.w;
            o[3][0] += p3 * vv.x; o[3][1] += p3 * vv.y; o[3][2] += p3 * vv.z; o[3][3] += p3 * vv.w;
        }
    }

    const float gsc = gamma[h];
    float* Og = g_Ctx + ((size_t)b * PS + (size_t)qt * 64) * PE + h * PD;
#pragma unroll
    for (int i = 0; i < 4; i++) {
        float inv = gsc / l_i[i];
        float4 ov = make_float4(o[i][0] * inv, o[i][1] * inv,
                                o[i][2] * inv, o[i][3] * inv);
        *(float4*)&Og[(size_t)(ty * 4 + i) * PE + tx * 4] = ov;
    }
}

// ---------------------------------------------------------------------------
extern "C" void kernel_launch(void* const* d_in, const int* in_sizes, int n_in,
                              void* d_out, int out_size)
{
    const float* query = (const float*)d_in[0];
    const float* key   = (const float*)d_in[1];
    const float* value = (const float*)d_in[2];
    const unsigned char* mask = (const unsigned char*)d_in[3];
    const float* Wq = (const float*)d_in[4];
    const float* Wk = (const float*)d_in[5];
    const float* Wv = (const float*)d_in[6];
    const float* Wo = (const float*)d_in[7];
    const float* gamma = (const float*)d_in[8];

    dim3 gp(PE / 128, PM / 128);   // (8, 64)
    gemm_nt_kernel<0, false><<<gp, 256>>>(query, Wq, nullptr);
    gemm_nt_kernel<1, false><<<gp, 256>>>(key, Wk, nullptr);
    gemm_nt_kernel<2, false><<<gp, 256>>>(value, Wv, nullptr);

    attn_kernel<<<dim3(PS / 64, PH, PB), 256>>>(mask, gamma);

    gemm_nt_kernel<3, true><<<gp, 256>>>(nullptr, Wo, (float*)d_out);
}

// round 5
// speedup vs baseline: 1.2304x; 1.2304x over previous
#include <cuda_runtime.h>
#include <cuda_bf16.h>
#include <cstdint>

// Problem constants
#define PB 4
#define PS 2048
#define PE 1024
#define PH 16
#define PD 64
#define PM (PB * PS)   // 8192

// Scratch (device globals: allocation-free)
__device__ float g_Q[PB * PH * PS * PD];
__device__ float g_K[PB * PH * PS * PD];
__device__ float g_V[PB * PH * PS * PD];
__device__ float g_Ctx[PB * PS * PE];

// ===========================================================================
// helpers
// ===========================================================================
__device__ __forceinline__ uint32_t smem_u32(const void* p) {
    uint32_t a;
    asm("{ .reg .u64 t; cvta.to.shared.u64 t, %1; cvt.u32.u64 %0, t; }"
        : "=r"(a) : "l"(p));
    return a;
}

__device__ __forceinline__ void ldsm_x4(uint32_t* r, uint32_t addr) {
    asm volatile("ldmatrix.sync.aligned.m8n8.x4.shared.b16 {%0,%1,%2,%3}, [%4];"
                 : "=r"(r[0]), "=r"(r[1]), "=r"(r[2]), "=r"(r[3]) : "r"(addr));
}
__device__ __forceinline__ void ldsm_x2(uint32_t* r, uint32_t addr) {
    asm volatile("ldmatrix.sync.aligned.m8n8.x2.shared.b16 {%0,%1}, [%2];"
                 : "=r"(r[0]), "=r"(r[1]) : "r"(addr));
}

__device__ __forceinline__ void mma_bf16(float* c, const uint32_t* a, const uint32_t* b) {
    asm volatile(
        "mma.sync.aligned.m16n8k16.row.col.f32.bf16.bf16.f32 "
        "{%0,%1,%2,%3}, {%4,%5,%6,%7}, {%8,%9}, {%0,%1,%2,%3};"
        : "+f"(c[0]), "+f"(c[1]), "+f"(c[2]), "+f"(c[3])
        : "r"(a[0]), "r"(a[1]), "r"(a[2]), "r"(a[3]), "r"(b[0]), "r"(b[1]));
}

// fp32 -> (hi, lo) bf16 split, packed as bf16x2 words
__device__ __forceinline__ void split2(float x, float y, uint32_t& hi, uint32_t& lo) {
    __nv_bfloat16 hx = __float2bfloat16_rn(x);
    __nv_bfloat16 hy = __float2bfloat16_rn(y);
    float rx = x - __bfloat162float(hx);
    float ry = y - __bfloat162float(hy);
    __nv_bfloat16 lx = __float2bfloat16_rn(rx);
    __nv_bfloat16 ly = __float2bfloat16_rn(ry);
    hi = ((uint32_t)__bfloat16_as_ushort(hy) << 16) | (uint32_t)__bfloat16_as_ushort(hx);
    lo = ((uint32_t)__bfloat16_as_ushort(ly) << 16) | (uint32_t)__bfloat16_as_ushort(lx);
}

// ===========================================================================
// mma.sync GEMM (NT): C[m,n] = sum_k A[m,k] * W[n,k]
// M=8192, N=1024, K=1024. CTA: 128x128 tile, BK=64, 256 threads.
// Split bf16: D += Ahi*Bhi + Ahi*Blo + Alo*Bhi (fp32 accum in registers).
// SMEM rows padded to 72 bf16 (144B) -> conflict-free ldmatrix.
// DST: 0->g_Q, 1->g_K, 2->g_V (scatter to [b,h,s,d]), 3->Cparam row-major.
// ===========================================================================
#define G_RS 72
#define G_TILE_B (128 * G_RS * 2)        // 18432
#define OFF_ALO (G_TILE_B)
#define OFF_BHI (2 * G_TILE_B)
#define OFF_BLO (3 * G_TILE_B)
#define G_SMEM  (4 * G_TILE_B)           // 73728

template <int DST, bool SRCCTX>
__global__ __launch_bounds__(256, 2) void gemm_mma_kernel(
    const float* __restrict__ Aparam,
    const float* __restrict__ W,
    float* __restrict__ Cparam)
{
    extern __shared__ __align__(16) char smem[];
    const uint32_t sbase = smem_u32(smem);

    const float* A = SRCCTX ? (const float*)g_Ctx : Aparam;

    const int tid  = threadIdx.x;
    const int lane = tid & 31;
    const int warp = tid >> 5;
    const int wm = warp >> 2;       // 0..1
    const int wn = warp & 3;        // 0..3
    const int bm = blockIdx.y;
    const int bn = blockIdx.x;

    float acc[4][4][4];
#pragma unroll
    for (int i = 0; i < 4; i++)
#pragma unroll
        for (int j = 0; j < 4; j++)
#pragma unroll
            for (int q = 0; q < 4; q++) acc[i][j][q] = 0.0f;

    // global load mapping: thread -> (row, 32-col span)
    const int lrow = tid >> 1;              // 0..127
    const int lcol = (tid & 1) * 32;        // 0 or 32
    const float* Ag = A + (size_t)(bm * 128 + lrow) * PE + lcol;
    const float* Bg = W + (size_t)(bn * 128 + lrow) * PE + lcol;

    // smem byte offsets for this thread's stores
    char* stA = smem + (lrow * G_RS + lcol) * 2;
    char* stB = stA + OFF_BHI;

    // ldmatrix addresses (per ks they get +2*ks bytes... computed inline)
    const int a_r = wm * 64 + (lane & 15);
    const int a_c = (lane >> 4) * 8;
    const uint32_t a_addr0 = sbase + (a_r * G_RS + a_c) * 2;
    const int b_r = wn * 32 + (lane & 7);
    const int b_c = ((lane >> 3) & 1) * 8;
    const uint32_t b_addr0 = sbase + OFF_BHI + (b_r * G_RS + b_c) * 2;

    for (int s = 0; s < PE / 64; s++) {
        const float* Ags = Ag + s * 64;
        const float* Bgs = Bg + s * 64;

        // ---- half 0: cols 0..15 of this thread's span ----
        float4 av[4], bv[4];
#pragma unroll
        for (int q = 0; q < 4; q++) av[q] = *(const float4*)(Ags + q * 4);
#pragma unroll
        for (int q = 0; q < 4; q++) bv[q] = *(const float4*)(Bgs + q * 4);

        __syncthreads();   // previous stage compute done

#pragma unroll
        for (int q = 0; q < 4; q++) {
            uint32_t h0, l0, h1, l1;
            split2(av[q].x, av[q].y, h0, l0);
            split2(av[q].z, av[q].w, h1, l1);
            *(uint2*)(stA + q * 8)           = make_uint2(h0, h1);
            *(uint2*)(stA + OFF_ALO + q * 8) = make_uint2(l0, l1);
            split2(bv[q].x, bv[q].y, h0, l0);
            split2(bv[q].z, bv[q].w, h1, l1);
            *(uint2*)(stB + q * 8)                         = make_uint2(h0, h1);
            *(uint2*)(stB + (OFF_BLO - OFF_BHI) + q * 8)   = make_uint2(l0, l1);
        }

        // ---- half 1: cols 16..31 ----
#pragma unroll
        for (int q = 0; q < 4; q++) av[q] = *(const float4*)(Ags + 16 + q * 4);
#pragma unroll
        for (int q = 0; q < 4; q++) bv[q] = *(const float4*)(Bgs + 16 + q * 4);
#pragma unroll
        for (int q = 0; q < 4; q++) {
            uint32_t h0, l0, h1, l1;
            split2(av[q].x, av[q].y, h0, l0);
            split2(av[q].z, av[q].w, h1, l1);
            *(uint2*)(stA + 32 + q * 8)           = make_uint2(h0, h1);
            *(uint2*)(stA + OFF_ALO + 32 + q * 8) = make_uint2(l0, l1);
            split2(bv[q].x, bv[q].y, h0, l0);
            split2(bv[q].z, bv[q].w, h1, l1);
            *(uint2*)(stB + 32 + q * 8)                       = make_uint2(h0, h1);
            *(uint2*)(stB + (OFF_BLO - OFF_BHI) + 32 + q * 8) = make_uint2(l0, l1);
        }
        __syncthreads();

        // ---- compute: 4 k16-steps ----
#pragma unroll
        for (int ks = 0; ks < 64; ks += 16) {
            uint32_t bh[4][2], bl[4][2];
#pragma unroll
            for (int ni = 0; ni < 4; ni++) {
                uint32_t ba = b_addr0 + (ni * 8 * G_RS + ks) * 2;
                ldsm_x2(bh[ni], ba);
                ldsm_x2(bl[ni], ba + (OFF_BLO - OFF_BHI));
            }
#pragma unroll
            for (int mi = 0; mi < 4; mi++) {
                uint32_t ah[4], al[4];
                uint32_t aa = a_addr0 + (mi * 16 * G_RS + ks) * 2;
                ldsm_x4(ah, aa);
                ldsm_x4(al, aa + OFF_ALO);
#pragma unroll
                for (int ni = 0; ni < 4; ni++) {
                    mma_bf16(acc[mi][ni], ah, bh[ni]);
                    mma_bf16(acc[mi][ni], ah, bl[ni]);
                    mma_bf16(acc[mi][ni], al, bh[ni]);
                }
            }
        }
    }

    // ---- epilogue ----
    float* Cdst = (DST == 0) ? g_Q : (DST == 1) ? g_K : (DST == 2) ? g_V : Cparam;
#pragma unroll
    for (int mi = 0; mi < 4; mi++) {
        const int m0 = bm * 128 + wm * 64 + mi * 16 + (lane >> 2);
#pragma unroll
        for (int half = 0; half < 2; half++) {
            const int m = m0 + half * 8;
            const int bb = m >> 11;
            const int ms = m & (PS - 1);
#pragma unroll
            for (int ni = 0; ni < 4; ni++) {
                const int n = bn * 128 + wn * 32 + ni * 8 + (lane & 3) * 2;
                float2 v = make_float2(acc[mi][ni][half * 2 + 0],
                                       acc[mi][ni][half * 2 + 1]);
                if (DST < 3) {
                    const int h = n >> 6;
                    const int d = n & 63;
                    *(float2*)&Cdst[((size_t)(bb * PH + h) * PS + ms) * PD + d] = v;
                } else {
                    *(float2*)&Cdst[(size_t)m * PE + n] = v;
                }
            }
        }
    }
}

// ---------------------------------------------------------------------------
// Flash attention (fp32, unchanged — passed R3): block = (q-tile 64, head, batch)
// ---------------------------------------------------------------------------
__global__ __launch_bounds__(256) void attn_kernel(
    const unsigned char* __restrict__ mask,
    const float* __restrict__ gamma)
{
    __shared__ float Qs[64 * 64];
    __shared__ float KPs[64 * 64];
    __shared__ float Vs[64 * 64];

    const int tid = threadIdx.x;
    const int qt = blockIdx.x;
    const int h  = blockIdx.y;
    const int b  = blockIdx.z;
    const int tx = tid & 15;
    const int ty = tid >> 4;

    const size_t headBase = (size_t)(b * PH + h) * PS * PD;
    const float* Qg = g_Q + headBase + (size_t)qt * 64 * PD;

#pragma unroll
    for (int it = 0; it < 4; it++) {
        int f = tid + it * 256;
        ((float4*)Qs)[f] = ((const float4*)Qg)[f];
    }

    float m_i[4], l_i[4], o[4][4];
#pragma unroll
    for (int i = 0; i < 4; i++) {
        m_i[i] = -3.0e38f;
        l_i[i] = 0.0f;
#pragma unroll
        for (int j = 0; j < 4; j++) o[i][j] = 0.0f;
    }

    const unsigned char* mrow = mask + (size_t)b * PS;

    for (int kt = 0; kt < PS / 64; kt++) {
        const float* Kg = g_K + headBase + (size_t)kt * 64 * PD;
        const float* Vg = g_V + headBase + (size_t)kt * 64 * PD;

        __syncthreads();
#pragma unroll
        for (int it = 0; it < 4; it++) {
            int f = tid + it * 256;
            int kk = f >> 4;
            int dq = (f & 15) * 4;
            float4 kv = ((const float4*)Kg)[f];
            KPs[(dq + 0) * 64 + kk] = kv.x;
            KPs[(dq + 1) * 64 + kk] = kv.y;
            KPs[(dq + 2) * 64 + kk] = kv.z;
            KPs[(dq + 3) * 64 + kk] = kv.w;
            ((float4*)Vs)[f] = ((const float4*)Vg)[f];
        }
        __syncthreads();

        float s[4][4];
#pragma unroll
        for (int i = 0; i < 4; i++)
#pragma unroll
            for (int j = 0; j < 4; j++) s[i][j] = 0.0f;

#pragma unroll 8
        for (int d = 0; d < 64; d++) {
            float a0 = Qs[(ty * 4 + 0) * 64 + d];
            float a1 = Qs[(ty * 4 + 1) * 64 + d];
            float a2 = Qs[(ty * 4 + 2) * 64 + d];
            float a3 = Qs[(ty * 4 + 3) * 64 + d];
            float4 bv = *(const float4*)&KPs[d * 64 + tx * 4];
            s[0][0] += a0 * bv.x; s[0][1] += a0 * bv.y; s[0][2] += a0 * bv.z; s[0][3] += a0 * bv.w;
            s[1][0] += a1 * bv.x; s[1][1] += a1 * bv.y; s[1][2] += a1 * bv.z; s[1][3] += a1 * bv.w;
            s[2][0] += a2 * bv.x; s[2][1] += a2 * bv.y; s[2][2] += a2 * bv.z; s[2][3] += a2 * bv.w;
            s[3][0] += a3 * bv.x; s[3][1] += a3 * bv.y; s[3][2] += a3 * bv.z; s[3][3] += a3 * bv.w;
        }

        uchar4 mv = *(const uchar4*)&mrow[kt * 64 + tx * 4];
        float mb[4];
        mb[0] = mv.x ? 1.0f : 0.0f;
        mb[1] = mv.y ? 1.0f : 0.0f;
        mb[2] = mv.z ? 1.0f : 0.0f;
        mb[3] = mv.w ? 1.0f : 0.0f;
#pragma unroll
        for (int i = 0; i < 4; i++)
#pragma unroll
            for (int j = 0; j < 4; j++) {
                float v = s[i][j] * 0.125f;
                s[i][j] = (mb[j] != 0.0f) ? -3.0e38f : v;
            }

        float tm[4];
#pragma unroll
        for (int i = 0; i < 4; i++) {
            tm[i] = fmaxf(fmaxf(s[i][0], s[i][1]), fmaxf(s[i][2], s[i][3]));
#pragma unroll
            for (int off = 8; off >= 1; off >>= 1)
                tm[i] = fmaxf(tm[i], __shfl_xor_sync(0xffffffffu, tm[i], off, 16));
        }

        float p[4][4], rs[4], csc[4];
#pragma unroll
        for (int i = 0; i < 4; i++) {
            float mn = fmaxf(m_i[i], tm[i]);
            csc[i] = __expf(m_i[i] - mn);
            m_i[i] = mn;
            float acc2 = 0.0f;
#pragma unroll
            for (int j = 0; j < 4; j++) {
                p[i][j] = __expf(s[i][j] - mn);
                acc2 += p[i][j];
            }
            rs[i] = acc2;
#pragma unroll
            for (int off = 8; off >= 1; off >>= 1)
                rs[i] += __shfl_xor_sync(0xffffffffu, rs[i], off, 16);
            l_i[i] = l_i[i] * csc[i] + rs[i];
#pragma unroll
            for (int j = 0; j < 4; j++) o[i][j] *= csc[i];
        }

        __syncthreads();
#pragma unroll
        for (int i = 0; i < 4; i++)
            *(float4*)&KPs[(ty * 4 + i) * 64 + tx * 4] =
                make_float4(p[i][0], p[i][1], p[i][2], p[i][3]);
        __syncthreads();

#pragma unroll 8
        for (int k = 0; k < 64; k++) {
            float p0 = KPs[(ty * 4 + 0) * 64 + k];
            float p1 = KPs[(ty * 4 + 1) * 64 + k];
            float p2 = KPs[(ty * 4 + 2) * 64 + k];
            float p3 = KPs[(ty * 4 + 3) * 64 + k];
            float4 vv = *(const float4*)&Vs[k * 64 + tx * 4];
            o[0][0] += p0 * vv.x; o[0][1] += p0 * vv.y; o[0][2] += p0 * vv.z; o[0][3] += p0 * vv.w;
            o[1][0] += p1 * vv.x; o[1][1] += p1 * vv.y; o[1][2] += p1 * vv.z; o[1][3] += p1 * vv.w;
            o[2][0] += p2 * vv.x; o[2][1] += p2 * vv.y; o[2][2] += p2 * vv.z; o[2][3] += p2 * vv.w;
            o[3][0] += p3 * vv.x; o[3][1] += p3 * vv.y; o[3][2] += p3 * vv.z; o[3][3] += p3 * vv.w;
        }
    }

    const float gsc = gamma[h];
    float* Og = g_Ctx + ((size_t)b * PS + (size_t)qt * 64) * PE + h * PD;
#pragma unroll
    for (int i = 0; i < 4; i++) {
        float inv = gsc / l_i[i];
        float4 ov = make_float4(o[i][0] * inv, o[i][1] * inv,
                                o[i][2] * inv, o[i][3] * inv);
        *(float4*)&Og[(size_t)(ty * 4 + i) * PE + tx * 4] = ov;
    }
}

// ---------------------------------------------------------------------------
extern "C" void kernel_launch(void* const* d_in, const int* in_sizes, int n_in,
                              void* d_out, int out_size)
{
    const float* query = (const float*)d_in[0];
    const float* key   = (const float*)d_in[1];
    const float* value = (const float*)d_in[2];
    const unsigned char* mask = (const unsigned char*)d_in[3];
    const float* Wq = (const float*)d_in[4];
    const float* Wk = (const float*)d_in[5];
    const float* Wv = (const float*)d_in[6];
    const float* Wo = (const float*)d_in[7];
    const float* gamma = (const float*)d_in[8];

    cudaFuncSetAttribute(gemm_mma_kernel<0, false>,
                         cudaFuncAttributeMaxDynamicSharedMemorySize, G_SMEM);
    cudaFuncSetAttribute(gemm_mma_kernel<1, false>,
                         cudaFuncAttributeMaxDynamicSharedMemorySize, G_SMEM);
    cudaFuncSetAttribute(gemm_mma_kernel<2, false>,
                         cudaFuncAttributeMaxDynamicSharedMemorySize, G_SMEM);
    cudaFuncSetAttribute(gemm_mma_kernel<3, true>,
                         cudaFuncAttributeMaxDynamicSharedMemorySize, G_SMEM);

    dim3 gp(PE / 128, PM / 128);   // (8, 64)
    gemm_mma_kernel<0, false><<<gp, 256, G_SMEM>>>(query, Wq, nullptr);
    gemm_mma_kernel<1, false><<<gp, 256, G_SMEM>>>(key, Wk, nullptr);
    gemm_mma_kernel<2, false><<<gp, 256, G_SMEM>>>(value, Wv, nullptr);

    attn_kernel<<<dim3(PS / 64, PH, PB), 256>>>(mask, gamma);

    gemm_mma_kernel<3, true><<<gp, 256, G_SMEM>>>(nullptr, Wo, (float*)d_out);
}

// round 6
// speedup vs baseline: 1.9108x; 1.5530x over previous
#include <cuda_runtime.h>
#include <cuda_bf16.h>
#include <cstdint>

// Problem constants
#define PB 4
#define PS 2048
#define PE 1024
#define PH 16
#define PD 64
#define PM (PB * PS)   // 8192

// Scratch (device globals: allocation-free)
__device__ float g_Q[PB * PH * PS * PD];
__device__ float g_K[PB * PH * PS * PD];
__device__ float g_V[PB * PH * PS * PD];
__device__ float g_Ctx[PB * PS * PE];

// ===========================================================================
// helpers
// ===========================================================================
__device__ __forceinline__ uint32_t smem_u32(const void* p) {
    uint32_t a;
    asm("{ .reg .u64 t; cvta.to.shared.u64 t, %1; cvt.u32.u64 %0, t; }"
        : "=r"(a) : "l"(p));
    return a;
}

__device__ __forceinline__ void ldsm_x4(uint32_t* r, uint32_t addr) {
    asm volatile("ldmatrix.sync.aligned.m8n8.x4.shared.b16 {%0,%1,%2,%3}, [%4];"
                 : "=r"(r[0]), "=r"(r[1]), "=r"(r[2]), "=r"(r[3]) : "r"(addr));
}
__device__ __forceinline__ void ldsm_x2(uint32_t* r, uint32_t addr) {
    asm volatile("ldmatrix.sync.aligned.m8n8.x2.shared.b16 {%0,%1}, [%2];"
                 : "=r"(r[0]), "=r"(r[1]) : "r"(addr));
}
__device__ __forceinline__ void ldsm_x2_t(uint32_t* r, uint32_t addr) {
    asm volatile("ldmatrix.sync.aligned.m8n8.x2.trans.shared.b16 {%0,%1}, [%2];"
                 : "=r"(r[0]), "=r"(r[1]) : "r"(addr));
}

__device__ __forceinline__ void mma_bf16(float* c, const uint32_t* a, const uint32_t* b) {
    asm volatile(
        "mma.sync.aligned.m16n8k16.row.col.f32.bf16.bf16.f32 "
        "{%0,%1,%2,%3}, {%4,%5,%6,%7}, {%8,%9}, {%0,%1,%2,%3};"
        : "+f"(c[0]), "+f"(c[1]), "+f"(c[2]), "+f"(c[3])
        : "r"(a[0]), "r"(a[1]), "r"(a[2]), "r"(a[3]), "r"(b[0]), "r"(b[1]));
}

// fp32 -> (hi, lo) bf16 split, packed as bf16x2 words
__device__ __forceinline__ void split2(float x, float y, uint32_t& hi, uint32_t& lo) {
    __nv_bfloat16 hx = __float2bfloat16_rn(x);
    __nv_bfloat16 hy = __float2bfloat16_rn(y);
    float rx = x - __bfloat162float(hx);
    float ry = y - __bfloat162float(hy);
    __nv_bfloat16 lx = __float2bfloat16_rn(rx);
    __nv_bfloat16 ly = __float2bfloat16_rn(ry);
    hi = ((uint32_t)__bfloat16_as_ushort(hy) << 16) | (uint32_t)__bfloat16_as_ushort(hx);
    lo = ((uint32_t)__bfloat16_as_ushort(ly) << 16) | (uint32_t)__bfloat16_as_ushort(lx);
}

// ===========================================================================
// mma.sync GEMM (NT) — unchanged from R4 (passed, ~300us each)
// ===========================================================================
#define G_RS 72
#define G_TILE_B (128 * G_RS * 2)        // 18432
#define OFF_ALO (G_TILE_B)
#define OFF_BHI (2 * G_TILE_B)
#define OFF_BLO (3 * G_TILE_B)
#define G_SMEM  (4 * G_TILE_B)           // 73728

template <int DST, bool SRCCTX>
__global__ __launch_bounds__(256, 2) void gemm_mma_kernel(
    const float* __restrict__ Aparam,
    const float* __restrict__ W,
    float* __restrict__ Cparam)
{
    extern __shared__ __align__(16) char smem[];
    const uint32_t sbase = smem_u32(smem);

    const float* A = SRCCTX ? (const float*)g_Ctx : Aparam;

    const int tid  = threadIdx.x;
    const int lane = tid & 31;
    const int warp = tid >> 5;
    const int wm = warp >> 2;
    const int wn = warp & 3;
    const int bm = blockIdx.y;
    const int bn = blockIdx.x;

    float acc[4][4][4];
#pragma unroll
    for (int i = 0; i < 4; i++)
#pragma unroll
        for (int j = 0; j < 4; j++)
#pragma unroll
            for (int q = 0; q < 4; q++) acc[i][j][q] = 0.0f;

    const int lrow = tid >> 1;
    const int lcol = (tid & 1) * 32;
    const float* Ag = A + (size_t)(bm * 128 + lrow) * PE + lcol;
    const float* Bg = W + (size_t)(bn * 128 + lrow) * PE + lcol;

    char* stA = smem + (lrow * G_RS + lcol) * 2;
    char* stB = stA + OFF_BHI;

    const int a_r = wm * 64 + (lane & 15);
    const int a_c = (lane >> 4) * 8;
    const uint32_t a_addr0 = sbase + (a_r * G_RS + a_c) * 2;
    const int b_r = wn * 32 + (lane & 7);
    const int b_c = ((lane >> 3) & 1) * 8;
    const uint32_t b_addr0 = sbase + OFF_BHI + (b_r * G_RS + b_c) * 2;

    for (int s = 0; s < PE / 64; s++) {
        const float* Ags = Ag + s * 64;
        const float* Bgs = Bg + s * 64;

        float4 av[4], bv[4];
#pragma unroll
        for (int q = 0; q < 4; q++) av[q] = *(const float4*)(Ags + q * 4);
#pragma unroll
        for (int q = 0; q < 4; q++) bv[q] = *(const float4*)(Bgs + q * 4);

        __syncthreads();

#pragma unroll
        for (int q = 0; q < 4; q++) {
            uint32_t h0, l0, h1, l1;
            split2(av[q].x, av[q].y, h0, l0);
            split2(av[q].z, av[q].w, h1, l1);
            *(uint2*)(stA + q * 8)           = make_uint2(h0, h1);
            *(uint2*)(stA + OFF_ALO + q * 8) = make_uint2(l0, l1);
            split2(bv[q].x, bv[q].y, h0, l0);
            split2(bv[q].z, bv[q].w, h1, l1);
            *(uint2*)(stB + q * 8)                         = make_uint2(h0, h1);
            *(uint2*)(stB + (OFF_BLO - OFF_BHI) + q * 8)   = make_uint2(l0, l1);
        }

#pragma unroll
        for (int q = 0; q < 4; q++) av[q] = *(const float4*)(Ags + 16 + q * 4);
#pragma unroll
        for (int q = 0; q < 4; q++) bv[q] = *(const float4*)(Bgs + 16 + q * 4);
#pragma unroll
        for (int q = 0; q < 4; q++) {
            uint32_t h0, l0, h1, l1;
            split2(av[q].x, av[q].y, h0, l0);
            split2(av[q].z, av[q].w, h1, l1);
            *(uint2*)(stA + 32 + q * 8)           = make_uint2(h0, h1);
            *(uint2*)(stA + OFF_ALO + 32 + q * 8) = make_uint2(l0, l1);
            split2(bv[q].x, bv[q].y, h0, l0);
            split2(bv[q].z, bv[q].w, h1, l1);
            *(uint2*)(stB + 32 + q * 8)                       = make_uint2(h0, h1);
            *(uint2*)(stB + (OFF_BLO - OFF_BHI) + 32 + q * 8) = make_uint2(l0, l1);
        }
        __syncthreads();

#pragma unroll
        for (int ks = 0; ks < 64; ks += 16) {
            uint32_t bh[4][2], bl[4][2];
#pragma unroll
            for (int ni = 0; ni < 4; ni++) {
                uint32_t ba = b_addr0 + (ni * 8 * G_RS + ks) * 2;
                ldsm_x2(bh[ni], ba);
                ldsm_x2(bl[ni], ba + (OFF_BLO - OFF_BHI));
            }
#pragma unroll
            for (int mi = 0; mi < 4; mi++) {
                uint32_t ah[4], al[4];
                uint32_t aa = a_addr0 + (mi * 16 * G_RS + ks) * 2;
                ldsm_x4(ah, aa);
                ldsm_x4(al, aa + OFF_ALO);
#pragma unroll
                for (int ni = 0; ni < 4; ni++) {
                    mma_bf16(acc[mi][ni], ah, bh[ni]);
                    mma_bf16(acc[mi][ni], ah, bl[ni]);
                    mma_bf16(acc[mi][ni], al, bh[ni]);
                }
            }
        }
    }

    float* Cdst = (DST == 0) ? g_Q : (DST == 1) ? g_K : (DST == 2) ? g_V : Cparam;
#pragma unroll
    for (int mi = 0; mi < 4; mi++) {
        const int m0 = bm * 128 + wm * 64 + mi * 16 + (lane >> 2);
#pragma unroll
        for (int half = 0; half < 2; half++) {
            const int m = m0 + half * 8;
            const int bb = m >> 11;
            const int ms = m & (PS - 1);
#pragma unroll
            for (int ni = 0; ni < 4; ni++) {
                const int n = bn * 128 + wn * 32 + ni * 8 + (lane & 3) * 2;
                float2 v = make_float2(acc[mi][ni][half * 2 + 0],
                                       acc[mi][ni][half * 2 + 1]);
                if (DST < 3) {
                    const int h = n >> 6;
                    const int d = n & 63;
                    *(float2*)&Cdst[((size_t)(bb * PH + h) * PS + ms) * PD + d] = v;
                } else {
                    *(float2*)&Cdst[(size_t)m * PE + n] = v;
                }
            }
        }
    }
}

// ===========================================================================
// Flash attention with mma.sync bf16 split precision.
// Block = (q-tile 64, head, batch), 128 threads (4 warps x 16 Q rows).
// Smem: Q/K/V hi+lo tiles (64 x 72-padded bf16) + f32 mask bias row.
// S = QhiKhi + QhiKlo + QloKhi ; O += PhiVhi + PhiVlo + PloVhi.
// P stays in registers (accumulator layout == A-fragment layout).
// ===========================================================================
#define ATT_RS 72
#define ATT_TILE (64 * ATT_RS * 2)      // 9216
#define A_QHI 0
#define A_QLO (ATT_TILE)
#define A_KHI (2 * ATT_TILE)
#define A_KLO (3 * ATT_TILE)
#define A_VHI (4 * ATT_TILE)
#define A_VLO (5 * ATT_TILE)
#define A_BIAS (6 * ATT_TILE)           // 55296
#define ATT_SMEM (A_BIAS + PS * 4)      // 63488

__global__ __launch_bounds__(128) void attn_mma_kernel(
    const unsigned char* __restrict__ mask,
    const float* __restrict__ gamma)
{
    extern __shared__ __align__(16) char sm[];
    const uint32_t sb = smem_u32(sm);

    const int tid  = threadIdx.x;
    const int lane = tid & 31;
    const int warp = tid >> 5;
    const int qt = blockIdx.x;
    const int h  = blockIdx.y;
    const int b  = blockIdx.z;

    const size_t headBase = (size_t)(b * PH + h) * PS * PD;

    // mask -> f32 bias row (0 or -3e38), shared by all q rows
    {
        const unsigned char* mrow = mask + (size_t)b * PS;
        float* biasp = (float*)(sm + A_BIAS);
#pragma unroll
        for (int i = 0; i < PS / 128; i++) {
            int kk = tid + i * 128;
            biasp[kk] = mrow[kk] ? -3.0e38f : 0.0f;
        }
    }

    // Q tile load + split
    const int lrow = tid >> 1;
    const int lcol = (tid & 1) * 32;
    {
        const float* qp = g_Q + headBase + (size_t)(qt * 64 + lrow) * PD + lcol;
        char* qhiP = sm + A_QHI + (lrow * ATT_RS + lcol) * 2;
#pragma unroll
        for (int q = 0; q < 8; q++) {
            float4 v = *(const float4*)(qp + q * 4);
            uint32_t h0, l0, h1, l1;
            split2(v.x, v.y, h0, l0);
            split2(v.z, v.w, h1, l1);
            *(uint2*)(qhiP + q * 8)                   = make_uint2(h0, h1);
            *(uint2*)(qhiP + (A_QLO - A_QHI) + q * 8) = make_uint2(l0, l1);
        }
    }

    // fragment base addresses
    const uint32_t qa = sb + A_QHI + ((warp * 16 + (lane & 15)) * ATT_RS + (lane >> 4) * 8) * 2;
    const uint32_t kb = sb + A_KHI + ((lane & 7) * ATT_RS + ((lane >> 3) & 1) * 8) * 2;
    const uint32_t vb = sb + A_VHI + ((lane & 15) * ATT_RS) * 2;

    float o[8][4];
#pragma unroll
    for (int nj = 0; nj < 8; nj++)
#pragma unroll
        for (int q = 0; q < 4; q++) o[nj][q] = 0.0f;
    float m0 = -3.0e38f, m1 = -3.0e38f, l0 = 0.0f, l1 = 0.0f;

    const float* Kgb = g_K + headBase + (size_t)lrow * PD + lcol;
    const float* Vgb = g_V + headBase + (size_t)lrow * PD + lcol;
    char* khiP = sm + A_KHI + (lrow * ATT_RS + lcol) * 2;
    char* vhiP = sm + A_VHI + (lrow * ATT_RS + lcol) * 2;

    for (int kt = 0; kt < PS / 64; kt++) {
        __syncthreads();   // prior iter's ldmatrix done
        {
            const float* kp = Kgb + (size_t)kt * 64 * PD;
            const float* vp = Vgb + (size_t)kt * 64 * PD;
#pragma unroll
            for (int q = 0; q < 8; q++) {
                float4 v = *(const float4*)(kp + q * 4);
                uint32_t h0, lw0, h1, lw1;
                split2(v.x, v.y, h0, lw0);
                split2(v.z, v.w, h1, lw1);
                *(uint2*)(khiP + q * 8)                   = make_uint2(h0, h1);
                *(uint2*)(khiP + (A_KLO - A_KHI) + q * 8) = make_uint2(lw0, lw1);
            }
#pragma unroll
            for (int q = 0; q < 8; q++) {
                float4 v = *(const float4*)(vp + q * 4);
                uint32_t h0, lw0, h1, lw1;
                split2(v.x, v.y, h0, lw0);
                split2(v.z, v.w, h1, lw1);
                *(uint2*)(vhiP + q * 8)                   = make_uint2(h0, h1);
                *(uint2*)(vhiP + (A_VLO - A_VHI) + q * 8) = make_uint2(lw0, lw1);
            }
        }
        __syncthreads();

        // ---- S = Q K^T (split bf16) ----
        float sa[8][4];
#pragma unroll
        for (int ni = 0; ni < 8; ni++)
#pragma unroll
            for (int q = 0; q < 4; q++) sa[ni][q] = 0.0f;

#pragma unroll
        for (int ks = 0; ks < 4; ks++) {
            uint32_t qh[4], ql[4];
            ldsm_x4(qh, qa + ks * 32);
            ldsm_x4(ql, qa + (A_QLO - A_QHI) + ks * 32);
#pragma unroll
            for (int ni = 0; ni < 8; ni++) {
                uint32_t kh[2], kl[2];
                uint32_t ba = kb + ni * (8 * ATT_RS * 2) + ks * 32;
                ldsm_x2(kh, ba);
                ldsm_x2(kl, ba + (A_KLO - A_KHI));
                mma_bf16(sa[ni], qh, kh);
                mma_bf16(sa[ni], qh, kl);
                mma_bf16(sa[ni], ql, kh);
            }
        }

        // ---- scale + bias + online softmax ----
        float mx0 = -3.0e38f, mx1 = -3.0e38f;
#pragma unroll
        for (int ni = 0; ni < 8; ni++) {
            float2 bias = *(const float2*)(sm + A_BIAS + (kt * 64 + ni * 8 + (lane & 3) * 2) * 4);
            sa[ni][0] = sa[ni][0] * 0.125f + bias.x;
            sa[ni][1] = sa[ni][1] * 0.125f + bias.y;
            sa[ni][2] = sa[ni][2] * 0.125f + bias.x;
            sa[ni][3] = sa[ni][3] * 0.125f + bias.y;
            mx0 = fmaxf(mx0, fmaxf(sa[ni][0], sa[ni][1]));
            mx1 = fmaxf(mx1, fmaxf(sa[ni][2], sa[ni][3]));
        }
        mx0 = fmaxf(mx0, __shfl_xor_sync(0xffffffffu, mx0, 1));
        mx0 = fmaxf(mx0, __shfl_xor_sync(0xffffffffu, mx0, 2));
        mx1 = fmaxf(mx1, __shfl_xor_sync(0xffffffffu, mx1, 1));
        mx1 = fmaxf(mx1, __shfl_xor_sync(0xffffffffu, mx1, 2));

        float mn0 = fmaxf(m0, mx0);
        float mn1 = fmaxf(m1, mx1);
        float csc0 = __expf(m0 - mn0);
        float csc1 = __expf(m1 - mn1);
        m0 = mn0; m1 = mn1;

        float ls0 = 0.0f, ls1 = 0.0f;
#pragma unroll
        for (int ni = 0; ni < 8; ni++) {
            sa[ni][0] = __expf(sa[ni][0] - mn0);
            sa[ni][1] = __expf(sa[ni][1] - mn0);
            sa[ni][2] = __expf(sa[ni][2] - mn1);
            sa[ni][3] = __expf(sa[ni][3] - mn1);
            ls0 += sa[ni][0] + sa[ni][1];
            ls1 += sa[ni][2] + sa[ni][3];
        }
        ls0 += __shfl_xor_sync(0xffffffffu, ls0, 1);
        ls0 += __shfl_xor_sync(0xffffffffu, ls0, 2);
        ls1 += __shfl_xor_sync(0xffffffffu, ls1, 1);
        ls1 += __shfl_xor_sync(0xffffffffu, ls1, 2);
        l0 = l0 * csc0 + ls0;
        l1 = l1 * csc1 + ls1;

#pragma unroll
        for (int nj = 0; nj < 8; nj++) {
            o[nj][0] *= csc0; o[nj][1] *= csc0;
            o[nj][2] *= csc1; o[nj][3] *= csc1;
        }

        // ---- O += P V (P split in registers, V split in smem, trans load) ----
#pragma unroll
        for (int ks = 0; ks < 4; ks++) {
            const float* t0 = sa[2 * ks];
            const float* t1 = sa[2 * ks + 1];
            uint32_t ah[4], al[4];
            split2(t0[0], t0[1], ah[0], al[0]);
            split2(t0[2], t0[3], ah[1], al[1]);
            split2(t1[0], t1[1], ah[2], al[2]);
            split2(t1[2], t1[3], ah[3], al[3]);
#pragma unroll
            for (int nj = 0; nj < 8; nj++) {
                uint32_t vh[2], vl[2];
                uint32_t va = vb + ks * (16 * ATT_RS * 2) + nj * 16;
                ldsm_x2_t(vh, va);
                ldsm_x2_t(vl, va + (A_VLO - A_VHI));
                mma_bf16(o[nj], ah, vh);
                mma_bf16(o[nj], ah, vl);
                mma_bf16(o[nj], al, vh);
            }
        }
    }

    // ---- epilogue: gamma / l, write ctx ----
    const float gsc = gamma[h];
    const float inv0 = gsc / l0;
    const float inv1 = gsc / l1;
    const int r0 = qt * 64 + warp * 16 + (lane >> 2);
    float* O0 = g_Ctx + ((size_t)b * PS + r0) * PE + h * PD;
    float* O1 = O0 + (size_t)8 * PE;
#pragma unroll
    for (int nj = 0; nj < 8; nj++) {
        const int col = nj * 8 + (lane & 3) * 2;
        *(float2*)&O0[col] = make_float2(o[nj][0] * inv0, o[nj][1] * inv0);
        *(float2*)&O1[col] = make_float2(o[nj][2] * inv1, o[nj][3] * inv1);
    }
}

// ---------------------------------------------------------------------------
extern "C" void kernel_launch(void* const* d_in, const int* in_sizes, int n_in,
                              void* d_out, int out_size)
{
    const float* query = (const float*)d_in[0];
    const float* key   = (const float*)d_in[1];
    const float* value = (const float*)d_in[2];
    const unsigned char* mask = (const unsigned char*)d_in[3];
    const float* Wq = (const float*)d_in[4];
    const float* Wk = (const float*)d_in[5];
    const float* Wv = (const float*)d_in[6];
    const float* Wo = (const float*)d_in[7];
    const float* gamma = (const float*)d_in[8];

    cudaFuncSetAttribute(gemm_mma_kernel<0, false>,
                         cudaFuncAttributeMaxDynamicSharedMemorySize, G_SMEM);
    cudaFuncSetAttribute(gemm_mma_kernel<1, false>,
                         cudaFuncAttributeMaxDynamicSharedMemorySize, G_SMEM);
    cudaFuncSetAttribute(gemm_mma_kernel<2, false>,
                         cudaFuncAttributeMaxDynamicSharedMemorySize, G_SMEM);
    cudaFuncSetAttribute(gemm_mma_kernel<3, true>,
                         cudaFuncAttributeMaxDynamicSharedMemorySize, G_SMEM);
    cudaFuncSetAttribute(attn_mma_kernel,
                         cudaFuncAttributeMaxDynamicSharedMemorySize, ATT_SMEM);

    dim3 gp(PE / 128, PM / 128);   // (8, 64)
    gemm_mma_kernel<0, false><<<gp, 256, G_SMEM>>>(query, Wq, nullptr);
    gemm_mma_kernel<1, false><<<gp, 256, G_SMEM>>>(key, Wk, nullptr);
    gemm_mma_kernel<2, false><<<gp, 256, G_SMEM>>>(value, Wv, nullptr);

    attn_mma_kernel<<<dim3(PS / 64, PH, PB), 128, ATT_SMEM>>>(mask, gamma);

    gemm_mma_kernel<3, true><<<gp, 256, G_SMEM>>>(nullptr, Wo, (float*)d_out);
}

// round 7
// speedup vs baseline: 2.2614x; 1.1835x over previous
#include <cuda_runtime.h>
#include <cuda_bf16.h>
#include <cstdint>

// Problem constants
#define PB 4
#define PS 2048
#define PE 1024
#define PH 16
#define PD 64
#define PM (PB * PS)   // 8192
#define NEL (PM * PE)  // 8388608

// ---------------------------------------------------------------------------
// Persistent bf16 hi/lo scratch (device globals: allocation-free)
// ---------------------------------------------------------------------------
__device__ __nv_bfloat16 g_InHi[3][NEL];     // split query/key/value
__device__ __nv_bfloat16 g_InLo[3][NEL];
__device__ __nv_bfloat16 g_WHi[4][PE * PE];  // split Wq,Wk,Wv,Wo
__device__ __nv_bfloat16 g_WLo[4][PE * PE];
__device__ __nv_bfloat16 g_QHi[NEL], g_QLo[NEL];   // [b,h,s,d]
__device__ __nv_bfloat16 g_KHi[NEL], g_KLo[NEL];
__device__ __nv_bfloat16 g_VHi[NEL], g_VLo[NEL];
__device__ __nv_bfloat16 g_CtxHi[NEL], g_CtxLo[NEL]; // [b,s,e]

// ===========================================================================
// helpers
// ===========================================================================
__device__ __forceinline__ uint32_t smem_u32(const void* p) {
    uint32_t a;
    asm("{ .reg .u64 t; cvta.to.shared.u64 t, %1; cvt.u32.u64 %0, t; }"
        : "=r"(a) : "l"(p));
    return a;
}
__device__ __forceinline__ void ldsm_x4(uint32_t* r, uint32_t addr) {
    asm volatile("ldmatrix.sync.aligned.m8n8.x4.shared.b16 {%0,%1,%2,%3}, [%4];"
                 : "=r"(r[0]), "=r"(r[1]), "=r"(r[2]), "=r"(r[3]) : "r"(addr));
}
__device__ __forceinline__ void ldsm_x2(uint32_t* r, uint32_t addr) {
    asm volatile("ldmatrix.sync.aligned.m8n8.x2.shared.b16 {%0,%1}, [%2];"
                 : "=r"(r[0]), "=r"(r[1]) : "r"(addr));
}
__device__ __forceinline__ void ldsm_x2_t(uint32_t* r, uint32_t addr) {
    asm volatile("ldmatrix.sync.aligned.m8n8.x2.trans.shared.b16 {%0,%1}, [%2];"
                 : "=r"(r[0]), "=r"(r[1]) : "r"(addr));
}
__device__ __forceinline__ void mma_bf16(float* c, const uint32_t* a, const uint32_t* b) {
    asm volatile(
        "mma.sync.aligned.m16n8k16.row.col.f32.bf16.bf16.f32 "
        "{%0,%1,%2,%3}, {%4,%5,%6,%7}, {%8,%9}, {%0,%1,%2,%3};"
        : "+f"(c[0]), "+f"(c[1]), "+f"(c[2]), "+f"(c[3])
        : "r"(a[0]), "r"(a[1]), "r"(a[2]), "r"(a[3]), "r"(b[0]), "r"(b[1]));
}
__device__ __forceinline__ void cp_async16(uint32_t saddr, const void* gptr) {
    asm volatile("cp.async.ca.shared.global [%0], [%1], 16;"
                 :: "r"(saddr), "l"(gptr));
}
#define CP_COMMIT() asm volatile("cp.async.commit_group;" ::: "memory")
#define CP_WAIT1()  asm volatile("cp.async.wait_group 1;" ::: "memory")
#define CP_WAIT0()  asm volatile("cp.async.wait_group 0;" ::: "memory")

// fp32 -> (hi, lo) bf16 split, packed as bf16x2 words
__device__ __forceinline__ void split2(float x, float y, uint32_t& hi, uint32_t& lo) {
    __nv_bfloat16 hx = __float2bfloat16_rn(x);
    __nv_bfloat16 hy = __float2bfloat16_rn(y);
    float rx = x - __bfloat162float(hx);
    float ry = y - __bfloat162float(hy);
    __nv_bfloat16 lx = __float2bfloat16_rn(rx);
    __nv_bfloat16 ly = __float2bfloat16_rn(ry);
    hi = ((uint32_t)__bfloat16_as_ushort(hy) << 16) | (uint32_t)__bfloat16_as_ushort(hx);
    lo = ((uint32_t)__bfloat16_as_ushort(ly) << 16) | (uint32_t)__bfloat16_as_ushort(lx);
}

// ===========================================================================
// split kernels: fp32 -> bf16 hi/lo (IN: inputs 0..2, W: weights 0..3)
// ===========================================================================
template <int IDX>
__global__ __launch_bounds__(256) void split_in_kernel(const float* __restrict__ src) {
    int i = blockIdx.x * 256 + threadIdx.x;       // float4 index
    float4 v = ((const float4*)src)[i];
    uint32_t h0, l0, h1, l1;
    split2(v.x, v.y, h0, l0);
    split2(v.z, v.w, h1, l1);
    ((uint2*)g_InHi[IDX])[i] = make_uint2(h0, h1);
    ((uint2*)g_InLo[IDX])[i] = make_uint2(l0, l1);
}
template <int IDX>
__global__ __launch_bounds__(256) void split_w_kernel(const float* __restrict__ src) {
    int i = blockIdx.x * 256 + threadIdx.x;
    float4 v = ((const float4*)src)[i];
    uint32_t h0, l0, h1, l1;
    split2(v.x, v.y, h0, l0);
    split2(v.z, v.w, h1, l1);
    ((uint2*)g_WHi[IDX])[i] = make_uint2(h0, h1);
    ((uint2*)g_WLo[IDX])[i] = make_uint2(l0, l1);
}

// ===========================================================================
// GEMM (NT), all-bf16 operands, cp.async double-buffered.
// C[m,n] = sum_k A[m,k]*W[n,k]; M=8192, N=1024, K=1024.
// CTA: 128x128, BK=32, 256 threads, warp tiles 64x32.
// 3-term split: D += Ahi*Bhi + Ahi*Blo + Alo*Bhi  (fp32 regs).
// DST 0..2: write bf16 hi/lo into g_{Q,K,V}Hi/Lo with [b,h,s,d] scatter.
// DST 3:   write fp32 row-major into Cparam.
// ===========================================================================
#define T_RS 56                         // row stride (bf16 elems) for 32-col tile
#define T_BYTES (128 * T_RS * 2)        // 14336
#define STAGE_B (4 * T_BYTES)           // 57344 : tiles [Ahi, Alo, Bhi, Blo]
#define GS_SMEM (2 * STAGE_B)           // 114688
#define NSTAGE (PE / 32)                // 32

template <int DST, bool SRCCTX>
__global__ __launch_bounds__(256, 2) void gemm_mma_kernel(float* __restrict__ Cparam)
{
    extern __shared__ __align__(16) char smem[];
    const uint32_t sbase = smem_u32(smem);

    const __nv_bfloat16* Ahi = SRCCTX ? g_CtxHi : g_InHi[DST];
    const __nv_bfloat16* Alo = SRCCTX ? g_CtxLo : g_InLo[DST];
    const __nv_bfloat16* Bhi = g_WHi[DST];
    const __nv_bfloat16* Blo = g_WLo[DST];

    const int tid  = threadIdx.x;
    const int lane = tid & 31;
    const int warp = tid >> 5;
    const int wm = warp >> 2;
    const int wn = warp & 3;
    const int bm = blockIdx.y;
    const int bn = blockIdx.x;

    float acc[4][4][4];
#pragma unroll
    for (int i = 0; i < 4; i++)
#pragma unroll
        for (int j = 0; j < 4; j++)
#pragma unroll
            for (int q = 0; q < 4; q++) acc[i][j][q] = 0.0f;

    // copy mapping: thread -> (row 0..127, 16-elem col half)
    const int crow = tid >> 1;
    const int ccol = (tid & 1) * 16;
    const __nv_bfloat16* gAh = Ahi + (size_t)(bm * 128 + crow) * PE + ccol;
    const __nv_bfloat16* gAl = Alo + (size_t)(bm * 128 + crow) * PE + ccol;
    const __nv_bfloat16* gBh = Bhi + (size_t)(bn * 128 + crow) * PE + ccol;
    const __nv_bfloat16* gBl = Blo + (size_t)(bn * 128 + crow) * PE + ccol;
    const uint32_t sOff = (uint32_t)(crow * T_RS + ccol) * 2;

    // fragment offsets within a tile
    const uint32_t a_off = ((wm * 64 + (lane & 15)) * T_RS + (lane >> 4) * 8) * 2;
    const uint32_t b_off = ((wn * 32 + (lane & 7)) * T_RS + ((lane >> 3) & 1) * 8) * 2;

    // prologue: stage 0 into buf 0
    {
        uint32_t d = sbase + sOff;
        cp_async16(d + 0 * T_BYTES,      gAh);
        cp_async16(d + 0 * T_BYTES + 16, gAh + 8);
        cp_async16(d + 1 * T_BYTES,      gAl);
        cp_async16(d + 1 * T_BYTES + 16, gAl + 8);
        cp_async16(d + 2 * T_BYTES,      gBh);
        cp_async16(d + 2 * T_BYTES + 16, gBh + 8);
        cp_async16(d + 3 * T_BYTES,      gBl);
        cp_async16(d + 3 * T_BYTES + 16, gBl + 8);
        CP_COMMIT();
    }

#pragma unroll 1
    for (int s = 0; s < NSTAGE; s++) {
        if (s + 1 < NSTAGE) {
            const int g = (s + 1) * 32;
            uint32_t d = sbase + ((s + 1) & 1) * STAGE_B + sOff;
            cp_async16(d + 0 * T_BYTES,      gAh + g);
            cp_async16(d + 0 * T_BYTES + 16, gAh + g + 8);
            cp_async16(d + 1 * T_BYTES,      gAl + g);
            cp_async16(d + 1 * T_BYTES + 16, gAl + g + 8);
            cp_async16(d + 2 * T_BYTES,      gBh + g);
            cp_async16(d + 2 * T_BYTES + 16, gBh + g + 8);
            cp_async16(d + 3 * T_BYTES,      gBl + g);
            cp_async16(d + 3 * T_BYTES + 16, gBl + g + 8);
            CP_COMMIT();
            CP_WAIT1();
        } else {
            CP_WAIT0();
        }
        __syncthreads();   // stage s visible everywhere

        const uint32_t bufb = sbase + (s & 1) * STAGE_B;
#pragma unroll
        for (int ks = 0; ks < 32; ks += 16) {
            uint32_t bh[4][2], bl[4][2];
#pragma unroll
            for (int ni = 0; ni < 4; ni++) {
                uint32_t ba = bufb + 2 * T_BYTES + b_off + (ni * 8 * T_RS + ks) * 2;
                ldsm_x2(bh[ni], ba);
                ldsm_x2(bl[ni], ba + T_BYTES);
            }
#pragma unroll
            for (int mi = 0; mi < 4; mi++) {
                uint32_t ah[4], al[4];
                uint32_t aa = bufb + a_off + (mi * 16 * T_RS + ks) * 2;
                ldsm_x4(ah, aa);
                ldsm_x4(al, aa + T_BYTES);
#pragma unroll
                for (int ni = 0; ni < 4; ni++) {
                    mma_bf16(acc[mi][ni], ah, bh[ni]);
                    mma_bf16(acc[mi][ni], ah, bl[ni]);
                    mma_bf16(acc[mi][ni], al, bh[ni]);
                }
            }
        }
        __syncthreads();   // done reading buf (s&1) before it is refilled
    }

    // ---- epilogue ----
    __nv_bfloat16* Dhi = (DST == 0) ? g_QHi : (DST == 1) ? g_KHi : g_VHi;
    __nv_bfloat16* Dlo = (DST == 0) ? g_QLo : (DST == 1) ? g_KLo : g_VLo;
#pragma unroll
    for (int mi = 0; mi < 4; mi++) {
        const int m0 = bm * 128 + wm * 64 + mi * 16 + (lane >> 2);
#pragma unroll
        for (int half = 0; half < 2; half++) {
            const int m = m0 + half * 8;
            const int bb = m >> 11;
            const int ms = m & (PS - 1);
#pragma unroll
            for (int ni = 0; ni < 4; ni++) {
                const int n = bn * 128 + wn * 32 + ni * 8 + (lane & 3) * 2;
                float v0 = acc[mi][ni][half * 2 + 0];
                float v1 = acc[mi][ni][half * 2 + 1];
                if (DST < 3) {
                    const int h = n >> 6;
                    const int d = n & 63;
                    size_t idx = ((size_t)(bb * PH + h) * PS + ms) * PD + d;
                    uint32_t hw, lw;
                    split2(v0, v1, hw, lw);
                    *(uint32_t*)&Dhi[idx] = hw;
                    *(uint32_t*)&Dlo[idx] = lw;
                } else {
                    *(float2*)&Cparam[(size_t)m * PE + n] = make_float2(v0, v1);
                }
            }
        }
    }
}

// ===========================================================================
// Flash attention, mma.sync bf16 split, pre-split K/V/Q (no in-loop convert).
// Block = (q-tile 64, head, batch), 128 threads.
// Writes Ctx as bf16 hi/lo for the output projection.
// ===========================================================================
#define ATT_RS 72
#define ATT_TILE (64 * ATT_RS * 2)      // 9216
#define A_QHI 0
#define A_QLO (ATT_TILE)
#define A_KHI (2 * ATT_TILE)
#define A_KLO (3 * ATT_TILE)
#define A_VHI (4 * ATT_TILE)
#define A_VLO (5 * ATT_TILE)
#define A_BIAS (6 * ATT_TILE)           // 55296
#define ATT_SMEM (A_BIAS + PS * 4)      // 63488

__global__ __launch_bounds__(128) void attn_mma_kernel(
    const unsigned char* __restrict__ mask,
    const float* __restrict__ gamma)
{
    extern __shared__ __align__(16) char sm[];
    const uint32_t sb = smem_u32(sm);

    const int tid  = threadIdx.x;
    const int lane = tid & 31;
    const int warp = tid >> 5;
    const int qt = blockIdx.x;
    const int h  = blockIdx.y;
    const int b  = blockIdx.z;

    const size_t headBase = (size_t)(b * PH + h) * PS * PD;

    // mask -> f32 bias row
    {
        const unsigned char* mrow = mask + (size_t)b * PS;
        float* biasp = (float*)(sm + A_BIAS);
#pragma unroll
        for (int i = 0; i < PS / 128; i++) {
            int kk = tid + i * 128;
            biasp[kk] = mrow[kk] ? -3.0e38f : 0.0f;
        }
    }

    // copy mapping: row 0..63, 32-elem col half
    const int crow = tid >> 1;
    const int ccol = (tid & 1) * 32;
    const size_t rowOff = headBase + (size_t)crow * PD + ccol;
    const uint32_t sOff = (uint32_t)(crow * ATT_RS + ccol) * 2;

    // Q tile (bf16 hi/lo direct copy)
    {
        const __nv_bfloat16* qh = g_QHi + rowOff + (size_t)qt * 64 * PD;
        const __nv_bfloat16* ql = g_QLo + rowOff + (size_t)qt * 64 * PD;
#pragma unroll
        for (int q = 0; q < 4; q++) {
            *(uint4*)(sm + A_QHI + sOff + q * 16) = *(const uint4*)(qh + q * 8);
            *(uint4*)(sm + A_QLO + sOff + q * 16) = *(const uint4*)(ql + q * 8);
        }
    }

    const uint32_t qa = sb + A_QHI + ((warp * 16 + (lane & 15)) * ATT_RS + (lane >> 4) * 8) * 2;
    const uint32_t kb = sb + A_KHI + ((lane & 7) * ATT_RS + ((lane >> 3) & 1) * 8) * 2;
    const uint32_t vb = sb + A_VHI + ((lane & 15) * ATT_RS) * 2;

    float o[8][4];
#pragma unroll
    for (int nj = 0; nj < 8; nj++)
#pragma unroll
        for (int q = 0; q < 4; q++) o[nj][q] = 0.0f;
    float m0 = -3.0e38f, m1 = -3.0e38f, l0 = 0.0f, l1 = 0.0f;

    for (int kt = 0; kt < PS / 64; kt++) {
        __syncthreads();
        {
            const size_t t = rowOff + (size_t)kt * 64 * PD;
            const __nv_bfloat16* kh = g_KHi + t;
            const __nv_bfloat16* kl = g_KLo + t;
            const __nv_bfloat16* vh = g_VHi + t;
            const __nv_bfloat16* vl = g_VLo + t;
#pragma unroll
            for (int q = 0; q < 4; q++) {
                *(uint4*)(sm + A_KHI + sOff + q * 16) = *(const uint4*)(kh + q * 8);
                *(uint4*)(sm + A_KLO + sOff + q * 16) = *(const uint4*)(kl + q * 8);
                *(uint4*)(sm + A_VHI + sOff + q * 16) = *(const uint4*)(vh + q * 8);
                *(uint4*)(sm + A_VLO + sOff + q * 16) = *(const uint4*)(vl + q * 8);
            }
        }
        __syncthreads();

        // ---- S = Q K^T ----
        float sa[8][4];
#pragma unroll
        for (int ni = 0; ni < 8; ni++)
#pragma unroll
            for (int q = 0; q < 4; q++) sa[ni][q] = 0.0f;

#pragma unroll
        for (int ks = 0; ks < 4; ks++) {
            uint32_t qh[4], ql[4];
            ldsm_x4(qh, qa + ks * 32);
            ldsm_x4(ql, qa + (A_QLO - A_QHI) + ks * 32);
#pragma unroll
            for (int ni = 0; ni < 8; ni++) {
                uint32_t kh[2], kl[2];
                uint32_t ba = kb + ni * (8 * ATT_RS * 2) + ks * 32;
                ldsm_x2(kh, ba);
                ldsm_x2(kl, ba + (A_KLO - A_KHI));
                mma_bf16(sa[ni], qh, kh);
                mma_bf16(sa[ni], qh, kl);
                mma_bf16(sa[ni], ql, kh);
            }
        }

        // ---- scale + bias + online softmax ----
        float mx0 = -3.0e38f, mx1 = -3.0e38f;
#pragma unroll
        for (int ni = 0; ni < 8; ni++) {
            float2 bias = *(const float2*)(sm + A_BIAS + (kt * 64 + ni * 8 + (lane & 3) * 2) * 4);
            sa[ni][0] = sa[ni][0] * 0.125f + bias.x;
            sa[ni][1] = sa[ni][1] * 0.125f + bias.y;
            sa[ni][2] = sa[ni][2] * 0.125f + bias.x;
            sa[ni][3] = sa[ni][3] * 0.125f + bias.y;
            mx0 = fmaxf(mx0, fmaxf(sa[ni][0], sa[ni][1]));
            mx1 = fmaxf(mx1, fmaxf(sa[ni][2], sa[ni][3]));
        }
        mx0 = fmaxf(mx0, __shfl_xor_sync(0xffffffffu, mx0, 1));
        mx0 = fmaxf(mx0, __shfl_xor_sync(0xffffffffu, mx0, 2));
        mx1 = fmaxf(mx1, __shfl_xor_sync(0xffffffffu, mx1, 1));
        mx1 = fmaxf(mx1, __shfl_xor_sync(0xffffffffu, mx1, 2));

        float mn0 = fmaxf(m0, mx0);
        float mn1 = fmaxf(m1, mx1);
        float csc0 = __expf(m0 - mn0);
        float csc1 = __expf(m1 - mn1);
        m0 = mn0; m1 = mn1;

        float ls0 = 0.0f, ls1 = 0.0f;
#pragma unroll
        for (int ni = 0; ni < 8; ni++) {
            sa[ni][0] = __expf(sa[ni][0] - mn0);
            sa[ni][1] = __expf(sa[ni][1] - mn0);
            sa[ni][2] = __expf(sa[ni][2] - mn1);
            sa[ni][3] = __expf(sa[ni][3] - mn1);
            ls0 += sa[ni][0] + sa[ni][1];
            ls1 += sa[ni][2] + sa[ni][3];
        }
        ls0 += __shfl_xor_sync(0xffffffffu, ls0, 1);
        ls0 += __shfl_xor_sync(0xffffffffu, ls0, 2);
        ls1 += __shfl_xor_sync(0xffffffffu, ls1, 1);
        ls1 += __shfl_xor_sync(0xffffffffu, ls1, 2);
        l0 = l0 * csc0 + ls0;
        l1 = l1 * csc1 + ls1;

#pragma unroll
        for (int nj = 0; nj < 8; nj++) {
            o[nj][0] *= csc0; o[nj][1] *= csc0;
            o[nj][2] *= csc1; o[nj][3] *= csc1;
        }

        // ---- O += P V (P split in regs; V hi/lo trans loads) ----
#pragma unroll
        for (int ks = 0; ks < 4; ks++) {
            const float* t0 = sa[2 * ks];
            const float* t1 = sa[2 * ks + 1];
            uint32_t ah[4], al[4];
            split2(t0[0], t0[1], ah[0], al[0]);
            split2(t0[2], t0[3], ah[1], al[1]);
            split2(t1[0], t1[1], ah[2], al[2]);
            split2(t1[2], t1[3], ah[3], al[3]);
#pragma unroll
            for (int nj = 0; nj < 8; nj++) {
                uint32_t vh[2], vl[2];
                uint32_t va = vb + ks * (16 * ATT_RS * 2) + nj * 16;
                ldsm_x2_t(vh, va);
                ldsm_x2_t(vl, va + (A_VLO - A_VHI));
                mma_bf16(o[nj], ah, vh);
                mma_bf16(o[nj], ah, vl);
                mma_bf16(o[nj], al, vh);
            }
        }
    }

    // ---- epilogue: gamma / l, split, write Ctx hi/lo ----
    const float gsc = gamma[h];
    const float inv0 = gsc / l0;
    const float inv1 = gsc / l1;
    const int r0 = qt * 64 + warp * 16 + (lane >> 2);
    const size_t base0 = ((size_t)b * PS + r0) * PE + h * PD;
    const size_t base1 = base0 + (size_t)8 * PE;
#pragma unroll
    for (int nj = 0; nj < 8; nj++) {
        const int col = nj * 8 + (lane & 3) * 2;
        uint32_t hw, lw;
        split2(o[nj][0] * inv0, o[nj][1] * inv0, hw, lw);
        *(uint32_t*)&g_CtxHi[base0 + col] = hw;
        *(uint32_t*)&g_CtxLo[base0 + col] = lw;
        split2(o[nj][2] * inv1, o[nj][3] * inv1, hw, lw);
        *(uint32_t*)&g_CtxHi[base1 + col] = hw;
        *(uint32_t*)&g_CtxLo[base1 + col] = lw;
    }
}

// ---------------------------------------------------------------------------
extern "C" void kernel_launch(void* const* d_in, const int* in_sizes, int n_in,
                              void* d_out, int out_size)
{
    const float* query = (const float*)d_in[0];
    const float* key   = (const float*)d_in[1];
    const float* value = (const float*)d_in[2];
    const unsigned char* mask = (const unsigned char*)d_in[3];
    const float* Wq = (const float*)d_in[4];
    const float* Wk = (const float*)d_in[5];
    const float* Wv = (const float*)d_in[6];
    const float* Wo = (const float*)d_in[7];
    const float* gamma = (const float*)d_in[8];

    cudaFuncSetAttribute(gemm_mma_kernel<0, false>,
                         cudaFuncAttributeMaxDynamicSharedMemorySize, GS_SMEM);
    cudaFuncSetAttribute(gemm_mma_kernel<1, false>,
                         cudaFuncAttributeMaxDynamicSharedMemorySize, GS_SMEM);
    cudaFuncSetAttribute(gemm_mma_kernel<2, false>,
                         cudaFuncAttributeMaxDynamicSharedMemorySize, GS_SMEM);
    cudaFuncSetAttribute(gemm_mma_kernel<3, true>,
                         cudaFuncAttributeMaxDynamicSharedMemorySize, GS_SMEM);
    cudaFuncSetAttribute(attn_mma_kernel,
                         cudaFuncAttributeMaxDynamicSharedMemorySize, ATT_SMEM);

    // pre-split inputs and weights (bandwidth-bound, ~30us total)
    split_in_kernel<0><<<NEL / 4 / 256, 256>>>(query);
    split_in_kernel<1><<<NEL / 4 / 256, 256>>>(key);
    split_in_kernel<2><<<NEL / 4 / 256, 256>>>(value);
    split_w_kernel<0><<<PE * PE / 4 / 256, 256>>>(Wq);
    split_w_kernel<1><<<PE * PE / 4 / 256, 256>>>(Wk);
    split_w_kernel<2><<<PE * PE / 4 / 256, 256>>>(Wv);
    split_w_kernel<3><<<PE * PE / 4 / 256, 256>>>(Wo);

    dim3 gp(PE / 128, PM / 128);   // (8, 64)
    gemm_mma_kernel<0, false><<<gp, 256, GS_SMEM>>>(nullptr);
    gemm_mma_kernel<1, false><<<gp, 256, GS_SMEM>>>(nullptr);
    gemm_mma_kernel<2, false><<<gp, 256, GS_SMEM>>>(nullptr);

    attn_mma_kernel<<<dim3(PS / 64, PH, PB), 128, ATT_SMEM>>>(mask, gamma);

    gemm_mma_kernel<3, true><<<gp, 256, GS_SMEM>>>((float*)d_out);
}

// round 8
// speedup vs baseline: 2.3479x; 1.0382x over previous
#include <cuda_runtime.h>
#include <cuda_bf16.h>
#include <cstdint>

// Problem constants
#define PB 4
#define PS 2048
#define PE 1024
#define PH 16
#define PD 64
#define PM (PB * PS)   // 8192
#define NEL (PM * PE)  // 8388608

// ---------------------------------------------------------------------------
// Persistent bf16 hi/lo scratch (device globals: allocation-free)
// ---------------------------------------------------------------------------
__device__ __nv_bfloat16 g_InHi[3][NEL];     // split query/key/value
__device__ __nv_bfloat16 g_InLo[3][NEL];
__device__ __nv_bfloat16 g_WHi[4][PE * PE];  // split Wq,Wk,Wv,Wo
__device__ __nv_bfloat16 g_WLo[4][PE * PE];
__device__ __nv_bfloat16 g_QHi[NEL], g_QLo[NEL];   // [b,h,s,d]
__device__ __nv_bfloat16 g_KHi[NEL], g_KLo[NEL];
__device__ __nv_bfloat16 g_VHi[NEL], g_VLo[NEL];
__device__ __nv_bfloat16 g_CtxHi[NEL], g_CtxLo[NEL]; // [b,s,e]

// ===========================================================================
// helpers
// ===========================================================================
__device__ __forceinline__ uint32_t smem_u32(const void* p) {
    uint32_t a;
    asm("{ .reg .u64 t; cvta.to.shared.u64 t, %1; cvt.u32.u64 %0, t; }"
        : "=r"(a) : "l"(p));
    return a;
}
__device__ __forceinline__ void ldsm_x4(uint32_t* r, uint32_t addr) {
    asm volatile("ldmatrix.sync.aligned.m8n8.x4.shared.b16 {%0,%1,%2,%3}, [%4];"
                 : "=r"(r[0]), "=r"(r[1]), "=r"(r[2]), "=r"(r[3]) : "r"(addr));
}
__device__ __forceinline__ void ldsm_x2(uint32_t* r, uint32_t addr) {
    asm volatile("ldmatrix.sync.aligned.m8n8.x2.shared.b16 {%0,%1}, [%2];"
                 : "=r"(r[0]), "=r"(r[1]) : "r"(addr));
}
__device__ __forceinline__ void ldsm_x2_t(uint32_t* r, uint32_t addr) {
    asm volatile("ldmatrix.sync.aligned.m8n8.x2.trans.shared.b16 {%0,%1}, [%2];"
                 : "=r"(r[0]), "=r"(r[1]) : "r"(addr));
}
__device__ __forceinline__ void mma_bf16(float* c, const uint32_t* a, const uint32_t* b) {
    asm volatile(
        "mma.sync.aligned.m16n8k16.row.col.f32.bf16.bf16.f32 "
        "{%0,%1,%2,%3}, {%4,%5,%6,%7}, {%8,%9}, {%0,%1,%2,%3};"
        : "+f"(c[0]), "+f"(c[1]), "+f"(c[2]), "+f"(c[3])
        : "r"(a[0]), "r"(a[1]), "r"(a[2]), "r"(a[3]), "r"(b[0]), "r"(b[1]));
}
__device__ __forceinline__ void cp_async16(uint32_t saddr, const void* gptr) {
    asm volatile("cp.async.ca.shared.global [%0], [%1], 16;"
                 :: "r"(saddr), "l"(gptr));
}
#define CP_COMMIT() asm volatile("cp.async.commit_group;" ::: "memory")
#define CP_WAIT1()  asm volatile("cp.async.wait_group 1;" ::: "memory")
#define CP_WAIT0()  asm volatile("cp.async.wait_group 0;" ::: "memory")

// fp32 -> (hi, lo) bf16 split, packed as bf16x2 words
__device__ __forceinline__ void split2(float x, float y, uint32_t& hi, uint32_t& lo) {
    __nv_bfloat16 hx = __float2bfloat16_rn(x);
    __nv_bfloat16 hy = __float2bfloat16_rn(y);
    float rx = x - __bfloat162float(hx);
    float ry = y - __bfloat162float(hy);
    __nv_bfloat16 lx = __float2bfloat16_rn(rx);
    __nv_bfloat16 ly = __float2bfloat16_rn(ry);
    hi = ((uint32_t)__bfloat16_as_ushort(hy) << 16) | (uint32_t)__bfloat16_as_ushort(hx);
    lo = ((uint32_t)__bfloat16_as_ushort(ly) << 16) | (uint32_t)__bfloat16_as_ushort(lx);
}

// ===========================================================================
// split kernels: fp32 -> bf16 hi/lo
// ===========================================================================
template <int IDX>
__global__ __launch_bounds__(256) void split_in_kernel(const float* __restrict__ src) {
    int i = blockIdx.x * 256 + threadIdx.x;       // float4 index
    float4 v = ((const float4*)src)[i];
    uint32_t h0, l0, h1, l1;
    split2(v.x, v.y, h0, l0);
    split2(v.z, v.w, h1, l1);
    ((uint2*)g_InHi[IDX])[i] = make_uint2(h0, h1);
    ((uint2*)g_InLo[IDX])[i] = make_uint2(l0, l1);
}
template <int IDX>
__global__ __launch_bounds__(256) void split_w_kernel(const float* __restrict__ src) {
    int i = blockIdx.x * 256 + threadIdx.x;
    float4 v = ((const float4*)src)[i];
    uint32_t h0, l0, h1, l1;
    split2(v.x, v.y, h0, l0);
    split2(v.z, v.w, h1, l1);
    ((uint2*)g_WHi[IDX])[i] = make_uint2(h0, h1);
    ((uint2*)g_WLo[IDX])[i] = make_uint2(l0, l1);
}

// ===========================================================================
// GEMM (NT), all-bf16, cp.async double-buffered (unchanged from R6 — passed)
// ===========================================================================
#define T_RS 56
#define T_BYTES (128 * T_RS * 2)        // 14336
#define STAGE_B (4 * T_BYTES)           // 57344
#define GS_SMEM (2 * STAGE_B)           // 114688
#define NSTAGE (PE / 32)                // 32

template <int DST, bool SRCCTX>
__global__ __launch_bounds__(256, 2) void gemm_mma_kernel(float* __restrict__ Cparam)
{
    extern __shared__ __align__(16) char smem[];
    const uint32_t sbase = smem_u32(smem);

    const __nv_bfloat16* Ahi = SRCCTX ? g_CtxHi : g_InHi[DST];
    const __nv_bfloat16* Alo = SRCCTX ? g_CtxLo : g_InLo[DST];
    const __nv_bfloat16* Bhi = g_WHi[DST];
    const __nv_bfloat16* Blo = g_WLo[DST];

    const int tid  = threadIdx.x;
    const int lane = tid & 31;
    const int warp = tid >> 5;
    const int wm = warp >> 2;
    const int wn = warp & 3;
    const int bm = blockIdx.y;
    const int bn = blockIdx.x;

    float acc[4][4][4];
#pragma unroll
    for (int i = 0; i < 4; i++)
#pragma unroll
        for (int j = 0; j < 4; j++)
#pragma unroll
            for (int q = 0; q < 4; q++) acc[i][j][q] = 0.0f;

    const int crow = tid >> 1;
    const int ccol = (tid & 1) * 16;
    const __nv_bfloat16* gAh = Ahi + (size_t)(bm * 128 + crow) * PE + ccol;
    const __nv_bfloat16* gAl = Alo + (size_t)(bm * 128 + crow) * PE + ccol;
    const __nv_bfloat16* gBh = Bhi + (size_t)(bn * 128 + crow) * PE + ccol;
    const __nv_bfloat16* gBl = Blo + (size_t)(bn * 128 + crow) * PE + ccol;
    const uint32_t sOff = (uint32_t)(crow * T_RS + ccol) * 2;

    const uint32_t a_off = ((wm * 64 + (lane & 15)) * T_RS + (lane >> 4) * 8) * 2;
    const uint32_t b_off = ((wn * 32 + (lane & 7)) * T_RS + ((lane >> 3) & 1) * 8) * 2;

    {
        uint32_t d = sbase + sOff;
        cp_async16(d + 0 * T_BYTES,      gAh);
        cp_async16(d + 0 * T_BYTES + 16, gAh + 8);
        cp_async16(d + 1 * T_BYTES,      gAl);
        cp_async16(d + 1 * T_BYTES + 16, gAl + 8);
        cp_async16(d + 2 * T_BYTES,      gBh);
        cp_async16(d + 2 * T_BYTES + 16, gBh + 8);
        cp_async16(d + 3 * T_BYTES,      gBl);
        cp_async16(d + 3 * T_BYTES + 16, gBl + 8);
        CP_COMMIT();
    }

#pragma unroll 1
    for (int s = 0; s < NSTAGE; s++) {
        if (s + 1 < NSTAGE) {
            const int g = (s + 1) * 32;
            uint32_t d = sbase + ((s + 1) & 1) * STAGE_B + sOff;
            cp_async16(d + 0 * T_BYTES,      gAh + g);
            cp_async16(d + 0 * T_BYTES + 16, gAh + g + 8);
            cp_async16(d + 1 * T_BYTES,      gAl + g);
            cp_async16(d + 1 * T_BYTES + 16, gAl + g + 8);
            cp_async16(d + 2 * T_BYTES,      gBh + g);
            cp_async16(d + 2 * T_BYTES + 16, gBh + g + 8);
            cp_async16(d + 3 * T_BYTES,      gBl + g);
            cp_async16(d + 3 * T_BYTES + 16, gBl + g + 8);
            CP_COMMIT();
            CP_WAIT1();
        } else {
            CP_WAIT0();
        }
        __syncthreads();

        const uint32_t bufb = sbase + (s & 1) * STAGE_B;
#pragma unroll
        for (int ks = 0; ks < 32; ks += 16) {
            uint32_t bh[4][2], bl[4][2];
#pragma unroll
            for (int ni = 0; ni < 4; ni++) {
                uint32_t ba = bufb + 2 * T_BYTES + b_off + (ni * 8 * T_RS + ks) * 2;
                ldsm_x2(bh[ni], ba);
                ldsm_x2(bl[ni], ba + T_BYTES);
            }
#pragma unroll
            for (int mi = 0; mi < 4; mi++) {
                uint32_t ah[4], al[4];
                uint32_t aa = bufb + a_off + (mi * 16 * T_RS + ks) * 2;
                ldsm_x4(ah, aa);
                ldsm_x4(al, aa + T_BYTES);
#pragma unroll
                for (int ni = 0; ni < 4; ni++) {
                    mma_bf16(acc[mi][ni], ah, bh[ni]);
                    mma_bf16(acc[mi][ni], ah, bl[ni]);
                    mma_bf16(acc[mi][ni], al, bh[ni]);
                }
            }
        }
        __syncthreads();
    }

    __nv_bfloat16* Dhi = (DST == 0) ? g_QHi : (DST == 1) ? g_KHi : g_VHi;
    __nv_bfloat16* Dlo = (DST == 0) ? g_QLo : (DST == 1) ? g_KLo : g_VLo;
#pragma unroll
    for (int mi = 0; mi < 4; mi++) {
        const int m0 = bm * 128 + wm * 64 + mi * 16 + (lane >> 2);
#pragma unroll
        for (int half = 0; half < 2; half++) {
            const int m = m0 + half * 8;
            const int bb = m >> 11;
            const int ms = m & (PS - 1);
#pragma unroll
            for (int ni = 0; ni < 4; ni++) {
                const int n = bn * 128 + wn * 32 + ni * 8 + (lane & 3) * 2;
                float v0 = acc[mi][ni][half * 2 + 0];
                float v1 = acc[mi][ni][half * 2 + 1];
                if (DST < 3) {
                    const int h = n >> 6;
                    const int d = n & 63;
                    size_t idx = ((size_t)(bb * PH + h) * PS + ms) * PD + d;
                    uint32_t hw, lw;
                    split2(v0, v1, hw, lw);
                    *(uint32_t*)&Dhi[idx] = hw;
                    *(uint32_t*)&Dlo[idx] = lw;
                } else {
                    *(float2*)&Cparam[(size_t)m * PE + n] = make_float2(v0, v1);
                }
            }
        }
    }
}

// ===========================================================================
// Flash attention: 128 Q rows per CTA, 256 threads (8 warps x 16 rows),
// cp.async double-buffered K/V hi/lo tiles (64 k-rows per stage).
// ===========================================================================
#define ATT_RS 72
#define AQT_B (128 * ATT_RS * 2)        // 18432 (Q tile, 128 rows)
#define KV_TILE (64 * ATT_RS * 2)       // 9216
#define S_QHI 0
#define S_QLO AQT_B
#define S_KV (2 * AQT_B)                // 36864
#define KV_STAGE (4 * KV_TILE)          // 36864 : [Khi, Klo, Vhi, Vlo]
#define S_BIAS (S_KV + 2 * KV_STAGE)    // 110592
#define ATT_SMEM (S_BIAS + PS * 4)      // 118784

__global__ __launch_bounds__(256) void attn_mma_kernel(
    const unsigned char* __restrict__ mask,
    const float* __restrict__ gamma)
{
    extern __shared__ __align__(16) char sm[];
    const uint32_t sb = smem_u32(sm);

    const int tid  = threadIdx.x;
    const int lane = tid & 31;
    const int warp = tid >> 5;
    const int qt = blockIdx.x;
    const int h  = blockIdx.y;
    const int b  = blockIdx.z;

    const size_t headBase = (size_t)(b * PH + h) * PS * PD;

    // mask -> f32 bias row
    {
        const unsigned char* mrow = mask + (size_t)b * PS;
        float* biasp = (float*)(sm + S_BIAS);
#pragma unroll
        for (int i = 0; i < PS / 256; i++) {
            int kk = tid + i * 256;
            biasp[kk] = mrow[kk] ? -3.0e38f : 0.0f;
        }
    }

    // Q tile copy (128 rows): thread -> (row = tid>>1, 32-col half)
    {
        const int crow = tid >> 1;
        const int ccol = (tid & 1) * 32;
        const __nv_bfloat16* qh = g_QHi + headBase + (size_t)(qt * 128 + crow) * PD + ccol;
        const __nv_bfloat16* ql = g_QLo + headBase + (size_t)(qt * 128 + crow) * PD + ccol;
        const uint32_t so = (uint32_t)(crow * ATT_RS + ccol) * 2;
#pragma unroll
        for (int q = 0; q < 4; q++) {
            *(uint4*)(sm + S_QHI + so + q * 16) = *(const uint4*)(qh + q * 8);
            *(uint4*)(sm + S_QLO + so + q * 16) = *(const uint4*)(ql + q * 8);
        }
    }

    // K/V cp.async mapping: thread -> (kv row = tid>>2, chunk = tid&3 and +4)
    const int kvrow = tid >> 2;
    const int kvc = (tid & 3) * 16;       // byte offset of 8-elem chunk
    const size_t kvg = headBase + (size_t)kvrow * PD;   // +kt*64*PD later
    const uint32_t kvs = (uint32_t)(kvrow * ATT_RS * 2 + kvc);

    const __nv_bfloat16* KH = g_KHi + kvg;
    const __nv_bfloat16* KL = g_KLo + kvg;
    const __nv_bfloat16* VH = g_VHi + kvg;
    const __nv_bfloat16* VL = g_VLo + kvg;

#define KV_ISSUE(stagebuf, kt_)  do {                                          \
        const size_t go = (size_t)(kt_) * 64 * PD;                             \
        uint32_t d = sb + S_KV + (stagebuf) * KV_STAGE + kvs;                  \
        cp_async16(d + 0 * KV_TILE,      KH + go + (kvc >> 1));                \
        cp_async16(d + 0 * KV_TILE + 64, KH + go + (kvc >> 1) + 32);           \
        cp_async16(d + 1 * KV_TILE,      KL + go + (kvc >> 1));                \
        cp_async16(d + 1 * KV_TILE + 64, KL + go + (kvc >> 1) + 32);           \
        cp_async16(d + 2 * KV_TILE,      VH + go + (kvc >> 1));                \
        cp_async16(d + 2 * KV_TILE + 64, VH + go + (kvc >> 1) + 32);           \
        cp_async16(d + 3 * KV_TILE,      VL + go + (kvc >> 1));                \
        cp_async16(d + 3 * KV_TILE + 64, VL + go + (kvc >> 1) + 32);           \
        CP_COMMIT();                                                           \
    } while (0)

    // fragment addresses
    const uint32_t qa = sb + S_QHI + ((warp * 16 + (lane & 15)) * ATT_RS + (lane >> 4) * 8) * 2;
    const uint32_t kb_off = ((lane & 7) * ATT_RS + ((lane >> 3) & 1) * 8) * 2;
    const uint32_t vb_off = ((lane & 15) * ATT_RS) * 2;

    float o[8][4];
#pragma unroll
    for (int nj = 0; nj < 8; nj++)
#pragma unroll
        for (int q = 0; q < 4; q++) o[nj][q] = 0.0f;
    float m0 = -3.0e38f, m1 = -3.0e38f, l0 = 0.0f, l1 = 0.0f;

    KV_ISSUE(0, 0);

#pragma unroll 1
    for (int kt = 0; kt < PS / 64; kt++) {
        if (kt + 1 < PS / 64) {
            KV_ISSUE((kt + 1) & 1, kt + 1);
            CP_WAIT1();
        } else {
            CP_WAIT0();
        }
        __syncthreads();   // stage kt visible (and Q/bias on kt==0)

        const uint32_t stage = sb + S_KV + (kt & 1) * KV_STAGE;
        const uint32_t kb = stage + kb_off;
        const uint32_t vb = stage + 2 * KV_TILE + vb_off;

        // ---- S = Q K^T ----
        float sa[8][4];
#pragma unroll
        for (int ni = 0; ni < 8; ni++)
#pragma unroll
            for (int q = 0; q < 4; q++) sa[ni][q] = 0.0f;

#pragma unroll
        for (int ks = 0; ks < 4; ks++) {
            uint32_t qh[4], ql[4];
            ldsm_x4(qh, qa + ks * 32);
            ldsm_x4(ql, qa + (S_QLO - S_QHI) + ks * 32);
#pragma unroll
            for (int ni = 0; ni < 8; ni++) {
                uint32_t kh[2], kl[2];
                uint32_t ba = kb + ni * (8 * ATT_RS * 2) + ks * 32;
                ldsm_x2(kh, ba);
                ldsm_x2(kl, ba + KV_TILE);
                mma_bf16(sa[ni], qh, kh);
                mma_bf16(sa[ni], qh, kl);
                mma_bf16(sa[ni], ql, kh);
            }
        }

        // ---- scale + bias + online softmax ----
        float mx0 = -3.0e38f, mx1 = -3.0e38f;
#pragma unroll
        for (int ni = 0; ni < 8; ni++) {
            float2 bias = *(const float2*)(sm + S_BIAS + (kt * 64 + ni * 8 + (lane & 3) * 2) * 4);
            sa[ni][0] = sa[ni][0] * 0.125f + bias.x;
            sa[ni][1] = sa[ni][1] * 0.125f + bias.y;
            sa[ni][2] = sa[ni][2] * 0.125f + bias.x;
            sa[ni][3] = sa[ni][3] * 0.125f + bias.y;
            mx0 = fmaxf(mx0, fmaxf(sa[ni][0], sa[ni][1]));
            mx1 = fmaxf(mx1, fmaxf(sa[ni][2], sa[ni][3]));
        }
        mx0 = fmaxf(mx0, __shfl_xor_sync(0xffffffffu, mx0, 1));
        mx0 = fmaxf(mx0, __shfl_xor_sync(0xffffffffu, mx0, 2));
        mx1 = fmaxf(mx1, __shfl_xor_sync(0xffffffffu, mx1, 1));
        mx1 = fmaxf(mx1, __shfl_xor_sync(0xffffffffu, mx1, 2));

        float mn0 = fmaxf(m0, mx0);
        float mn1 = fmaxf(m1, mx1);
        float csc0 = __expf(m0 - mn0);
        float csc1 = __expf(m1 - mn1);
        m0 = mn0; m1 = mn1;

        float ls0 = 0.0f, ls1 = 0.0f;
#pragma unroll
        for (int ni = 0; ni < 8; ni++) {
            sa[ni][0] = __expf(sa[ni][0] - mn0);
            sa[ni][1] = __expf(sa[ni][1] - mn0);
            sa[ni][2] = __expf(sa[ni][2] - mn1);
            sa[ni][3] = __expf(sa[ni][3] - mn1);
            ls0 += sa[ni][0] + sa[ni][1];
            ls1 += sa[ni][2] + sa[ni][3];
        }
        ls0 += __shfl_xor_sync(0xffffffffu, ls0, 1);
        ls0 += __shfl_xor_sync(0xffffffffu, ls0, 2);
        ls1 += __shfl_xor_sync(0xffffffffu, ls1, 1);
        ls1 += __shfl_xor_sync(0xffffffffu, ls1, 2);
        l0 = l0 * csc0 + ls0;
        l1 = l1 * csc1 + ls1;

#pragma unroll
        for (int nj = 0; nj < 8; nj++) {
            o[nj][0] *= csc0; o[nj][1] *= csc0;
            o[nj][2] *= csc1; o[nj][3] *= csc1;
        }

        // ---- O += P V ----
#pragma unroll
        for (int ks = 0; ks < 4; ks++) {
            const float* t0 = sa[2 * ks];
            const float* t1 = sa[2 * ks + 1];
            uint32_t ah[4], al[4];
            split2(t0[0], t0[1], ah[0], al[0]);
            split2(t0[2], t0[3], ah[1], al[1]);
            split2(t1[0], t1[1], ah[2], al[2]);
            split2(t1[2], t1[3], ah[3], al[3]);
#pragma unroll
            for (int nj = 0; nj < 8; nj++) {
                uint32_t vh[2], vl[2];
                uint32_t va = vb + ks * (16 * ATT_RS * 2) + nj * 16;
                ldsm_x2_t(vh, va);
                ldsm_x2_t(vl, va + KV_TILE);
                mma_bf16(o[nj], ah, vh);
                mma_bf16(o[nj], ah, vl);
                mma_bf16(o[nj], al, vh);
            }
        }
        __syncthreads();   // done reading buf (kt&1) before next refill
    }

    // ---- epilogue: gamma / l, split, write Ctx hi/lo ----
    const float gsc = gamma[h];
    const float inv0 = gsc / l0;
    const float inv1 = gsc / l1;
    const int r0 = qt * 128 + warp * 16 + (lane >> 2);
    const size_t base0 = ((size_t)b * PS + r0) * PE + h * PD;
    const size_t base1 = base0 + (size_t)8 * PE;
#pragma unroll
    for (int nj = 0; nj < 8; nj++) {
        const int col = nj * 8 + (lane & 3) * 2;
        uint32_t hw, lw;
        split2(o[nj][0] * inv0, o[nj][1] * inv0, hw, lw);
        *(uint32_t*)&g_CtxHi[base0 + col] = hw;
        *(uint32_t*)&g_CtxLo[base0 + col] = lw;
        split2(o[nj][2] * inv1, o[nj][3] * inv1, hw, lw);
        *(uint32_t*)&g_CtxHi[base1 + col] = hw;
        *(uint32_t*)&g_CtxLo[base1 + col] = lw;
    }
}

// ---------------------------------------------------------------------------
extern "C" void kernel_launch(void* const* d_in, const int* in_sizes, int n_in,
                              void* d_out, int out_size)
{
    const float* query = (const float*)d_in[0];
    const float* key   = (const float*)d_in[1];
    const float* value = (const float*)d_in[2];
    const unsigned char* mask = (const unsigned char*)d_in[3];
    const float* Wq = (const float*)d_in[4];
    const float* Wk = (const float*)d_in[5];
    const float* Wv = (const float*)d_in[6];
    const float* Wo = (const float*)d_in[7];
    const float* gamma = (const float*)d_in[8];

    cudaFuncSetAttribute(gemm_mma_kernel<0, false>,
                         cudaFuncAttributeMaxDynamicSharedMemorySize, GS_SMEM);
    cudaFuncSetAttribute(gemm_mma_kernel<1, false>,
                         cudaFuncAttributeMaxDynamicSharedMemorySize, GS_SMEM);
    cudaFuncSetAttribute(gemm_mma_kernel<2, false>,
                         cudaFuncAttributeMaxDynamicSharedMemorySize, GS_SMEM);
    cudaFuncSetAttribute(gemm_mma_kernel<3, true>,
                         cudaFuncAttributeMaxDynamicSharedMemorySize, GS_SMEM);
    cudaFuncSetAttribute(attn_mma_kernel,
                         cudaFuncAttributeMaxDynamicSharedMemorySize, ATT_SMEM);

    // pre-split inputs and weights
    split_in_kernel<0><<<NEL / 4 / 256, 256>>>(query);
    split_in_kernel<1><<<NEL / 4 / 256, 256>>>(key);
    split_in_kernel<2><<<NEL / 4 / 256, 256>>>(value);
    split_w_kernel<0><<<PE * PE / 4 / 256, 256>>>(Wq);
    split_w_kernel<1><<<PE * PE / 4 / 256, 256>>>(Wk);
    split_w_kernel<2><<<PE * PE / 4 / 256, 256>>>(Wv);
    split_w_kernel<3><<<PE * PE / 4 / 256, 256>>>(Wo);

    dim3 gp(PE / 128, PM / 128);   // (8, 64)
    gemm_mma_kernel<0, false><<<gp, 256, GS_SMEM>>>(nullptr);
    gemm_mma_kernel<1, false><<<gp, 256, GS_SMEM>>>(nullptr);
    gemm_mma_kernel<2, false><<<gp, 256, GS_SMEM>>>(nullptr);

    attn_mma_kernel<<<dim3(PS / 128, PH, PB), 256, ATT_SMEM>>>(mask, gamma);

    gemm_mma_kernel<3, true><<<gp, 256, GS_SMEM>>>((float*)d_out);
}

// round 9
// speedup vs baseline: 2.4292x; 1.0346x over previous
#include <cuda_runtime.h>
#include <cuda_bf16.h>
#include <cstdint>

// Problem constants
#define PB 4
#define PS 2048
#define PE 1024
#define PH 16
#define PD 64
#define PM (PB * PS)   // 8192
#define NEL (PM * PE)  // 8388608

// ---------------------------------------------------------------------------
// Persistent bf16 hi/lo scratch (device globals: allocation-free)
// ---------------------------------------------------------------------------
__device__ __nv_bfloat16 g_InHi[3][NEL];     // split query/key/value
__device__ __nv_bfloat16 g_InLo[3][NEL];
__device__ __nv_bfloat16 g_WHi[4][PE * PE];  // split Wq,Wk,Wv,Wo
__device__ __nv_bfloat16 g_WLo[4][PE * PE];
__device__ __nv_bfloat16 g_QHi[NEL], g_QLo[NEL];   // [b,h,s,d]
__device__ __nv_bfloat16 g_KHi[NEL], g_KLo[NEL];
__device__ __nv_bfloat16 g_VHi[NEL], g_VLo[NEL];
__device__ __nv_bfloat16 g_CtxHi[NEL], g_CtxLo[NEL]; // [b,s,e]

// ===========================================================================
// helpers
// ===========================================================================
__device__ __forceinline__ uint32_t smem_u32(const void* p) {
    uint32_t a;
    asm("{ .reg .u64 t; cvta.to.shared.u64 t, %1; cvt.u32.u64 %0, t; }"
        : "=r"(a) : "l"(p));
    return a;
}
__device__ __forceinline__ void ldsm_x4(uint32_t* r, uint32_t addr) {
    asm volatile("ldmatrix.sync.aligned.m8n8.x4.shared.b16 {%0,%1,%2,%3}, [%4];"
                 : "=r"(r[0]), "=r"(r[1]), "=r"(r[2]), "=r"(r[3]) : "r"(addr));
}
__device__ __forceinline__ void ldsm_x2(uint32_t* r, uint32_t addr) {
    asm volatile("ldmatrix.sync.aligned.m8n8.x2.shared.b16 {%0,%1}, [%2];"
                 : "=r"(r[0]), "=r"(r[1]) : "r"(addr));
}
__device__ __forceinline__ void ldsm_x2_t(uint32_t* r, uint32_t addr) {
    asm volatile("ldmatrix.sync.aligned.m8n8.x2.trans.shared.b16 {%0,%1}, [%2];"
                 : "=r"(r[0]), "=r"(r[1]) : "r"(addr));
}
__device__ __forceinline__ void mma_bf16(float* c, const uint32_t* a, const uint32_t* b) {
    asm volatile(
        "mma.sync.aligned.m16n8k16.row.col.f32.bf16.bf16.f32 "
        "{%0,%1,%2,%3}, {%4,%5,%6,%7}, {%8,%9}, {%0,%1,%2,%3};"
        : "+f"(c[0]), "+f"(c[1]), "+f"(c[2]), "+f"(c[3])
        : "r"(a[0]), "r"(a[1]), "r"(a[2]), "r"(a[3]), "r"(b[0]), "r"(b[1]));
}
__device__ __forceinline__ void cp_async16(uint32_t saddr, const void* gptr) {
    asm volatile("cp.async.ca.shared.global [%0], [%1], 16;"
                 :: "r"(saddr), "l"(gptr));
}
#define CP_COMMIT() asm volatile("cp.async.commit_group;" ::: "memory")
#define CP_WAIT1()  asm volatile("cp.async.wait_group 1;" ::: "memory")
#define CP_WAIT0()  asm volatile("cp.async.wait_group 0;" ::: "memory")

// fp32 -> (hi, lo) bf16 split, packed as bf16x2 words
__device__ __forceinline__ void split2(float x, float y, uint32_t& hi, uint32_t& lo) {
    __nv_bfloat16 hx = __float2bfloat16_rn(x);
    __nv_bfloat16 hy = __float2bfloat16_rn(y);
    float rx = x - __bfloat162float(hx);
    float ry = y - __bfloat162float(hy);
    __nv_bfloat16 lx = __float2bfloat16_rn(rx);
    __nv_bfloat16 ly = __float2bfloat16_rn(ry);
    hi = ((uint32_t)__bfloat16_as_ushort(hy) << 16) | (uint32_t)__bfloat16_as_ushort(hx);
    lo = ((uint32_t)__bfloat16_as_ushort(ly) << 16) | (uint32_t)__bfloat16_as_ushort(lx);
}

// ===========================================================================
// split kernels
// ===========================================================================
template <int IDX>
__global__ __launch_bounds__(256) void split_in_kernel(const float* __restrict__ src) {
    int i = blockIdx.x * 256 + threadIdx.x;
    float4 v = ((const float4*)src)[i];
    uint32_t h0, l0, h1, l1;
    split2(v.x, v.y, h0, l0);
    split2(v.z, v.w, h1, l1);
    ((uint2*)g_InHi[IDX])[i] = make_uint2(h0, h1);
    ((uint2*)g_InLo[IDX])[i] = make_uint2(l0, l1);
}
template <int IDX>
__global__ __launch_bounds__(256) void split_w_kernel(const float* __restrict__ src) {
    int i = blockIdx.x * 256 + threadIdx.x;
    float4 v = ((const float4*)src)[i];
    uint32_t h0, l0, h1, l1;
    split2(v.x, v.y, h0, l0);
    split2(v.z, v.w, h1, l1);
    ((uint2*)g_WHi[IDX])[i] = make_uint2(h0, h1);
    ((uint2*)g_WLo[IDX])[i] = make_uint2(l0, l1);
}

// ===========================================================================
// GEMM (NT), all-bf16, BK=16, 3-stage cp.async pipeline, 1 sync/stage.
// OUTP=false: fused QKV, grid (24, 64): sel = bx>>3 picks {query,key,value}
//             x {Wq,Wk,Wv}; writes bf16 hi/lo [b,h,s,d].
// OUTP=true:  Ctx @ Wo^T, grid (8, 64), fp32 out.
// ===========================================================================
#define RS2 24                            // row stride (elems) for 16-col tile
#define T2_BYTES (128 * RS2 * 2)          // 6144
#define STAGE2_B (4 * T2_BYTES)           // 24576 : [Ahi, Alo, Bhi, Blo]
#define GS_SMEM (3 * STAGE2_B)            // 73728
#define NST2 (PE / 16)                    // 64

template <bool OUTP>
__global__ __launch_bounds__(256, 2) void gemm_mma_kernel(float* __restrict__ Cparam)
{
    extern __shared__ __align__(16) char smem[];
    const uint32_t sbase = smem_u32(smem);

    const int sel = OUTP ? 3 : (blockIdx.x >> 3);
    const int bn  = OUTP ? blockIdx.x : (blockIdx.x & 7);
    const int bm  = blockIdx.y;

    const __nv_bfloat16* Ahi = OUTP ? g_CtxHi : g_InHi[sel];
    const __nv_bfloat16* Alo = OUTP ? g_CtxLo : g_InLo[sel];
    const __nv_bfloat16* Bhi = g_WHi[sel];
    const __nv_bfloat16* Blo = g_WLo[sel];

    const int tid  = threadIdx.x;
    const int lane = tid & 31;
    const int warp = tid >> 5;
    const int wm = warp >> 2;
    const int wn = warp & 3;

    float acc[4][4][4];
#pragma unroll
    for (int i = 0; i < 4; i++)
#pragma unroll
        for (int j = 0; j < 4; j++)
#pragma unroll
            for (int q = 0; q < 4; q++) acc[i][j][q] = 0.0f;

    // copy mapping: thread -> (row = tid>>1, 8-elem half = tid&1); 1 cp/tile
    const int crow = tid >> 1;
    const int chalf = tid & 1;
    const __nv_bfloat16* gAh = Ahi + (size_t)(bm * 128 + crow) * PE + chalf * 8;
    const __nv_bfloat16* gAl = Alo + (size_t)(bm * 128 + crow) * PE + chalf * 8;
    const __nv_bfloat16* gBh = Bhi + (size_t)(bn * 128 + crow) * PE + chalf * 8;
    const __nv_bfloat16* gBl = Blo + (size_t)(bn * 128 + crow) * PE + chalf * 8;
    const uint32_t sOff = (uint32_t)(crow * RS2 * 2 + chalf * 16);

    const uint32_t a_off = ((wm * 64 + (lane & 15)) * RS2 + (lane >> 4) * 8) * 2;
    const uint32_t b_off = ((wn * 32 + (lane & 7)) * RS2 + ((lane >> 3) & 1) * 8) * 2;

#define G_ISSUE(st_) do {                                                      \
        const int g_ = (st_) * 16;                                             \
        uint32_t d_ = sbase + ((st_) % 3) * STAGE2_B + sOff;                   \
        cp_async16(d_ + 0 * T2_BYTES, gAh + g_);                               \
        cp_async16(d_ + 1 * T2_BYTES, gAl + g_);                               \
        cp_async16(d_ + 2 * T2_BYTES, gBh + g_);                               \
        cp_async16(d_ + 3 * T2_BYTES, gBl + g_);                               \
        CP_COMMIT();                                                           \
    } while (0)

    G_ISSUE(0);
    G_ISSUE(1);

#pragma unroll 1
    for (int s = 0; s < NST2; s++) {
        if (s + 1 < NST2) { CP_WAIT1(); } else { CP_WAIT0(); }
        __syncthreads();                 // stage s landed; prior reads done
        if (s + 2 < NST2) G_ISSUE(s + 2);

        const uint32_t bufb = sbase + (s % 3) * STAGE2_B;
        uint32_t bh[4][2], bl[4][2];
#pragma unroll
        for (int ni = 0; ni < 4; ni++) {
            uint32_t ba = bufb + 2 * T2_BYTES + b_off + (ni * 8 * RS2) * 2;
            ldsm_x2(bh[ni], ba);
            ldsm_x2(bl[ni], ba + T2_BYTES);
        }
#pragma unroll
        for (int mi = 0; mi < 4; mi++) {
            uint32_t ah[4], al[4];
            uint32_t aa = bufb + a_off + (mi * 16 * RS2) * 2;
            ldsm_x4(ah, aa);
            ldsm_x4(al, aa + T2_BYTES);
#pragma unroll
            for (int ni = 0; ni < 4; ni++) {
                mma_bf16(acc[mi][ni], ah, bh[ni]);
                mma_bf16(acc[mi][ni], ah, bl[ni]);
                mma_bf16(acc[mi][ni], al, bh[ni]);
            }
        }
    }

    // ---- epilogue ----
    __nv_bfloat16* Dhi = (sel == 0) ? g_QHi : (sel == 1) ? g_KHi : g_VHi;
    __nv_bfloat16* Dlo = (sel == 0) ? g_QLo : (sel == 1) ? g_KLo : g_VLo;
#pragma unroll
    for (int mi = 0; mi < 4; mi++) {
        const int m0 = bm * 128 + wm * 64 + mi * 16 + (lane >> 2);
#pragma unroll
        for (int half = 0; half < 2; half++) {
            const int m = m0 + half * 8;
            const int bb = m >> 11;
            const int ms = m & (PS - 1);
#pragma unroll
            for (int ni = 0; ni < 4; ni++) {
                const int n = bn * 128 + wn * 32 + ni * 8 + (lane & 3) * 2;
                float v0 = acc[mi][ni][half * 2 + 0];
                float v1 = acc[mi][ni][half * 2 + 1];
                if (!OUTP) {
                    const int h = n >> 6;
                    const int d = n & 63;
                    size_t idx = ((size_t)(bb * PH + h) * PS + ms) * PD + d;
                    uint32_t hw, lw;
                    split2(v0, v1, hw, lw);
                    *(uint32_t*)&Dhi[idx] = hw;
                    *(uint32_t*)&Dlo[idx] = lw;
                } else {
                    *(float2*)&Cparam[(size_t)m * PE + n] = make_float2(v0, v1);
                }
            }
        }
    }
}

// ===========================================================================
// Flash attention: 128 Q rows/CTA, 256 threads, 3-stage cp.async KV pipeline,
// 1 sync per K-iteration.
// ===========================================================================
#define ATT_RS 72
#define AQT_B (128 * ATT_RS * 2)        // 18432 (one Q tile)
#define KV_TILE (64 * ATT_RS * 2)       // 9216
#define S_QHI 0
#define S_QLO AQT_B
#define S_KV (2 * AQT_B)                // 36864
#define KV_STAGE (4 * KV_TILE)          // 36864 : [Khi, Klo, Vhi, Vlo]
#define S_BIAS (S_KV + 3 * KV_STAGE)    // 147456
#define ATT_SMEM (S_BIAS + PS * 4)      // 155648
#define NKT (PS / 64)                   // 32

__global__ __launch_bounds__(256) void attn_mma_kernel(
    const unsigned char* __restrict__ mask,
    const float* __restrict__ gamma)
{
    extern __shared__ __align__(16) char sm[];
    const uint32_t sb = smem_u32(sm);

    const int tid  = threadIdx.x;
    const int lane = tid & 31;
    const int warp = tid >> 5;
    const int qt = blockIdx.x;
    const int h  = blockIdx.y;
    const int b  = blockIdx.z;

    const size_t headBase = (size_t)(b * PH + h) * PS * PD;

    // K/V cp.async mapping
    const int kvrow = tid >> 2;
    const int kvc = (tid & 3) * 16;
    const size_t kvg = headBase + (size_t)kvrow * PD;
    const uint32_t kvs = (uint32_t)(kvrow * ATT_RS * 2 + kvc);
    const __nv_bfloat16* KH = g_KHi + kvg;
    const __nv_bfloat16* KL = g_KLo + kvg;
    const __nv_bfloat16* VH = g_VHi + kvg;
    const __nv_bfloat16* VL = g_VLo + kvg;

#define KV_ISSUE(kt_)  do {                                                    \
        const size_t go = (size_t)(kt_) * 64 * PD;                             \
        uint32_t d = sb + S_KV + ((kt_) % 3) * KV_STAGE + kvs;                 \
        cp_async16(d + 0 * KV_TILE,      KH + go + (kvc >> 1));                \
        cp_async16(d + 0 * KV_TILE + 64, KH + go + (kvc >> 1) + 32);           \
        cp_async16(d + 1 * KV_TILE,      KL + go + (kvc >> 1));                \
        cp_async16(d + 1 * KV_TILE + 64, KL + go + (kvc >> 1) + 32);           \
        cp_async16(d + 2 * KV_TILE,      VH + go + (kvc >> 1));                \
        cp_async16(d + 2 * KV_TILE + 64, VH + go + (kvc >> 1) + 32);           \
        cp_async16(d + 3 * KV_TILE,      VL + go + (kvc >> 1));                \
        cp_async16(d + 3 * KV_TILE + 64, VL + go + (kvc >> 1) + 32);           \
        CP_COMMIT();                                                           \
    } while (0)

    KV_ISSUE(0);
    KV_ISSUE(1);

    // mask -> f32 bias row
    {
        const unsigned char* mrow = mask + (size_t)b * PS;
        float* biasp = (float*)(sm + S_BIAS);
#pragma unroll
        for (int i = 0; i < PS / 256; i++) {
            int kk = tid + i * 256;
            biasp[kk] = mrow[kk] ? -3.0e38f : 0.0f;
        }
    }

    // Q tile copy (plain LDG/STS — covered by first loop sync)
    {
        const int crow = tid >> 1;
        const int ccol = (tid & 1) * 32;
        const __nv_bfloat16* qh = g_QHi + headBase + (size_t)(qt * 128 + crow) * PD + ccol;
        const __nv_bfloat16* ql = g_QLo + headBase + (size_t)(qt * 128 + crow) * PD + ccol;
        const uint32_t so = (uint32_t)(crow * ATT_RS + ccol) * 2;
#pragma unroll
        for (int q = 0; q < 4; q++) {
            *(uint4*)(sm + S_QHI + so + q * 16) = *(const uint4*)(qh + q * 8);
            *(uint4*)(sm + S_QLO + so + q * 16) = *(const uint4*)(ql + q * 8);
        }
    }

    const uint32_t qa = sb + S_QHI + ((warp * 16 + (lane & 15)) * ATT_RS + (lane >> 4) * 8) * 2;
    const uint32_t kb_off = ((lane & 7) * ATT_RS + ((lane >> 3) & 1) * 8) * 2;
    const uint32_t vb_off = ((lane & 15) * ATT_RS) * 2;

    float o[8][4];
#pragma unroll
    for (int nj = 0; nj < 8; nj++)
#pragma unroll
        for (int q = 0; q < 4; q++) o[nj][q] = 0.0f;
    float m0 = -3.0e38f, m1 = -3.0e38f, l0 = 0.0f, l1 = 0.0f;

#pragma unroll 1
    for (int kt = 0; kt < NKT; kt++) {
        if (kt + 1 < NKT) { CP_WAIT1(); } else { CP_WAIT0(); }
        __syncthreads();               // stage kt landed; prior reads done
        if (kt + 2 < NKT) KV_ISSUE(kt + 2);

        const uint32_t stage = sb + S_KV + (kt % 3) * KV_STAGE;
        const uint32_t kb = stage + kb_off;
        const uint32_t vb = stage + 2 * KV_TILE + vb_off;

        // ---- S = Q K^T ----
        float sa[8][4];
#pragma unroll
        for (int ni = 0; ni < 8; ni++)
#pragma unroll
            for (int q = 0; q < 4; q++) sa[ni][q] = 0.0f;

#pragma unroll
        for (int ks = 0; ks < 4; ks++) {
            uint32_t qh[4], ql[4];
            ldsm_x4(qh, qa + ks * 32);
            ldsm_x4(ql, qa + (S_QLO - S_QHI) + ks * 32);
#pragma unroll
            for (int ni = 0; ni < 8; ni++) {
                uint32_t kh[2], kl[2];
                uint32_t ba = kb + ni * (8 * ATT_RS * 2) + ks * 32;
                ldsm_x2(kh, ba);
                ldsm_x2(kl, ba + KV_TILE);
                mma_bf16(sa[ni], qh, kh);
                mma_bf16(sa[ni], qh, kl);
                mma_bf16(sa[ni], ql, kh);
            }
        }

        // ---- scale + bias + online softmax ----
        float mx0 = -3.0e38f, mx1 = -3.0e38f;
#pragma unroll
        for (int ni = 0; ni < 8; ni++) {
            float2 bias = *(const float2*)(sm + S_BIAS + (kt * 64 + ni * 8 + (lane & 3) * 2) * 4);
            sa[ni][0] = sa[ni][0] * 0.125f + bias.x;
            sa[ni][1] = sa[ni][1] * 0.125f + bias.y;
            sa[ni][2] = sa[ni][2] * 0.125f + bias.x;
            sa[ni][3] = sa[ni][3] * 0.125f + bias.y;
            mx0 = fmaxf(mx0, fmaxf(sa[ni][0], sa[ni][1]));
            mx1 = fmaxf(mx1, fmaxf(sa[ni][2], sa[ni][3]));
        }
        mx0 = fmaxf(mx0, __shfl_xor_sync(0xffffffffu, mx0, 1));
        mx0 = fmaxf(mx0, __shfl_xor_sync(0xffffffffu, mx0, 2));
        mx1 = fmaxf(mx1, __shfl_xor_sync(0xffffffffu, mx1, 1));
        mx1 = fmaxf(mx1, __shfl_xor_sync(0xffffffffu, mx1, 2));

        float mn0 = fmaxf(m0, mx0);
        float mn1 = fmaxf(m1, mx1);
        float csc0 = __expf(m0 - mn0);
        float csc1 = __expf(m1 - mn1);
        m0 = mn0; m1 = mn1;

        float ls0 = 0.0f, ls1 = 0.0f;
#pragma unroll
        for (int ni = 0; ni < 8; ni++) {
            sa[ni][0] = __expf(sa[ni][0] - mn0);
            sa[ni][1] = __expf(sa[ni][1] - mn0);
            sa[ni][2] = __expf(sa[ni][2] - mn1);
            sa[ni][3] = __expf(sa[ni][3] - mn1);
            ls0 += sa[ni][0] + sa[ni][1];
            ls1 += sa[ni][2] + sa[ni][3];
        }
        ls0 += __shfl_xor_sync(0xffffffffu, ls0, 1);
        ls0 += __shfl_xor_sync(0xffffffffu, ls0, 2);
        ls1 += __shfl_xor_sync(0xffffffffu, ls1, 1);
        ls1 += __shfl_xor_sync(0xffffffffu, ls1, 2);
        l0 = l0 * csc0 + ls0;
        l1 = l1 * csc1 + ls1;

#pragma unroll
        for (int nj = 0; nj < 8; nj++) {
            o[nj][0] *= csc0; o[nj][1] *= csc0;
            o[nj][2] *= csc1; o[nj][3] *= csc1;
        }

        // ---- O += P V ----
#pragma unroll
        for (int ks = 0; ks < 4; ks++) {
            const float* t0 = sa[2 * ks];
            const float* t1 = sa[2 * ks + 1];
            uint32_t ah[4], al[4];
            split2(t0[0], t0[1], ah[0], al[0]);
            split2(t0[2], t0[3], ah[1], al[1]);
            split2(t1[0], t1[1], ah[2], al[2]);
            split2(t1[2], t1[3], ah[3], al[3]);
#pragma unroll
            for (int nj = 0; nj < 8; nj++) {
                uint32_t vh[2], vl[2];
                uint32_t va = vb + ks * (16 * ATT_RS * 2) + nj * 16;
                ldsm_x2_t(vh, va);
                ldsm_x2_t(vl, va + KV_TILE);
                mma_bf16(o[nj], ah, vh);
                mma_bf16(o[nj], ah, vl);
                mma_bf16(o[nj], al, vh);
            }
        }
    }

    // ---- epilogue ----
    const float gsc = gamma[h];
    const float inv0 = gsc / l0;
    const float inv1 = gsc / l1;
    const int r0 = qt * 128 + warp * 16 + (lane >> 2);
    const size_t base0 = ((size_t)b * PS + r0) * PE + h * PD;
    const size_t base1 = base0 + (size_t)8 * PE;
#pragma unroll
    for (int nj = 0; nj < 8; nj++) {
        const int col = nj * 8 + (lane & 3) * 2;
        uint32_t hw, lw;
        split2(o[nj][0] * inv0, o[nj][1] * inv0, hw, lw);
        *(uint32_t*)&g_CtxHi[base0 + col] = hw;
        *(uint32_t*)&g_CtxLo[base0 + col] = lw;
        split2(o[nj][2] * inv1, o[nj][3] * inv1, hw, lw);
        *(uint32_t*)&g_CtxHi[base1 + col] = hw;
        *(uint32_t*)&g_CtxLo[base1 + col] = lw;
    }
}

// ---------------------------------------------------------------------------
extern "C" void kernel_launch(void* const* d_in, const int* in_sizes, int n_in,
                              void* d_out, int out_size)
{
    const float* query = (const float*)d_in[0];
    const float* key   = (const float*)d_in[1];
    const float* value = (const float*)d_in[2];
    const unsigned char* mask = (const unsigned char*)d_in[3];
    const float* Wq = (const float*)d_in[4];
    const float* Wk = (const float*)d_in[5];
    const float* Wv = (const float*)d_in[6];
    const float* Wo = (const float*)d_in[7];
    const float* gamma = (const float*)d_in[8];

    cudaFuncSetAttribute(gemm_mma_kernel<false>,
                         cudaFuncAttributeMaxDynamicSharedMemorySize, GS_SMEM);
    cudaFuncSetAttribute(gemm_mma_kernel<true>,
                         cudaFuncAttributeMaxDynamicSharedMemorySize, GS_SMEM);
    cudaFuncSetAttribute(attn_mma_kernel,
                         cudaFuncAttributeMaxDynamicSharedMemorySize, ATT_SMEM);

    // pre-split inputs and weights
    split_in_kernel<0><<<NEL / 4 / 256, 256>>>(query);
    split_in_kernel<1><<<NEL / 4 / 256, 256>>>(key);
    split_in_kernel<2><<<NEL / 4 / 256, 256>>>(value);
    split_w_kernel<0><<<PE * PE / 4 / 256, 256>>>(Wq);
    split_w_kernel<1><<<PE * PE / 4 / 256, 256>>>(Wk);
    split_w_kernel<2><<<PE * PE / 4 / 256, 256>>>(Wv);
    split_w_kernel<3><<<PE * PE / 4 / 256, 256>>>(Wo);

    // fused Q/K/V projections: grid.x = 3 weights x 8 n-tiles
    gemm_mma_kernel<false><<<dim3(24, PM / 128), 256, GS_SMEM>>>(nullptr);

    attn_mma_kernel<<<dim3(PS / 128, PH, PB), 256, ATT_SMEM>>>(mask, gamma);

    gemm_mma_kernel<true><<<dim3(8, PM / 128), 256, GS_SMEM>>>((float*)d_out);
}

// round 10
// speedup vs baseline: 3.5659x; 1.4680x over previous
#include <cuda_runtime.h>
#include <cuda_fp16.h>
#include <cstdint>

// Problem constants
#define PB 4
#define PS 2048
#define PE 1024
#define PH 16
#define PD 64
#define PM (PB * PS)   // 8192
#define NEL (PM * PE)  // 8388608

// ---------------------------------------------------------------------------
// Persistent fp16 scratch (device globals: allocation-free)
// 2-term split scheme: lo-planes kept only where needed.
// ---------------------------------------------------------------------------
__device__ __half g_InHi[3][NEL], g_InLo[3][NEL];   // split query/key/value
__device__ __half g_WHi[4][PE * PE];                // weights: hi only
__device__ __half g_QHi[NEL], g_QLo[NEL];           // Q: 2-term   [b,h,s,d]
__device__ __half g_KHi[NEL];                       // K: 1-term
__device__ __half g_VHi[NEL], g_VLo[NEL];           // V: 2-term
__device__ __half g_CtxHi[NEL], g_CtxLo[NEL];       // Ctx: 2-term [b,s,e]

// ===========================================================================
// helpers
// ===========================================================================
__device__ __forceinline__ uint32_t smem_u32(const void* p) {
    uint32_t a;
    asm("{ .reg .u64 t; cvta.to.shared.u64 t, %1; cvt.u32.u64 %0, t; }"
        : "=r"(a) : "l"(p));
    return a;
}
__device__ __forceinline__ void ldsm_x4(uint32_t* r, uint32_t addr) {
    asm volatile("ldmatrix.sync.aligned.m8n8.x4.shared.b16 {%0,%1,%2,%3}, [%4];"
                 : "=r"(r[0]), "=r"(r[1]), "=r"(r[2]), "=r"(r[3]) : "r"(addr));
}
__device__ __forceinline__ void ldsm_x2(uint32_t* r, uint32_t addr) {
    asm volatile("ldmatrix.sync.aligned.m8n8.x2.shared.b16 {%0,%1}, [%2];"
                 : "=r"(r[0]), "=r"(r[1]) : "r"(addr));
}
__device__ __forceinline__ void ldsm_x2_t(uint32_t* r, uint32_t addr) {
    asm volatile("ldmatrix.sync.aligned.m8n8.x2.trans.shared.b16 {%0,%1}, [%2];"
                 : "=r"(r[0]), "=r"(r[1]) : "r"(addr));
}
__device__ __forceinline__ void mma_f16(float* c, const uint32_t* a, const uint32_t* b) {
    asm volatile(
        "mma.sync.aligned.m16n8k16.row.col.f32.f16.f16.f32 "
        "{%0,%1,%2,%3}, {%4,%5,%6,%7}, {%8,%9}, {%0,%1,%2,%3};"
        : "+f"(c[0]), "+f"(c[1]), "+f"(c[2]), "+f"(c[3])
        : "r"(a[0]), "r"(a[1]), "r"(a[2]), "r"(a[3]), "r"(b[0]), "r"(b[1]));
}
__device__ __forceinline__ void cp_async16(uint32_t saddr, const void* gptr) {
    asm volatile("cp.async.ca.shared.global [%0], [%1], 16;"
                 :: "r"(saddr), "l"(gptr));
}
#define CP_COMMIT() asm volatile("cp.async.commit_group;" ::: "memory")
#define CP_WAIT1()  asm volatile("cp.async.wait_group 1;" ::: "memory")
#define CP_WAIT0()  asm volatile("cp.async.wait_group 0;" ::: "memory")

// fp32 -> (hi, lo) fp16 split, packed as half2 words
__device__ __forceinline__ void split2h(float x, float y, uint32_t& hi, uint32_t& lo) {
    __half hx = __float2half_rn(x);
    __half hy = __float2half_rn(y);
    float rx = x - __half2float(hx);
    float ry = y - __half2float(hy);
    __half lx = __float2half_rn(rx);
    __half ly = __float2half_rn(ry);
    hi = ((uint32_t)__half_as_ushort(hy) << 16) | (uint32_t)__half_as_ushort(hx);
    lo = ((uint32_t)__half_as_ushort(ly) << 16) | (uint32_t)__half_as_ushort(lx);
}
__device__ __forceinline__ uint32_t packh2(float x, float y) {
    __half2 t = __floats2half2_rn(x, y);
    return *(uint32_t*)&t;
}

// ===========================================================================
// prep kernels
// ===========================================================================
template <int IDX>
__global__ __launch_bounds__(256) void split_in_kernel(const float* __restrict__ src) {
    int i = blockIdx.x * 256 + threadIdx.x;       // float4 index
    float4 v = ((const float4*)src)[i];
    uint32_t h0, l0, h1, l1;
    split2h(v.x, v.y, h0, l0);
    split2h(v.z, v.w, h1, l1);
    ((uint2*)g_InHi[IDX])[i] = make_uint2(h0, h1);
    ((uint2*)g_InLo[IDX])[i] = make_uint2(l0, l1);
}
template <int IDX>
__global__ __launch_bounds__(256) void cvt_w_kernel(const float* __restrict__ src) {
    int i = blockIdx.x * 256 + threadIdx.x;
    float4 v = ((const float4*)src)[i];
    ((uint2*)g_WHi[IDX])[i] = make_uint2(packh2(v.x, v.y), packh2(v.z, v.w));
}

// ===========================================================================
// GEMM (NT), fp16 2-term on A, 1-term on B. BK=16, 3-stage cp.async, 1 sync.
// OUTP=false: fused QKV, grid (24, 64); sel = bx>>3.
// OUTP=true:  Ctx @ Wo^T, grid (8, 64), fp32 out.
// Stage tiles: [Ahi, Alo, Bhi].
// ===========================================================================
#define RS2 24                            // row stride (elems) for 16-col tile
#define T2_BYTES (128 * RS2 * 2)          // 6144
#define STAGE2_B (3 * T2_BYTES)           // 18432
#define GS_SMEM (3 * STAGE2_B)            // 55296
#define NST2 (PE / 16)                    // 64

template <bool OUTP>
__global__ __launch_bounds__(256, 2) void gemm_mma_kernel(float* __restrict__ Cparam)
{
    extern __shared__ __align__(16) char smem[];
    const uint32_t sbase = smem_u32(smem);

    const int sel = OUTP ? 3 : (blockIdx.x >> 3);
    const int bn  = OUTP ? blockIdx.x : (blockIdx.x & 7);
    const int bm  = blockIdx.y;

    const __half* Ahi = OUTP ? g_CtxHi : g_InHi[sel];
    const __half* Alo = OUTP ? g_CtxLo : g_InLo[sel];
    const __half* Bhi = g_WHi[sel];

    const int tid  = threadIdx.x;
    const int lane = tid & 31;
    const int warp = tid >> 5;
    const int wm = warp >> 2;
    const int wn = warp & 3;

    float acc[4][4][4];
#pragma unroll
    for (int i = 0; i < 4; i++)
#pragma unroll
        for (int j = 0; j < 4; j++)
#pragma unroll
            for (int q = 0; q < 4; q++) acc[i][j][q] = 0.0f;

    // copy mapping: thread -> (row = tid>>1, 8-elem half = tid&1); 1 cp/tile
    const int crow = tid >> 1;
    const int chalf = tid & 1;
    const __half* gAh = Ahi + (size_t)(bm * 128 + crow) * PE + chalf * 8;
    const __half* gAl = Alo + (size_t)(bm * 128 + crow) * PE + chalf * 8;
    const __half* gBh = Bhi + (size_t)(bn * 128 + crow) * PE + chalf * 8;
    const uint32_t sOff = (uint32_t)(crow * RS2 * 2 + chalf * 16);

    const uint32_t a_off = ((wm * 64 + (lane & 15)) * RS2 + (lane >> 4) * 8) * 2;
    const uint32_t b_off = ((wn * 32 + (lane & 7)) * RS2 + ((lane >> 3) & 1) * 8) * 2;

#define G_ISSUE(st_) do {                                                      \
        const int g_ = (st_) * 16;                                             \
        uint32_t d_ = sbase + ((st_) % 3) * STAGE2_B + sOff;                   \
        cp_async16(d_ + 0 * T2_BYTES, gAh + g_);                               \
        cp_async16(d_ + 1 * T2_BYTES, gAl + g_);                               \
        cp_async16(d_ + 2 * T2_BYTES, gBh + g_);                               \
        CP_COMMIT();                                                           \
    } while (0)

    G_ISSUE(0);
    G_ISSUE(1);

#pragma unroll 1
    for (int s = 0; s < NST2; s++) {
        if (s + 1 < NST2) { CP_WAIT1(); } else { CP_WAIT0(); }
        __syncthreads();                 // stage s landed; prior reads done
        if (s + 2 < NST2) G_ISSUE(s + 2);

        const uint32_t bufb = sbase + (s % 3) * STAGE2_B;
        uint32_t bh[4][2];
#pragma unroll
        for (int ni = 0; ni < 4; ni++)
            ldsm_x2(bh[ni], bufb + 2 * T2_BYTES + b_off + (ni * 8 * RS2) * 2);
#pragma unroll
        for (int mi = 0; mi < 4; mi++) {
            uint32_t ah[4], al[4];
            uint32_t aa = bufb + a_off + (mi * 16 * RS2) * 2;
            ldsm_x4(ah, aa);
            ldsm_x4(al, aa + T2_BYTES);
#pragma unroll
            for (int ni = 0; ni < 4; ni++) {
                mma_f16(acc[mi][ni], ah, bh[ni]);
                mma_f16(acc[mi][ni], al, bh[ni]);
            }
        }
    }

    // ---- epilogue ----
#pragma unroll
    for (int mi = 0; mi < 4; mi++) {
        const int m0 = bm * 128 + wm * 64 + mi * 16 + (lane >> 2);
#pragma unroll
        for (int half = 0; half < 2; half++) {
            const int m = m0 + half * 8;
            const int bb = m >> 11;
            const int ms = m & (PS - 1);
#pragma unroll
            for (int ni = 0; ni < 4; ni++) {
                const int n = bn * 128 + wn * 32 + ni * 8 + (lane & 3) * 2;
                float v0 = acc[mi][ni][half * 2 + 0];
                float v1 = acc[mi][ni][half * 2 + 1];
                if (!OUTP) {
                    const int h = n >> 6;
                    const int d = n & 63;
                    size_t idx = ((size_t)(bb * PH + h) * PS + ms) * PD + d;
                    if (sel == 0) {            // Q: 2-term
                        uint32_t hw, lw;
                        split2h(v0, v1, hw, lw);
                        *(uint32_t*)&g_QHi[idx] = hw;
                        *(uint32_t*)&g_QLo[idx] = lw;
                    } else if (sel == 1) {     // K: 1-term
                        *(uint32_t*)&g_KHi[idx] = packh2(v0, v1);
                    } else {                   // V: 2-term
                        uint32_t hw, lw;
                        split2h(v0, v1, hw, lw);
                        *(uint32_t*)&g_VHi[idx] = hw;
                        *(uint32_t*)&g_VLo[idx] = lw;
                    }
                } else {
                    *(float2*)&Cparam[(size_t)m * PE + n] = make_float2(v0, v1);
                }
            }
        }
    }
}

// ===========================================================================
// Flash attention: 128 Q rows/CTA, 256 threads, 3-stage cp.async KV pipeline.
// S = (Qhi+Qlo)·Khi ; O += cvt16(P)·(Vhi+Vlo).
// ===========================================================================
#define ATT_RS 72
#define AQT_B (128 * ATT_RS * 2)        // 18432 (one Q plane)
#define KV_TILE (64 * ATT_RS * 2)       // 9216
#define S_QHI 0
#define S_QLO AQT_B
#define S_KV (2 * AQT_B)                // 36864
#define KV_STAGE (3 * KV_TILE)          // 27648 : [Khi, Vhi, Vlo]
#define S_BIAS (S_KV + 3 * KV_STAGE)    // 119808
#define ATT_SMEM (S_BIAS + PS * 4)      // 128000
#define NKT (PS / 64)                   // 32

__global__ __launch_bounds__(256) void attn_mma_kernel(
    const unsigned char* __restrict__ mask,
    const float* __restrict__ gamma)
{
    extern __shared__ __align__(16) char sm[];
    const uint32_t sb = smem_u32(sm);

    const int tid  = threadIdx.x;
    const int lane = tid & 31;
    const int warp = tid >> 5;
    const int qt = blockIdx.x;
    const int h  = blockIdx.y;
    const int b  = blockIdx.z;

    const size_t headBase = (size_t)(b * PH + h) * PS * PD;

    // K/V cp.async mapping
    const int kvrow = tid >> 2;
    const int kvc = (tid & 3) * 16;
    const size_t kvg = headBase + (size_t)kvrow * PD;
    const uint32_t kvs = (uint32_t)(kvrow * ATT_RS * 2 + kvc);
    const __half* KH = g_KHi + kvg;
    const __half* VH = g_VHi + kvg;
    const __half* VL = g_VLo + kvg;

#define KV_ISSUE(kt_)  do {                                                    \
        const size_t go = (size_t)(kt_) * 64 * PD;                             \
        uint32_t d = sb + S_KV + ((kt_) % 3) * KV_STAGE + kvs;                 \
        cp_async16(d + 0 * KV_TILE,      KH + go + (kvc >> 1));                \
        cp_async16(d + 0 * KV_TILE + 64, KH + go + (kvc >> 1) + 32);           \
        cp_async16(d + 1 * KV_TILE,      VH + go + (kvc >> 1));                \
        cp_async16(d + 1 * KV_TILE + 64, VH + go + (kvc >> 1) + 32);           \
        cp_async16(d + 2 * KV_TILE,      VL + go + (kvc >> 1));                \
        cp_async16(d + 2 * KV_TILE + 64, VL + go + (kvc >> 1) + 32);           \
        CP_COMMIT();                                                           \
    } while (0)

    KV_ISSUE(0);
    KV_ISSUE(1);

    // mask -> f32 bias row
    {
        const unsigned char* mrow = mask + (size_t)b * PS;
        float* biasp = (float*)(sm + S_BIAS);
#pragma unroll
        for (int i = 0; i < PS / 256; i++) {
            int kk = tid + i * 256;
            biasp[kk] = mrow[kk] ? -3.0e38f : 0.0f;
        }
    }

    // Q tile copy (hi + lo planes)
    {
        const int crow = tid >> 1;
        const int ccol = (tid & 1) * 32;
        const __half* qh = g_QHi + headBase + (size_t)(qt * 128 + crow) * PD + ccol;
        const __half* ql = g_QLo + headBase + (size_t)(qt * 128 + crow) * PD + ccol;
        const uint32_t so = (uint32_t)(crow * ATT_RS + ccol) * 2;
#pragma unroll
        for (int q = 0; q < 4; q++) {
            *(uint4*)(sm + S_QHI + so + q * 16) = *(const uint4*)(qh + q * 8);
            *(uint4*)(sm + S_QLO + so + q * 16) = *(const uint4*)(ql + q * 8);
        }
    }

    const uint32_t qa = sb + S_QHI + ((warp * 16 + (lane & 15)) * ATT_RS + (lane >> 4) * 8) * 2;
    const uint32_t kb_off = ((lane & 7) * ATT_RS + ((lane >> 3) & 1) * 8) * 2;
    const uint32_t vb_off = ((lane & 15) * ATT_RS) * 2;

    float o[8][4];
#pragma unroll
    for (int nj = 0; nj < 8; nj++)
#pragma unroll
        for (int q = 0; q < 4; q++) o[nj][q] = 0.0f;
    float m0 = -3.0e38f, m1 = -3.0e38f, l0 = 0.0f, l1 = 0.0f;

#pragma unroll 1
    for (int kt = 0; kt < NKT; kt++) {
        if (kt + 1 < NKT) { CP_WAIT1(); } else { CP_WAIT0(); }
        __syncthreads();               // stage kt landed; prior reads done
        if (kt + 2 < NKT) KV_ISSUE(kt + 2);

        const uint32_t stage = sb + S_KV + (kt % 3) * KV_STAGE;
        const uint32_t kb = stage + kb_off;
        const uint32_t vb = stage + KV_TILE + vb_off;

        // ---- S = Q K^T ----
        float sa[8][4];
#pragma unroll
        for (int ni = 0; ni < 8; ni++)
#pragma unroll
            for (int q = 0; q < 4; q++) sa[ni][q] = 0.0f;

#pragma unroll
        for (int ks = 0; ks < 4; ks++) {
            uint32_t qh[4], ql[4];
            ldsm_x4(qh, qa + ks * 32);
            ldsm_x4(ql, qa + (S_QLO - S_QHI) + ks * 32);
#pragma unroll
            for (int ni = 0; ni < 8; ni++) {
                uint32_t kh[2];
                ldsm_x2(kh, kb + ni * (8 * ATT_RS * 2) + ks * 32);
                mma_f16(sa[ni], qh, kh);
                mma_f16(sa[ni], ql, kh);
            }
        }

        // ---- scale + bias + online softmax ----
        float mx0 = -3.0e38f, mx1 = -3.0e38f;
#pragma unroll
        for (int ni = 0; ni < 8; ni++) {
            float2 bias = *(const float2*)(sm + S_BIAS + (kt * 64 + ni * 8 + (lane & 3) * 2) * 4);
            sa[ni][0] = sa[ni][0] * 0.125f + bias.x;
            sa[ni][1] = sa[ni][1] * 0.125f + bias.y;
            sa[ni][2] = sa[ni][2] * 0.125f + bias.x;
            sa[ni][3] = sa[ni][3] * 0.125f + bias.y;
            mx0 = fmaxf(mx0, fmaxf(sa[ni][0], sa[ni][1]));
            mx1 = fmaxf(mx1, fmaxf(sa[ni][2], sa[ni][3]));
        }
        mx0 = fmaxf(mx0, __shfl_xor_sync(0xffffffffu, mx0, 1));
        mx0 = fmaxf(mx0, __shfl_xor_sync(0xffffffffu, mx0, 2));
        mx1 = fmaxf(mx1, __shfl_xor_sync(0xffffffffu, mx1, 1));
        mx1 = fmaxf(mx1, __shfl_xor_sync(0xffffffffu, mx1, 2));

        float mn0 = fmaxf(m0, mx0);
        float mn1 = fmaxf(m1, mx1);
        float csc0 = __expf(m0 - mn0);
        float csc1 = __expf(m1 - mn1);
        m0 = mn0; m1 = mn1;

        float ls0 = 0.0f, ls1 = 0.0f;
#pragma unroll
        for (int ni = 0; ni < 8; ni++) {
            sa[ni][0] = __expf(sa[ni][0] - mn0);
            sa[ni][1] = __expf(sa[ni][1] - mn0);
            sa[ni][2] = __expf(sa[ni][2] - mn1);
            sa[ni][3] = __expf(sa[ni][3] - mn1);
            ls0 += sa[ni][0] + sa[ni][1];
            ls1 += sa[ni][2] + sa[ni][3];
        }
        ls0 += __shfl_xor_sync(0xffffffffu, ls0, 1);
        ls0 += __shfl_xor_sync(0xffffffffu, ls0, 2);
        ls1 += __shfl_xor_sync(0xffffffffu, ls1, 1);
        ls1 += __shfl_xor_sync(0xffffffffu, ls1, 2);
        l0 = l0 * csc0 + ls0;
        l1 = l1 * csc1 + ls1;

#pragma unroll
        for (int nj = 0; nj < 8; nj++) {
            o[nj][0] *= csc0; o[nj][1] *= csc0;
            o[nj][2] *= csc1; o[nj][3] *= csc1;
        }

        // ---- O += P V (P 1-term fp16; V hi/lo trans loads) ----
#pragma unroll
        for (int ks = 0; ks < 4; ks++) {
            const float* t0 = sa[2 * ks];
            const float* t1 = sa[2 * ks + 1];
            uint32_t ah[4];
            ah[0] = packh2(t0[0], t0[1]);
            ah[1] = packh2(t0[2], t0[3]);
            ah[2] = packh2(t1[0], t1[1]);
            ah[3] = packh2(t1[2], t1[3]);
#pragma unroll
            for (int nj = 0; nj < 8; nj++) {
                uint32_t vh[2], vl[2];
                uint32_t va = vb + ks * (16 * ATT_RS * 2) + nj * 16;
                ldsm_x2_t(vh, va);
                ldsm_x2_t(vl, va + KV_TILE);
                mma_f16(o[nj], ah, vh);
                mma_f16(o[nj], ah, vl);
            }
        }
    }

    // ---- epilogue: gamma / l, 2-term split, write Ctx hi/lo ----
    const float gsc = gamma[h];
    const float inv0 = gsc / l0;
    const float inv1 = gsc / l1;
    const int r0 = qt * 128 + warp * 16 + (lane >> 2);
    const size_t base0 = ((size_t)b * PS + r0) * PE + h * PD;
    const size_t base1 = base0 + (size_t)8 * PE;
#pragma unroll
    for (int nj = 0; nj < 8; nj++) {
        const int col = nj * 8 + (lane & 3) * 2;
        uint32_t hw, lw;
        split2h(o[nj][0] * inv0, o[nj][1] * inv0, hw, lw);
        *(uint32_t*)&g_CtxHi[base0 + col] = hw;
        *(uint32_t*)&g_CtxLo[base0 + col] = lw;
        split2h(o[nj][2] * inv1, o[nj][3] * inv1, hw, lw);
        *(uint32_t*)&g_CtxHi[base1 + col] = hw;
        *(uint32_t*)&g_CtxLo[base1 + col] = lw;
    }
}

// ---------------------------------------------------------------------------
extern "C" void kernel_launch(void* const* d_in, const int* in_sizes, int n_in,
                              void* d_out, int out_size)
{
    const float* query = (const float*)d_in[0];
    const float* key   = (const float*)d_in[1];
    const float* value = (const float*)d_in[2];
    const unsigned char* mask = (const unsigned char*)d_in[3];
    const float* Wq = (const float*)d_in[4];
    const float* Wk = (const float*)d_in[5];
    const float* Wv = (const float*)d_in[6];
    const float* Wo = (const float*)d_in[7];
    const float* gamma = (const float*)d_in[8];

    cudaFuncSetAttribute(gemm_mma_kernel<false>,
                         cudaFuncAttributeMaxDynamicSharedMemorySize, GS_SMEM);
    cudaFuncSetAttribute(gemm_mma_kernel<true>,
                         cudaFuncAttributeMaxDynamicSharedMemorySize, GS_SMEM);
    cudaFuncSetAttribute(attn_mma_kernel,
                         cudaFuncAttributeMaxDynamicSharedMemorySize, ATT_SMEM);

    // prep: split inputs (hi+lo), convert weights (hi only)
    split_in_kernel<0><<<NEL / 4 / 256, 256>>>(query);
    split_in_kernel<1><<<NEL / 4 / 256, 256>>>(key);
    split_in_kernel<2><<<NEL / 4 / 256, 256>>>(value);
    cvt_w_kernel<0><<<PE * PE / 4 / 256, 256>>>(Wq);
    cvt_w_kernel<1><<<PE * PE / 4 / 256, 256>>>(Wk);
    cvt_w_kernel<2><<<PE * PE / 4 / 256, 256>>>(Wv);
    cvt_w_kernel<3><<<PE * PE / 4 / 256, 256>>>(Wo);

    // fused Q/K/V projections: grid.x = 3 weights x 8 n-tiles
    gemm_mma_kernel<false><<<dim3(24, PM / 128), 256, GS_SMEM>>>(nullptr);

    attn_mma_kernel<<<dim3(PS / 128, PH, PB), 256, ATT_SMEM>>>(mask, gamma);

    gemm_mma_kernel<true><<<dim3(8, PM / 128), 256, GS_SMEM>>>((float*)d_out);
}

// round 11
// speedup vs baseline: 4.4993x; 1.2617x over previous
#include <cuda_runtime.h>
#include <cuda_fp16.h>
#include <cstdint>

// Problem constants
#define PB 4
#define PS 2048
#define PE 1024
#define PH 16
#define PD 64
#define PM (PB * PS)   // 8192
#define NEL (PM * PE)  // 8388608

// ---------------------------------------------------------------------------
// Persistent fp16 scratch (device globals: allocation-free)
// ---------------------------------------------------------------------------
__device__ __half g_InHi[3][NEL], g_InLo[3][NEL];   // split query/key/value
__device__ __half g_WHi[4][PE * PE];                // weights: hi only
__device__ __half g_QHi[NEL];                       // Q: 1-term [b,h,s,d]
__device__ __half g_KHi[NEL];                       // K: 1-term
__device__ __half g_VHi[NEL];                       // V: 1-term
__device__ __half g_CtxHi[NEL], g_CtxLo[NEL];       // Ctx: 2-term [b,s,e]

// ===========================================================================
// helpers
// ===========================================================================
__device__ __forceinline__ uint32_t smem_u32(const void* p) {
    uint32_t a;
    asm("{ .reg .u64 t; cvta.to.shared.u64 t, %1; cvt.u32.u64 %0, t; }"
        : "=r"(a) : "l"(p));
    return a;
}
__device__ __forceinline__ void ldsm_x4(uint32_t* r, uint32_t addr) {
    asm volatile("ldmatrix.sync.aligned.m8n8.x4.shared.b16 {%0,%1,%2,%3}, [%4];"
                 : "=r"(r[0]), "=r"(r[1]), "=r"(r[2]), "=r"(r[3]) : "r"(addr));
}
__device__ __forceinline__ void ldsm_x2(uint32_t* r, uint32_t addr) {
    asm volatile("ldmatrix.sync.aligned.m8n8.x2.shared.b16 {%0,%1}, [%2];"
                 : "=r"(r[0]), "=r"(r[1]) : "r"(addr));
}
__device__ __forceinline__ void ldsm_x2_t(uint32_t* r, uint32_t addr) {
    asm volatile("ldmatrix.sync.aligned.m8n8.x2.trans.shared.b16 {%0,%1}, [%2];"
                 : "=r"(r[0]), "=r"(r[1]) : "r"(addr));
}
__device__ __forceinline__ void mma_f16(float* c, const uint32_t* a, const uint32_t* b) {
    asm volatile(
        "mma.sync.aligned.m16n8k16.row.col.f32.f16.f16.f32 "
        "{%0,%1,%2,%3}, {%4,%5,%6,%7}, {%8,%9}, {%0,%1,%2,%3};"
        : "+f"(c[0]), "+f"(c[1]), "+f"(c[2]), "+f"(c[3])
        : "r"(a[0]), "r"(a[1]), "r"(a[2]), "r"(a[3]), "r"(b[0]), "r"(b[1]));
}
__device__ __forceinline__ void cp_async16(uint32_t saddr, const void* gptr) {
    asm volatile("cp.async.ca.shared.global [%0], [%1], 16;"
                 :: "r"(saddr), "l"(gptr));
}
#define CP_COMMIT() asm volatile("cp.async.commit_group;" ::: "memory")
#define CP_WAIT1()  asm volatile("cp.async.wait_group 1;" ::: "memory")
#define CP_WAIT0()  asm volatile("cp.async.wait_group 0;" ::: "memory")

// fp32 -> (hi, lo) fp16 split, packed as half2 words
__device__ __forceinline__ void split2h(float x, float y, uint32_t& hi, uint32_t& lo) {
    __half hx = __float2half_rn(x);
    __half hy = __float2half_rn(y);
    float rx = x - __half2float(hx);
    float ry = y - __half2float(hy);
    __half lx = __float2half_rn(rx);
    __half ly = __float2half_rn(ry);
    hi = ((uint32_t)__half_as_ushort(hy) << 16) | (uint32_t)__half_as_ushort(hx);
    lo = ((uint32_t)__half_as_ushort(ly) << 16) | (uint32_t)__half_as_ushort(lx);
}
__device__ __forceinline__ uint32_t packh2(float x, float y) {
    __half2 t = __floats2half2_rn(x, y);
    return *(uint32_t*)&t;
}

// ===========================================================================
// prep kernels (merged: grid.y selects tensor)
// ===========================================================================
__global__ __launch_bounds__(256) void split_in_all_kernel(
    const float* __restrict__ s0, const float* __restrict__ s1,
    const float* __restrict__ s2)
{
    const int idx = blockIdx.y;
    const float* src = (idx == 0) ? s0 : (idx == 1) ? s1 : s2;
    int i = blockIdx.x * 256 + threadIdx.x;
    float4 v = ((const float4*)src)[i];
    uint32_t h0, l0, h1, l1;
    split2h(v.x, v.y, h0, l0);
    split2h(v.z, v.w, h1, l1);
    ((uint2*)g_InHi[idx])[i] = make_uint2(h0, h1);
    ((uint2*)g_InLo[idx])[i] = make_uint2(l0, l1);
}
__global__ __launch_bounds__(256) void cvt_w_all_kernel(
    const float* __restrict__ s0, const float* __restrict__ s1,
    const float* __restrict__ s2, const float* __restrict__ s3)
{
    const int idx = blockIdx.y;
    const float* src = (idx == 0) ? s0 : (idx == 1) ? s1 : (idx == 2) ? s2 : s3;
    int i = blockIdx.x * 256 + threadIdx.x;
    float4 v = ((const float4*)src)[i];
    ((uint2*)g_WHi[idx])[i] = make_uint2(packh2(v.x, v.y), packh2(v.z, v.w));
}

// ===========================================================================
// GEMM (NT), fp16 2-term on A, 1-term on B. BK=16, 3-stage cp.async, 1 sync.
// OUTP=false: fused QKV, grid (24, 64); sel = bx>>3; writes fp16 hi [b,h,s,d].
// OUTP=true:  Ctx @ Wo^T, grid (8, 64), fp32 out.
// ===========================================================================
#define RS2 24
#define T2_BYTES (128 * RS2 * 2)          // 6144
#define STAGE2_B (3 * T2_BYTES)           // 18432 : [Ahi, Alo, Bhi]
#define GS_SMEM (3 * STAGE2_B)            // 55296
#define NST2 (PE / 16)                    // 64

template <bool OUTP>
__global__ __launch_bounds__(256, 2) void gemm_mma_kernel(float* __restrict__ Cparam)
{
    extern __shared__ __align__(16) char smem[];
    const uint32_t sbase = smem_u32(smem);

    const int sel = OUTP ? 3 : (blockIdx.x >> 3);
    const int bn  = OUTP ? blockIdx.x : (blockIdx.x & 7);
    const int bm  = blockIdx.y;

    const __half* Ahi = OUTP ? g_CtxHi : g_InHi[sel];
    const __half* Alo = OUTP ? g_CtxLo : g_InLo[sel];
    const __half* Bhi = g_WHi[sel];

    const int tid  = threadIdx.x;
    const int lane = tid & 31;
    const int warp = tid >> 5;
    const int wm = warp >> 2;
    const int wn = warp & 3;

    float acc[4][4][4];
#pragma unroll
    for (int i = 0; i < 4; i++)
#pragma unroll
        for (int j = 0; j < 4; j++)
#pragma unroll
            for (int q = 0; q < 4; q++) acc[i][j][q] = 0.0f;

    const int crow = tid >> 1;
    const int chalf = tid & 1;
    const __half* gAh = Ahi + (size_t)(bm * 128 + crow) * PE + chalf * 8;
    const __half* gAl = Alo + (size_t)(bm * 128 + crow) * PE + chalf * 8;
    const __half* gBh = Bhi + (size_t)(bn * 128 + crow) * PE + chalf * 8;
    const uint32_t sOff = (uint32_t)(crow * RS2 * 2 + chalf * 16);

    const uint32_t a_off = ((wm * 64 + (lane & 15)) * RS2 + (lane >> 4) * 8) * 2;
    const uint32_t b_off = ((wn * 32 + (lane & 7)) * RS2 + ((lane >> 3) & 1) * 8) * 2;

#define G_ISSUE(st_) do {                                                      \
        const int g_ = (st_) * 16;                                             \
        uint32_t d_ = sbase + ((st_) % 3) * STAGE2_B + sOff;                   \
        cp_async16(d_ + 0 * T2_BYTES, gAh + g_);                               \
        cp_async16(d_ + 1 * T2_BYTES, gAl + g_);                               \
        cp_async16(d_ + 2 * T2_BYTES, gBh + g_);                               \
        CP_COMMIT();                                                           \
    } while (0)

    G_ISSUE(0);
    G_ISSUE(1);

#pragma unroll 1
    for (int s = 0; s < NST2; s++) {
        if (s + 1 < NST2) { CP_WAIT1(); } else { CP_WAIT0(); }
        __syncthreads();
        if (s + 2 < NST2) G_ISSUE(s + 2);

        const uint32_t bufb = sbase + (s % 3) * STAGE2_B;
        uint32_t bh[4][2];
#pragma unroll
        for (int ni = 0; ni < 4; ni++)
            ldsm_x2(bh[ni], bufb + 2 * T2_BYTES + b_off + (ni * 8 * RS2) * 2);
#pragma unroll
        for (int mi = 0; mi < 4; mi++) {
            uint32_t ah[4], al[4];
            uint32_t aa = bufb + a_off + (mi * 16 * RS2) * 2;
            ldsm_x4(ah, aa);
            ldsm_x4(al, aa + T2_BYTES);
#pragma unroll
            for (int ni = 0; ni < 4; ni++) {
                mma_f16(acc[mi][ni], ah, bh[ni]);
                mma_f16(acc[mi][ni], al, bh[ni]);
            }
        }
    }

    // ---- epilogue ----
    __half* Dhi = (sel == 0) ? g_QHi : (sel == 1) ? g_KHi : g_VHi;
#pragma unroll
    for (int mi = 0; mi < 4; mi++) {
        const int m0 = bm * 128 + wm * 64 + mi * 16 + (lane >> 2);
#pragma unroll
        for (int half = 0; half < 2; half++) {
            const int m = m0 + half * 8;
            const int bb = m >> 11;
            const int ms = m & (PS - 1);
#pragma unroll
            for (int ni = 0; ni < 4; ni++) {
                const int n = bn * 128 + wn * 32 + ni * 8 + (lane & 3) * 2;
                float v0 = acc[mi][ni][half * 2 + 0];
                float v1 = acc[mi][ni][half * 2 + 1];
                if (!OUTP) {
                    const int hh = n >> 6;
                    const int d = n & 63;
                    size_t idx = ((size_t)(bb * PH + hh) * PS + ms) * PD + d;
                    *(uint32_t*)&Dhi[idx] = packh2(v0, v1);
                } else {
                    *(float2*)&Cparam[(size_t)m * PE + n] = make_float2(v0, v1);
                }
            }
        }
    }
}

// ===========================================================================
// Flash attention: 128 Q rows/CTA, 256 threads, 3-stage cp.async KV pipeline,
// all 1-term fp16:  S = Qhi·Khi ; O += cvt16(P)·Vhi.  2 CTAs/SM.
// ===========================================================================
#define ATT_RS 72
#define AQT_B (128 * ATT_RS * 2)        // 18432 (Q hi plane)
#define KV_TILE (64 * ATT_RS * 2)       // 9216
#define S_QHI 0
#define S_KV AQT_B                      // 18432
#define KV_STAGE (2 * KV_TILE)          // 18432 : [Khi, Vhi]
#define S_BIAS (S_KV + 3 * KV_STAGE)    // 73728
#define ATT_SMEM (S_BIAS + PS * 4)      // 81920
#define NKT (PS / 64)                   // 32

__global__ __launch_bounds__(256, 2) void attn_mma_kernel(
    const unsigned char* __restrict__ mask,
    const float* __restrict__ gamma)
{
    extern __shared__ __align__(16) char sm[];
    const uint32_t sb = smem_u32(sm);

    const int tid  = threadIdx.x;
    const int lane = tid & 31;
    const int warp = tid >> 5;
    const int qt = blockIdx.x;
    const int h  = blockIdx.y;
    const int b  = blockIdx.z;

    const size_t headBase = (size_t)(b * PH + h) * PS * PD;

    // K/V cp.async mapping
    const int kvrow = tid >> 2;
    const int kvc = (tid & 3) * 16;
    const size_t kvg = headBase + (size_t)kvrow * PD;
    const uint32_t kvs = (uint32_t)(kvrow * ATT_RS * 2 + kvc);
    const __half* KH = g_KHi + kvg;
    const __half* VH = g_VHi + kvg;

#define KV_ISSUE(kt_)  do {                                                    \
        const size_t go = (size_t)(kt_) * 64 * PD;                             \
        uint32_t d = sb + S_KV + ((kt_) % 3) * KV_STAGE + kvs;                 \
        cp_async16(d + 0 * KV_TILE,      KH + go + (kvc >> 1));                \
        cp_async16(d + 0 * KV_TILE + 64, KH + go + (kvc >> 1) + 32);           \
        cp_async16(d + 1 * KV_TILE,      VH + go + (kvc >> 1));                \
        cp_async16(d + 1 * KV_TILE + 64, VH + go + (kvc >> 1) + 32);           \
        CP_COMMIT();                                                           \
    } while (0)

    KV_ISSUE(0);
    KV_ISSUE(1);

    // mask -> f32 bias row
    {
        const unsigned char* mrow = mask + (size_t)b * PS;
        float* biasp = (float*)(sm + S_BIAS);
#pragma unroll
        for (int i = 0; i < PS / 256; i++) {
            int kk = tid + i * 256;
            biasp[kk] = mrow[kk] ? -3.0e38f : 0.0f;
        }
    }

    // Q tile copy (hi plane only)
    {
        const int crow = tid >> 1;
        const int ccol = (tid & 1) * 32;
        const __half* qh = g_QHi + headBase + (size_t)(qt * 128 + crow) * PD + ccol;
        const uint32_t so = (uint32_t)(crow * ATT_RS + ccol) * 2;
#pragma unroll
        for (int q = 0; q < 4; q++)
            *(uint4*)(sm + S_QHI + so + q * 16) = *(const uint4*)(qh + q * 8);
    }

    const uint32_t qa = sb + S_QHI + ((warp * 16 + (lane & 15)) * ATT_RS + (lane >> 4) * 8) * 2;
    const uint32_t kb_off = ((lane & 7) * ATT_RS + ((lane >> 3) & 1) * 8) * 2;
    const uint32_t vb_off = ((lane & 15) * ATT_RS) * 2;

    float o[8][4];
#pragma unroll
    for (int nj = 0; nj < 8; nj++)
#pragma unroll
        for (int q = 0; q < 4; q++) o[nj][q] = 0.0f;
    float m0 = -3.0e38f, m1 = -3.0e38f, l0 = 0.0f, l1 = 0.0f;

#pragma unroll 1
    for (int kt = 0; kt < NKT; kt++) {
        if (kt + 1 < NKT) { CP_WAIT1(); } else { CP_WAIT0(); }
        __syncthreads();
        if (kt + 2 < NKT) KV_ISSUE(kt + 2);

        const uint32_t stage = sb + S_KV + (kt % 3) * KV_STAGE;
        const uint32_t kb = stage + kb_off;
        const uint32_t vb = stage + KV_TILE + vb_off;

        // ---- S = Q K^T (1-term) ----
        float sa[8][4];
#pragma unroll
        for (int ni = 0; ni < 8; ni++)
#pragma unroll
            for (int q = 0; q < 4; q++) sa[ni][q] = 0.0f;

#pragma unroll
        for (int ks = 0; ks < 4; ks++) {
            uint32_t qh[4];
            ldsm_x4(qh, qa + ks * 32);
#pragma unroll
            for (int ni = 0; ni < 8; ni++) {
                uint32_t kh[2];
                ldsm_x2(kh, kb + ni * (8 * ATT_RS * 2) + ks * 32);
                mma_f16(sa[ni], qh, kh);
            }
        }

        // ---- scale + bias + online softmax ----
        float mx0 = -3.0e38f, mx1 = -3.0e38f;
#pragma unroll
        for (int ni = 0; ni < 8; ni++) {
            float2 bias = *(const float2*)(sm + S_BIAS + (kt * 64 + ni * 8 + (lane & 3) * 2) * 4);
            sa[ni][0] = sa[ni][0] * 0.125f + bias.x;
            sa[ni][1] = sa[ni][1] * 0.125f + bias.y;
            sa[ni][2] = sa[ni][2] * 0.125f + bias.x;
            sa[ni][3] = sa[ni][3] * 0.125f + bias.y;
            mx0 = fmaxf(mx0, fmaxf(sa[ni][0], sa[ni][1]));
            mx1 = fmaxf(mx1, fmaxf(sa[ni][2], sa[ni][3]));
        }
        mx0 = fmaxf(mx0, __shfl_xor_sync(0xffffffffu, mx0, 1));
        mx0 = fmaxf(mx0, __shfl_xor_sync(0xffffffffu, mx0, 2));
        mx1 = fmaxf(mx1, __shfl_xor_sync(0xffffffffu, mx1, 1));
        mx1 = fmaxf(mx1, __shfl_xor_sync(0xffffffffu, mx1, 2));

        float mn0 = fmaxf(m0, mx0);
        float mn1 = fmaxf(m1, mx1);
        float csc0 = __expf(m0 - mn0);
        float csc1 = __expf(m1 - mn1);
        m0 = mn0; m1 = mn1;

        float ls0 = 0.0f, ls1 = 0.0f;
#pragma unroll
        for (int ni = 0; ni < 8; ni++) {
            sa[ni][0] = __expf(sa[ni][0] - mn0);
            sa[ni][1] = __expf(sa[ni][1] - mn0);
            sa[ni][2] = __expf(sa[ni][2] - mn1);
            sa[ni][3] = __expf(sa[ni][3] - mn1);
            ls0 += sa[ni][0] + sa[ni][1];
            ls1 += sa[ni][2] + sa[ni][3];
        }
        ls0 += __shfl_xor_sync(0xffffffffu, ls0, 1);
        ls0 += __shfl_xor_sync(0xffffffffu, ls0, 2);
        ls1 += __shfl_xor_sync(0xffffffffu, ls1, 1);
        ls1 += __shfl_xor_sync(0xffffffffu, ls1, 2);
        l0 = l0 * csc0 + ls0;
        l1 = l1 * csc1 + ls1;

#pragma unroll
        for (int nj = 0; nj < 8; nj++) {
            o[nj][0] *= csc0; o[nj][1] *= csc0;
            o[nj][2] *= csc1; o[nj][3] *= csc1;
        }

        // ---- O += P V (both 1-term) ----
#pragma unroll
        for (int ks = 0; ks < 4; ks++) {
            const float* t0 = sa[2 * ks];
            const float* t1 = sa[2 * ks + 1];
            uint32_t ah[4];
            ah[0] = packh2(t0[0], t0[1]);
            ah[1] = packh2(t0[2], t0[3]);
            ah[2] = packh2(t1[0], t1[1]);
            ah[3] = packh2(t1[2], t1[3]);
#pragma unroll
            for (int nj = 0; nj < 8; nj++) {
                uint32_t vh[2];
                ldsm_x2_t(vh, vb + ks * (16 * ATT_RS * 2) + nj * 16);
                mma_f16(o[nj], ah, vh);
            }
        }
    }

    // ---- epilogue: gamma / l, 2-term split, write Ctx hi/lo ----
    const float gsc = gamma[h];
    const float inv0 = gsc / l0;
    const float inv1 = gsc / l1;
    const int r0 = qt * 128 + warp * 16 + (lane >> 2);
    const size_t base0 = ((size_t)b * PS + r0) * PE + h * PD;
    const size_t base1 = base0 + (size_t)8 * PE;
#pragma unroll
    for (int nj = 0; nj < 8; nj++) {
        const int col = nj * 8 + (lane & 3) * 2;
        uint32_t hw, lw;
        split2h(o[nj][0] * inv0, o[nj][1] * inv0, hw, lw);
        *(uint32_t*)&g_CtxHi[base0 + col] = hw;
        *(uint32_t*)&g_CtxLo[base0 + col] = lw;
        split2h(o[nj][2] * inv1, o[nj][3] * inv1, hw, lw);
        *(uint32_t*)&g_CtxHi[base1 + col] = hw;
        *(uint32_t*)&g_CtxLo[base1 + col] = lw;
    }
}

// ---------------------------------------------------------------------------
extern "C" void kernel_launch(void* const* d_in, const int* in_sizes, int n_in,
                              void* d_out, int out_size)
{
    const float* query = (const float*)d_in[0];
    const float* key   = (const float*)d_in[1];
    const float* value = (const float*)d_in[2];
    const unsigned char* mask = (const unsigned char*)d_in[3];
    const float* Wq = (const float*)d_in[4];
    const float* Wk = (const float*)d_in[5];
    const float* Wv = (const float*)d_in[6];
    const float* Wo = (const float*)d_in[7];
    const float* gamma = (const float*)d_in[8];

    cudaFuncSetAttribute(gemm_mma_kernel<false>,
                         cudaFuncAttributeMaxDynamicSharedMemorySize, GS_SMEM);
    cudaFuncSetAttribute(gemm_mma_kernel<true>,
                         cudaFuncAttributeMaxDynamicSharedMemorySize, GS_SMEM);
    cudaFuncSetAttribute(attn_mma_kernel,
                         cudaFuncAttributeMaxDynamicSharedMemorySize, ATT_SMEM);

    // prep: split inputs (hi+lo), convert weights (hi only) — 2 launches
    split_in_all_kernel<<<dim3(NEL / 4 / 256, 3), 256>>>(query, key, value);
    cvt_w_all_kernel<<<dim3(PE * PE / 4 / 256, 4), 256>>>(Wq, Wk, Wv, Wo);

    // fused Q/K/V projections: grid.x = 3 weights x 8 n-tiles
    gemm_mma_kernel<false><<<dim3(24, PM / 128), 256, GS_SMEM>>>(nullptr);

    attn_mma_kernel<<<dim3(PS / 128, PH, PB), 256, ATT_SMEM>>>(mask, gamma);

    gemm_mma_kernel<true><<<dim3(8, PM / 128), 256, GS_SMEM>>>((float*)d_out);
}

// round 12
// speedup vs baseline: 6.2209x; 1.3827x over previous
#include <cuda_runtime.h>
#include <cuda_fp16.h>
#include <cstdint>

// Problem constants
#define PB 4
#define PS 2048
#define PE 1024
#define PH 16
#define PD 64
#define PM (PB * PS)   // 8192
#define NEL (PM * PE)  // 8388608

// ---------------------------------------------------------------------------
// Persistent fp16 scratch (device globals: allocation-free) — all 1-term
// ---------------------------------------------------------------------------
__device__ __half g_In[3][NEL];          // fp16 query/key/value
__device__ __half g_W[4][PE * PE];       // fp16 Wq,Wk,Wv,Wo
__device__ __half g_Q[NEL];              // [b,h,s,d]
__device__ __half g_K[NEL];
__device__ __half g_V[NEL];
__device__ __half g_Ctx[NEL];            // [b,s,e]

// ===========================================================================
// helpers
// ===========================================================================
__device__ __forceinline__ uint32_t smem_u32(const void* p) {
    uint32_t a;
    asm("{ .reg .u64 t; cvta.to.shared.u64 t, %1; cvt.u32.u64 %0, t; }"
        : "=r"(a) : "l"(p));
    return a;
}
__device__ __forceinline__ void ldsm_x4(uint32_t* r, uint32_t addr) {
    asm volatile("ldmatrix.sync.aligned.m8n8.x4.shared.b16 {%0,%1,%2,%3}, [%4];"
                 : "=r"(r[0]), "=r"(r[1]), "=r"(r[2]), "=r"(r[3]) : "r"(addr));
}
__device__ __forceinline__ void ldsm_x2(uint32_t* r, uint32_t addr) {
    asm volatile("ldmatrix.sync.aligned.m8n8.x2.shared.b16 {%0,%1}, [%2];"
                 : "=r"(r[0]), "=r"(r[1]) : "r"(addr));
}
__device__ __forceinline__ void ldsm_x2_t(uint32_t* r, uint32_t addr) {
    asm volatile("ldmatrix.sync.aligned.m8n8.x2.trans.shared.b16 {%0,%1}, [%2];"
                 : "=r"(r[0]), "=r"(r[1]) : "r"(addr));
}
__device__ __forceinline__ void mma_f16(float* c, const uint32_t* a, const uint32_t* b) {
    asm volatile(
        "mma.sync.aligned.m16n8k16.row.col.f32.f16.f16.f32 "
        "{%0,%1,%2,%3}, {%4,%5,%6,%7}, {%8,%9}, {%0,%1,%2,%3};"
        : "+f"(c[0]), "+f"(c[1]), "+f"(c[2]), "+f"(c[3])
        : "r"(a[0]), "r"(a[1]), "r"(a[2]), "r"(a[3]), "r"(b[0]), "r"(b[1]));
}
__device__ __forceinline__ void cp_async16(uint32_t saddr, const void* gptr) {
    asm volatile("cp.async.ca.shared.global [%0], [%1], 16;"
                 :: "r"(saddr), "l"(gptr));
}
#define CP_COMMIT() asm volatile("cp.async.commit_group;" ::: "memory")
#define CP_WAIT1()  asm volatile("cp.async.wait_group 1;" ::: "memory")
#define CP_WAIT0()  asm volatile("cp.async.wait_group 0;" ::: "memory")

__device__ __forceinline__ uint32_t packh2(float x, float y) {
    __half2 t = __floats2half2_rn(x, y);
    return *(uint32_t*)&t;
}

// ===========================================================================
// prep kernels: fp32 -> fp16 (grid.y selects tensor)
// ===========================================================================
__global__ __launch_bounds__(256) void cvt_in_all_kernel(
    const float* __restrict__ s0, const float* __restrict__ s1,
    const float* __restrict__ s2)
{
    const int idx = blockIdx.y;
    const float* src = (idx == 0) ? s0 : (idx == 1) ? s1 : s2;
    int i = blockIdx.x * 256 + threadIdx.x;
    float4 v = ((const float4*)src)[i];
    ((uint2*)g_In[idx])[i] = make_uint2(packh2(v.x, v.y), packh2(v.z, v.w));
}
__global__ __launch_bounds__(256) void cvt_w_all_kernel(
    const float* __restrict__ s0, const float* __restrict__ s1,
    const float* __restrict__ s2, const float* __restrict__ s3)
{
    const int idx = blockIdx.y;
    const float* src = (idx == 0) ? s0 : (idx == 1) ? s1 : (idx == 2) ? s2 : s3;
    int i = blockIdx.x * 256 + threadIdx.x;
    float4 v = ((const float4*)src)[i];
    ((uint2*)g_W[idx])[i] = make_uint2(packh2(v.x, v.y), packh2(v.z, v.w));
}

// ===========================================================================
// GEMM (NT), pure fp16. BK=16, 3-stage cp.async, 1 sync/stage.
// OUTP=false: fused QKV, grid (24, 64); sel = bx>>3; writes fp16 [b,h,s,d].
// OUTP=true:  Ctx @ Wo^T, grid (8, 64), fp32 out.
// Stage tiles: [A, B].
// ===========================================================================
#define RS2 24
#define T2_BYTES (128 * RS2 * 2)          // 6144
#define STAGE2_B (2 * T2_BYTES)           // 12288 : [A, B]
#define GS_SMEM (3 * STAGE2_B)            // 36864
#define NST2 (PE / 16)                    // 64

template <bool OUTP>
__global__ __launch_bounds__(256, 2) void gemm_mma_kernel(float* __restrict__ Cparam)
{
    extern __shared__ __align__(16) char smem[];
    const uint32_t sbase = smem_u32(smem);

    const int sel = OUTP ? 3 : (blockIdx.x >> 3);
    const int bn  = OUTP ? blockIdx.x : (blockIdx.x & 7);
    const int bm  = blockIdx.y;

    const __half* A = OUTP ? g_Ctx : g_In[sel];
    const __half* B = g_W[sel];

    const int tid  = threadIdx.x;
    const int lane = tid & 31;
    const int warp = tid >> 5;
    const int wm = warp >> 2;
    const int wn = warp & 3;

    float acc[4][4][4];
#pragma unroll
    for (int i = 0; i < 4; i++)
#pragma unroll
        for (int j = 0; j < 4; j++)
#pragma unroll
            for (int q = 0; q < 4; q++) acc[i][j][q] = 0.0f;

    const int crow = tid >> 1;
    const int chalf = tid & 1;
    const __half* gA = A + (size_t)(bm * 128 + crow) * PE + chalf * 8;
    const __half* gB = B + (size_t)(bn * 128 + crow) * PE + chalf * 8;
    const uint32_t sOff = (uint32_t)(crow * RS2 * 2 + chalf * 16);

    const uint32_t a_off = ((wm * 64 + (lane & 15)) * RS2 + (lane >> 4) * 8) * 2;
    const uint32_t b_off = ((wn * 32 + (lane & 7)) * RS2 + ((lane >> 3) & 1) * 8) * 2;

#define G_ISSUE(st_) do {                                                      \
        const int g_ = (st_) * 16;                                             \
        uint32_t d_ = sbase + ((st_) % 3) * STAGE2_B + sOff;                   \
        cp_async16(d_ + 0 * T2_BYTES, gA + g_);                                \
        cp_async16(d_ + 1 * T2_BYTES, gB + g_);                                \
        CP_COMMIT();                                                           \
    } while (0)

    G_ISSUE(0);
    G_ISSUE(1);

#pragma unroll 1
    for (int s = 0; s < NST2; s++) {
        if (s + 1 < NST2) { CP_WAIT1(); } else { CP_WAIT0(); }
        __syncthreads();
        if (s + 2 < NST2) G_ISSUE(s + 2);

        const uint32_t bufb = sbase + (s % 3) * STAGE2_B;
        uint32_t bh[4][2];
#pragma unroll
        for (int ni = 0; ni < 4; ni++)
            ldsm_x2(bh[ni], bufb + T2_BYTES + b_off + (ni * 8 * RS2) * 2);
#pragma unroll
        for (int mi = 0; mi < 4; mi++) {
            uint32_t ah[4];
            ldsm_x4(ah, bufb + a_off + (mi * 16 * RS2) * 2);
#pragma unroll
            for (int ni = 0; ni < 4; ni++)
                mma_f16(acc[mi][ni], ah, bh[ni]);
        }
    }

    // ---- epilogue ----
    __half* D = (sel == 0) ? g_Q : (sel == 1) ? g_K : g_V;
#pragma unroll
    for (int mi = 0; mi < 4; mi++) {
        const int m0 = bm * 128 + wm * 64 + mi * 16 + (lane >> 2);
#pragma unroll
        for (int half = 0; half < 2; half++) {
            const int m = m0 + half * 8;
            const int bb = m >> 11;
            const int ms = m & (PS - 1);
#pragma unroll
            for (int ni = 0; ni < 4; ni++) {
                const int n = bn * 128 + wn * 32 + ni * 8 + (lane & 3) * 2;
                float v0 = acc[mi][ni][half * 2 + 0];
                float v1 = acc[mi][ni][half * 2 + 1];
                if (!OUTP) {
                    const int hh = n >> 6;
                    const int d = n & 63;
                    size_t idx = ((size_t)(bb * PH + hh) * PS + ms) * PD + d;
                    *(uint32_t*)&D[idx] = packh2(v0, v1);
                } else {
                    *(float2*)&Cparam[(size_t)m * PE + n] = make_float2(v0, v1);
                }
            }
        }
    }
}

// ===========================================================================
// Flash attention: 128 Q rows/CTA, 256 threads, 3-stage cp.async KV pipeline,
// pure fp16:  S = Q·K^T ; O += cvt16(P)·V.  2 CTAs/SM.
// ===========================================================================
#define ATT_RS 72
#define AQT_B (128 * ATT_RS * 2)        // 18432 (Q tile)
#define KV_TILE (64 * ATT_RS * 2)       // 9216
#define S_Q 0
#define S_KV AQT_B                      // 18432
#define KV_STAGE (2 * KV_TILE)          // 18432 : [K, V]
#define S_BIAS (S_KV + 3 * KV_STAGE)    // 73728
#define ATT_SMEM (S_BIAS + PS * 4)      // 81920
#define NKT (PS / 64)                   // 32

__global__ __launch_bounds__(256, 2) void attn_mma_kernel(
    const unsigned char* __restrict__ mask,
    const float* __restrict__ gamma)
{
    extern __shared__ __align__(16) char sm[];
    const uint32_t sb = smem_u32(sm);

    const int tid  = threadIdx.x;
    const int lane = tid & 31;
    const int warp = tid >> 5;
    const int qt = blockIdx.x;
    const int h  = blockIdx.y;
    const int b  = blockIdx.z;

    const size_t headBase = (size_t)(b * PH + h) * PS * PD;

    // K/V cp.async mapping
    const int kvrow = tid >> 2;
    const int kvc = (tid & 3) * 16;
    const size_t kvg = headBase + (size_t)kvrow * PD;
    const uint32_t kvs = (uint32_t)(kvrow * ATT_RS * 2 + kvc);
    const __half* KH = g_K + kvg;
    const __half* VH = g_V + kvg;

#define KV_ISSUE(kt_)  do {                                                    \
        const size_t go = (size_t)(kt_) * 64 * PD;                             \
        uint32_t d = sb + S_KV + ((kt_) % 3) * KV_STAGE + kvs;                 \
        cp_async16(d + 0 * KV_TILE,      KH + go + (kvc >> 1));                \
        cp_async16(d + 0 * KV_TILE + 64, KH + go + (kvc >> 1) + 32);           \
        cp_async16(d + 1 * KV_TILE,      VH + go + (kvc >> 1));                \
        cp_async16(d + 1 * KV_TILE + 64, VH + go + (kvc >> 1) + 32);           \
        CP_COMMIT();                                                           \
    } while (0)

    KV_ISSUE(0);
    KV_ISSUE(1);

    // mask -> f32 bias row
    {
        const unsigned char* mrow = mask + (size_t)b * PS;
        float* biasp = (float*)(sm + S_BIAS);
#pragma unroll
        for (int i = 0; i < PS / 256; i++) {
            int kk = tid + i * 256;
            biasp[kk] = mrow[kk] ? -3.0e38f : 0.0f;
        }
    }

    // Q tile copy
    {
        const int crow = tid >> 1;
        const int ccol = (tid & 1) * 32;
        const __half* qh = g_Q + headBase + (size_t)(qt * 128 + crow) * PD + ccol;
        const uint32_t so = (uint32_t)(crow * ATT_RS + ccol) * 2;
#pragma unroll
        for (int q = 0; q < 4; q++)
            *(uint4*)(sm + S_Q + so + q * 16) = *(const uint4*)(qh + q * 8);
    }

    const uint32_t qa = sb + S_Q + ((warp * 16 + (lane & 15)) * ATT_RS + (lane >> 4) * 8) * 2;
    const uint32_t kb_off = ((lane & 7) * ATT_RS + ((lane >> 3) & 1) * 8) * 2;
    const uint32_t vb_off = ((lane & 15) * ATT_RS) * 2;

    float o[8][4];
#pragma unroll
    for (int nj = 0; nj < 8; nj++)
#pragma unroll
        for (int q = 0; q < 4; q++) o[nj][q] = 0.0f;
    float m0 = -3.0e38f, m1 = -3.0e38f, l0 = 0.0f, l1 = 0.0f;

#pragma unroll 1
    for (int kt = 0; kt < NKT; kt++) {
        if (kt + 1 < NKT) { CP_WAIT1(); } else { CP_WAIT0(); }
        __syncthreads();
        if (kt + 2 < NKT) KV_ISSUE(kt + 2);

        const uint32_t stage = sb + S_KV + (kt % 3) * KV_STAGE;
        const uint32_t kb = stage + kb_off;
        const uint32_t vb = stage + KV_TILE + vb_off;

        // ---- S = Q K^T ----
        float sa[8][4];
#pragma unroll
        for (int ni = 0; ni < 8; ni++)
#pragma unroll
            for (int q = 0; q < 4; q++) sa[ni][q] = 0.0f;

#pragma unroll
        for (int ks = 0; ks < 4; ks++) {
            uint32_t qh[4];
            ldsm_x4(qh, qa + ks * 32);
#pragma unroll
            for (int ni = 0; ni < 8; ni++) {
                uint32_t kh[2];
                ldsm_x2(kh, kb + ni * (8 * ATT_RS * 2) + ks * 32);
                mma_f16(sa[ni], qh, kh);
            }
        }

        // ---- scale + bias + online softmax ----
        float mx0 = -3.0e38f, mx1 = -3.0e38f;
#pragma unroll
        for (int ni = 0; ni < 8; ni++) {
            float2 bias = *(const float2*)(sm + S_BIAS + (kt * 64 + ni * 8 + (lane & 3) * 2) * 4);
            sa[ni][0] = sa[ni][0] * 0.125f + bias.x;
            sa[ni][1] = sa[ni][1] * 0.125f + bias.y;
            sa[ni][2] = sa[ni][2] * 0.125f + bias.x;
            sa[ni][3] = sa[ni][3] * 0.125f + bias.y;
            mx0 = fmaxf(mx0, fmaxf(sa[ni][0], sa[ni][1]));
            mx1 = fmaxf(mx1, fmaxf(sa[ni][2], sa[ni][3]));
        }
        mx0 = fmaxf(mx0, __shfl_xor_sync(0xffffffffu, mx0, 1));
        mx0 = fmaxf(mx0, __shfl_xor_sync(0xffffffffu, mx0, 2));
        mx1 = fmaxf(mx1, __shfl_xor_sync(0xffffffffu, mx1, 1));
        mx1 = fmaxf(mx1, __shfl_xor_sync(0xffffffffu, mx1, 2));

        float mn0 = fmaxf(m0, mx0);
        float mn1 = fmaxf(m1, mx1);
        float csc0 = __expf(m0 - mn0);
        float csc1 = __expf(m1 - mn1);
        m0 = mn0; m1 = mn1;

        float ls0 = 0.0f, ls1 = 0.0f;
#pragma unroll
        for (int ni = 0; ni < 8; ni++) {
            sa[ni][0] = __expf(sa[ni][0] - mn0);
            sa[ni][1] = __expf(sa[ni][1] - mn0);
            sa[ni][2] = __expf(sa[ni][2] - mn1);
            sa[ni][3] = __expf(sa[ni][3] - mn1);
            ls0 += sa[ni][0] + sa[ni][1];
            ls1 += sa[ni][2] + sa[ni][3];
        }
        ls0 += __shfl_xor_sync(0xffffffffu, ls0, 1);
        ls0 += __shfl_xor_sync(0xffffffffu, ls0, 2);
        ls1 += __shfl_xor_sync(0xffffffffu, ls1, 1);
        ls1 += __shfl_xor_sync(0xffffffffu, ls1, 2);
        l0 = l0 * csc0 + ls0;
        l1 = l1 * csc1 + ls1;

#pragma unroll
        for (int nj = 0; nj < 8; nj++) {
            o[nj][0] *= csc0; o[nj][1] *= csc0;
            o[nj][2] *= csc1; o[nj][3] *= csc1;
        }

        // ---- O += P V ----
#pragma unroll
        for (int ks = 0; ks < 4; ks++) {
            const float* t0 = sa[2 * ks];
            const float* t1 = sa[2 * ks + 1];
            uint32_t ah[4];
            ah[0] = packh2(t0[0], t0[1]);
            ah[1] = packh2(t0[2], t0[3]);
            ah[2] = packh2(t1[0], t1[1]);
            ah[3] = packh2(t1[2], t1[3]);
#pragma unroll
            for (int nj = 0; nj < 8; nj++) {
                uint32_t vh[2];
                ldsm_x2_t(vh, vb + ks * (16 * ATT_RS * 2) + nj * 16);
                mma_f16(o[nj], ah, vh);
            }
        }
    }

    // ---- epilogue: gamma / l, write Ctx fp16 ----
    const float gsc = gamma[h];
    const float inv0 = gsc / l0;
    const float inv1 = gsc / l1;
    const int r0 = qt * 128 + warp * 16 + (lane >> 2);
    const size_t base0 = ((size_t)b * PS + r0) * PE + h * PD;
    const size_t base1 = base0 + (size_t)8 * PE;
#pragma unroll
    for (int nj = 0; nj < 8; nj++) {
        const int col = nj * 8 + (lane & 3) * 2;
        *(uint32_t*)&g_Ctx[base0 + col] = packh2(o[nj][0] * inv0, o[nj][1] * inv0);
        *(uint32_t*)&g_Ctx[base1 + col] = packh2(o[nj][2] * inv1, o[nj][3] * inv1);
    }
}

// ---------------------------------------------------------------------------
extern "C" void kernel_launch(void* const* d_in, const int* in_sizes, int n_in,
                              void* d_out, int out_size)
{
    const float* query = (const float*)d_in[0];
    const float* key   = (const float*)d_in[1];
    const float* value = (const float*)d_in[2];
    const unsigned char* mask = (const unsigned char*)d_in[3];
    const float* Wq = (const float*)d_in[4];
    const float* Wk = (const float*)d_in[5];
    const float* Wv = (const float*)d_in[6];
    const float* Wo = (const float*)d_in[7];
    const float* gamma = (const float*)d_in[8];

    cudaFuncSetAttribute(gemm_mma_kernel<false>,
                         cudaFuncAttributeMaxDynamicSharedMemorySize, GS_SMEM);
    cudaFuncSetAttribute(gemm_mma_kernel<true>,
                         cudaFuncAttributeMaxDynamicSharedMemorySize, GS_SMEM);
    cudaFuncSetAttribute(attn_mma_kernel,
                         cudaFuncAttributeMaxDynamicSharedMemorySize, ATT_SMEM);

    // prep: fp32 -> fp16 converts (2 launches)
    cvt_in_all_kernel<<<dim3(NEL / 4 / 256, 3), 256>>>(query, key, value);
    cvt_w_all_kernel<<<dim3(PE * PE / 4 / 256, 4), 256>>>(Wq, Wk, Wv, Wo);

    // fused Q/K/V projections: grid.x = 3 weights x 8 n-tiles
    gemm_mma_kernel<false><<<dim3(24, PM / 128), 256, GS_SMEM>>>(nullptr);

    attn_mma_kernel<<<dim3(PS / 128, PH, PB), 256, ATT_SMEM>>>(mask, gamma);

    gemm_mma_kernel<true><<<dim3(8, PM / 128), 256, GS_SMEM>>>((float*)d_out);
}

// round 13
// speedup vs baseline: 6.4125x; 1.0308x over previous
#include <cuda_runtime.h>
#include <cuda_fp16.h>
#include <cstdint>

// Problem constants
#define PB 4
#define PS 2048
#define PE 1024
#define PH 16
#define PD 64
#define PM (PB * PS)   // 8192
#define NEL (PM * PE)  // 8388608

// ---------------------------------------------------------------------------
// Persistent fp16 scratch (device globals: allocation-free) — all 1-term
// ---------------------------------------------------------------------------
__device__ __half g_In[3][NEL];          // fp16 query/key/value
__device__ __half g_W[4][PE * PE];       // fp16 Wq,Wk,Wv,Wo
__device__ __half g_Q[NEL];              // [b,h,s,d]
__device__ __half g_K[NEL];
__device__ __half g_V[NEL];
__device__ __half g_Ctx[NEL];            // [b,s,e]

// ===========================================================================
// helpers
// ===========================================================================
__device__ __forceinline__ uint32_t smem_u32(const void* p) {
    uint32_t a;
    asm("{ .reg .u64 t; cvta.to.shared.u64 t, %1; cvt.u32.u64 %0, t; }"
        : "=r"(a) : "l"(p));
    return a;
}
__device__ __forceinline__ void ldsm_x4(uint32_t* r, uint32_t addr) {
    asm volatile("ldmatrix.sync.aligned.m8n8.x4.shared.b16 {%0,%1,%2,%3}, [%4];"
                 : "=r"(r[0]), "=r"(r[1]), "=r"(r[2]), "=r"(r[3]) : "r"(addr));
}
__device__ __forceinline__ void ldsm_x4_t(uint32_t* r, uint32_t addr) {
    asm volatile("ldmatrix.sync.aligned.m8n8.x4.trans.shared.b16 {%0,%1,%2,%3}, [%4];"
                 : "=r"(r[0]), "=r"(r[1]), "=r"(r[2]), "=r"(r[3]) : "r"(addr));
}
__device__ __forceinline__ void mma_f16(float* c, const uint32_t* a, const uint32_t* b) {
    asm volatile(
        "mma.sync.aligned.m16n8k16.row.col.f32.f16.f16.f32 "
        "{%0,%1,%2,%3}, {%4,%5,%6,%7}, {%8,%9}, {%0,%1,%2,%3};"
        : "+f"(c[0]), "+f"(c[1]), "+f"(c[2]), "+f"(c[3])
        : "r"(a[0]), "r"(a[1]), "r"(a[2]), "r"(a[3]), "r"(b[0]), "r"(b[1]));
}
__device__ __forceinline__ void cp_async16(uint32_t saddr, const void* gptr) {
    asm volatile("cp.async.ca.shared.global [%0], [%1], 16;"
                 :: "r"(saddr), "l"(gptr));
}
#define CP_COMMIT() asm volatile("cp.async.commit_group;" ::: "memory")
#define CP_WAIT1()  asm volatile("cp.async.wait_group 1;" ::: "memory")
#define CP_WAIT0()  asm volatile("cp.async.wait_group 0;" ::: "memory")

__device__ __forceinline__ uint32_t packh2(float x, float y) {
    __half2 t = __floats2half2_rn(x, y);
    return *(uint32_t*)&t;
}
__device__ __forceinline__ float ex2f(float x) {
    float r;
    asm("ex2.approx.f32 %0, %1;" : "=f"(r) : "f"(x));
    return r;
}
// 0.125 (1/sqrt(64)) * log2(e) — softmax done in log2 domain
#define SC2 0.1803368801111204f

// ===========================================================================
// prep kernels: fp32 -> fp16 (grid.y selects tensor)
// ===========================================================================
__global__ __launch_bounds__(256) void cvt_in_all_kernel(
    const float* __restrict__ s0, const float* __restrict__ s1,
    const float* __restrict__ s2)
{
    const int idx = blockIdx.y;
    const float* src = (idx == 0) ? s0 : (idx == 1) ? s1 : s2;
    int i = blockIdx.x * 256 + threadIdx.x;
    float4 v = ((const float4*)src)[i];
    ((uint2*)g_In[idx])[i] = make_uint2(packh2(v.x, v.y), packh2(v.z, v.w));
}
__global__ __launch_bounds__(256) void cvt_w_all_kernel(
    const float* __restrict__ s0, const float* __restrict__ s1,
    const float* __restrict__ s2, const float* __restrict__ s3)
{
    const int idx = blockIdx.y;
    const float* src = (idx == 0) ? s0 : (idx == 1) ? s1 : (idx == 2) ? s2 : s3;
    int i = blockIdx.x * 256 + threadIdx.x;
    float4 v = ((const float4*)src)[i];
    ((uint2*)g_W[idx])[i] = make_uint2(packh2(v.x, v.y), packh2(v.z, v.w));
}

// ===========================================================================
// GEMM (NT), pure fp16. BK=16, 3-stage cp.async, 1 sync/stage.
// OUTP=false: fused QKV, grid (24, 64); sel = bx>>3; writes fp16 [b,h,s,d].
// OUTP=true:  Ctx @ Wo^T, grid (8, 64), fp32 out.
// ===========================================================================
#define RS2 24
#define T2_BYTES (128 * RS2 * 2)          // 6144
#define STAGE2_B (2 * T2_BYTES)           // 12288 : [A, B]
#define GS_SMEM (3 * STAGE2_B)            // 36864
#define NST2 (PE / 16)                    // 64

template <bool OUTP>
__global__ __launch_bounds__(256, 2) void gemm_mma_kernel(float* __restrict__ Cparam)
{
    extern __shared__ __align__(16) char smem[];
    const uint32_t sbase = smem_u32(smem);

    const int sel = OUTP ? 3 : (blockIdx.x >> 3);
    const int bn  = OUTP ? blockIdx.x : (blockIdx.x & 7);
    const int bm  = blockIdx.y;

    const __half* A = OUTP ? g_Ctx : g_In[sel];
    const __half* B = g_W[sel];

    const int tid  = threadIdx.x;
    const int lane = tid & 31;
    const int warp = tid >> 5;
    const int wm = warp >> 2;
    const int wn = warp & 3;

    float acc[4][4][4];
#pragma unroll
    for (int i = 0; i < 4; i++)
#pragma unroll
        for (int j = 0; j < 4; j++)
#pragma unroll
            for (int q = 0; q < 4; q++) acc[i][j][q] = 0.0f;

    const int crow = tid >> 1;
    const int chalf = tid & 1;
    const __half* gA = A + (size_t)(bm * 128 + crow) * PE + chalf * 8;
    const __half* gB = B + (size_t)(bn * 128 + crow) * PE + chalf * 8;
    const uint32_t sOff = (uint32_t)(crow * RS2 * 2 + chalf * 16);

    const uint32_t a_off = ((wm * 64 + (lane & 15)) * RS2 + (lane >> 4) * 8) * 2;
    // paired-B ldmatrix.x4: rows = wn*32 + (lane&15) (two n8 tiles), k-col by lane>>4
    const uint32_t b2_off = ((wn * 32 + (lane & 15)) * RS2 + (lane >> 4) * 8) * 2;

#define G_ISSUE(st_) do {                                                      \
        const int g_ = (st_) * 16;                                             \
        uint32_t d_ = sbase + ((st_) % 3) * STAGE2_B + sOff;                   \
        cp_async16(d_ + 0 * T2_BYTES, gA + g_);                                \
        cp_async16(d_ + 1 * T2_BYTES, gB + g_);                                \
        CP_COMMIT();                                                           \
    } while (0)

    G_ISSUE(0);
    G_ISSUE(1);

#pragma unroll 1
    for (int s = 0; s < NST2; s++) {
        if (s + 1 < NST2) { CP_WAIT1(); } else { CP_WAIT0(); }
        __syncthreads();
        if (s + 2 < NST2) G_ISSUE(s + 2);

        const uint32_t bufb = sbase + (s % 3) * STAGE2_B;
        uint32_t bh[4][2];
#pragma unroll
        for (int nb = 0; nb < 2; nb++) {
            uint32_t br[4];
            ldsm_x4(br, bufb + T2_BYTES + b2_off + nb * (16 * RS2) * 2);
            bh[2 * nb + 0][0] = br[0]; bh[2 * nb + 0][1] = br[2];
            bh[2 * nb + 1][0] = br[1]; bh[2 * nb + 1][1] = br[3];
        }
#pragma unroll
        for (int mi = 0; mi < 4; mi++) {
            uint32_t ah[4];
            ldsm_x4(ah, bufb + a_off + (mi * 16 * RS2) * 2);
#pragma unroll
            for (int ni = 0; ni < 4; ni++)
                mma_f16(acc[mi][ni], ah, bh[ni]);
        }
    }

    // ---- epilogue ----
    __half* D = (sel == 0) ? g_Q : (sel == 1) ? g_K : g_V;
#pragma unroll
    for (int mi = 0; mi < 4; mi++) {
        const int m0 = bm * 128 + wm * 64 + mi * 16 + (lane >> 2);
#pragma unroll
        for (int half = 0; half < 2; half++) {
            const int m = m0 + half * 8;
            const int bb = m >> 11;
            const int ms = m & (PS - 1);
#pragma unroll
            for (int ni = 0; ni < 4; ni++) {
                const int n = bn * 128 + wn * 32 + ni * 8 + (lane & 3) * 2;
                float v0 = acc[mi][ni][half * 2 + 0];
                float v1 = acc[mi][ni][half * 2 + 1];
                if (!OUTP) {
                    const int hh = n >> 6;
                    const int d = n & 63;
                    size_t idx = ((size_t)(bb * PH + hh) * PS + ms) * PD + d;
                    *(uint32_t*)&D[idx] = packh2(v0, v1);
                } else {
                    *(float2*)&Cparam[(size_t)m * PE + n] = make_float2(v0, v1);
                }
            }
        }
    }
}

// ===========================================================================
// Flash attention: 128 Q rows/CTA, 256 threads, 3-stage cp.async KV pipeline,
// pure fp16, log2-domain softmax, paired ldmatrix.x4. 2 CTAs/SM.
// ===========================================================================
#define ATT_RS 72
#define AQT_B (128 * ATT_RS * 2)        // 18432 (Q tile)
#define KV_TILE (64 * ATT_RS * 2)       // 9216
#define S_Q 0
#define S_KV AQT_B                      // 18432
#define KV_STAGE (2 * KV_TILE)          // 18432 : [K, V]
#define S_BIAS (S_KV + 3 * KV_STAGE)    // 73728
#define ATT_SMEM (S_BIAS + PS * 4)      // 81920
#define NKT (PS / 64)                   // 32

__global__ __launch_bounds__(256, 2) void attn_mma_kernel(
    const unsigned char* __restrict__ mask,
    const float* __restrict__ gamma)
{
    extern __shared__ __align__(16) char sm[];
    const uint32_t sb = smem_u32(sm);

    const int tid  = threadIdx.x;
    const int lane = tid & 31;
    const int warp = tid >> 5;
    const int qt = blockIdx.x;
    const int h  = blockIdx.y;
    const int b  = blockIdx.z;

    const size_t headBase = (size_t)(b * PH + h) * PS * PD;

    // K/V cp.async mapping
    const int kvrow = tid >> 2;
    const int kvc = (tid & 3) * 16;
    const size_t kvg = headBase + (size_t)kvrow * PD;
    const uint32_t kvs = (uint32_t)(kvrow * ATT_RS * 2 + kvc);
    const __half* KH = g_K + kvg;
    const __half* VH = g_V + kvg;

#define KV_ISSUE(kt_)  do {                                                    \
        const size_t go = (size_t)(kt_) * 64 * PD;                             \
        uint32_t d = sb + S_KV + ((kt_) % 3) * KV_STAGE + kvs;                 \
        cp_async16(d + 0 * KV_TILE,      KH + go + (kvc >> 1));                \
        cp_async16(d + 0 * KV_TILE + 64, KH + go + (kvc >> 1) + 32);           \
        cp_async16(d + 1 * KV_TILE,      VH + go + (kvc >> 1));                \
        cp_async16(d + 1 * KV_TILE + 64, VH + go + (kvc >> 1) + 32);           \
        CP_COMMIT();                                                           \
    } while (0)

    KV_ISSUE(0);
    KV_ISSUE(1);

    // mask -> bias row (log2-domain units: 0 or -huge)
    {
        const unsigned char* mrow = mask + (size_t)b * PS;
        float* biasp = (float*)(sm + S_BIAS);
#pragma unroll
        for (int i = 0; i < PS / 256; i++) {
            int kk = tid + i * 256;
            biasp[kk] = mrow[kk] ? -3.0e38f : 0.0f;
        }
    }

    // Q tile copy
    {
        const int crow = tid >> 1;
        const int ccol = (tid & 1) * 32;
        const __half* qh = g_Q + headBase + (size_t)(qt * 128 + crow) * PD + ccol;
        const uint32_t so = (uint32_t)(crow * ATT_RS + ccol) * 2;
#pragma unroll
        for (int q = 0; q < 4; q++)
            *(uint4*)(sm + S_Q + so + q * 16) = *(const uint4*)(qh + q * 8);
    }

    const uint32_t qa = sb + S_Q + ((warp * 16 + (lane & 15)) * ATT_RS + (lane >> 4) * 8) * 2;
    // paired-K x4: rows = (lane&15) within 16-key span, k-col by lane>>4
    const uint32_t kb2_off = ((lane & 15) * ATT_RS + (lane >> 4) * 8) * 2;
    // paired-V x4.trans: rows (keys) = lane&15, d-col pair by lane>>4 (16 bytes)
    const uint32_t vb2_off = ((lane & 15) * ATT_RS) * 2 + (lane >> 4) * 16;

    float o[8][4];
#pragma unroll
    for (int nj = 0; nj < 8; nj++)
#pragma unroll
        for (int q = 0; q < 4; q++) o[nj][q] = 0.0f;
    float m0 = -3.0e38f, m1 = -3.0e38f, l0 = 0.0f, l1 = 0.0f;

#pragma unroll 1
    for (int kt = 0; kt < NKT; kt++) {
        if (kt + 1 < NKT) { CP_WAIT1(); } else { CP_WAIT0(); }
        __syncthreads();
        if (kt + 2 < NKT) KV_ISSUE(kt + 2);

        const uint32_t stage = sb + S_KV + (kt % 3) * KV_STAGE;
        const uint32_t kb = stage + kb2_off;
        const uint32_t vb = stage + KV_TILE + vb2_off;

        // ---- S = Q K^T (paired ldmatrix.x4 for K) ----
        float sa[8][4];
#pragma unroll
        for (int ni = 0; ni < 8; ni++)
#pragma unroll
            for (int q = 0; q < 4; q++) sa[ni][q] = 0.0f;

#pragma unroll
        for (int ks = 0; ks < 4; ks++) {
            uint32_t qh[4];
            ldsm_x4(qh, qa + ks * 32);
#pragma unroll
            for (int ni = 0; ni < 8; ni += 2) {
                uint32_t kr[4];
                ldsm_x4(kr, kb + ni * (8 * ATT_RS * 2) + ks * 32);
                uint32_t k0[2] = { kr[0], kr[2] };
                uint32_t k1[2] = { kr[1], kr[3] };
                mma_f16(sa[ni + 0], qh, k0);
                mma_f16(sa[ni + 1], qh, k1);
            }
        }

        // ---- scale(log2e) + bias + online softmax (log2 domain) ----
        float mx0 = -3.0e38f, mx1 = -3.0e38f;
#pragma unroll
        for (int ni = 0; ni < 8; ni++) {
            float2 bias = *(const float2*)(sm + S_BIAS + (kt * 64 + ni * 8 + (lane & 3) * 2) * 4);
            sa[ni][0] = sa[ni][0] * SC2 + bias.x;
            sa[ni][1] = sa[ni][1] * SC2 + bias.y;
            sa[ni][2] = sa[ni][2] * SC2 + bias.x;
            sa[ni][3] = sa[ni][3] * SC2 + bias.y;
            mx0 = fmaxf(mx0, fmaxf(sa[ni][0], sa[ni][1]));
            mx1 = fmaxf(mx1, fmaxf(sa[ni][2], sa[ni][3]));
        }
        mx0 = fmaxf(mx0, __shfl_xor_sync(0xffffffffu, mx0, 1));
        mx0 = fmaxf(mx0, __shfl_xor_sync(0xffffffffu, mx0, 2));
        mx1 = fmaxf(mx1, __shfl_xor_sync(0xffffffffu, mx1, 1));
        mx1 = fmaxf(mx1, __shfl_xor_sync(0xffffffffu, mx1, 2));

        float mn0 = fmaxf(m0, mx0);
        float mn1 = fmaxf(m1, mx1);
        float csc0 = ex2f(m0 - mn0);
        float csc1 = ex2f(m1 - mn1);
        m0 = mn0; m1 = mn1;

        float ls0 = 0.0f, ls1 = 0.0f;
#pragma unroll
        for (int ni = 0; ni < 8; ni++) {
            sa[ni][0] = ex2f(sa[ni][0] - mn0);
            sa[ni][1] = ex2f(sa[ni][1] - mn0);
            sa[ni][2] = ex2f(sa[ni][2] - mn1);
            sa[ni][3] = ex2f(sa[ni][3] - mn1);
            ls0 += sa[ni][0] + sa[ni][1];
            ls1 += sa[ni][2] + sa[ni][3];
        }
        ls0 += __shfl_xor_sync(0xffffffffu, ls0, 1);
        ls0 += __shfl_xor_sync(0xffffffffu, ls0, 2);
        ls1 += __shfl_xor_sync(0xffffffffu, ls1, 1);
        ls1 += __shfl_xor_sync(0xffffffffu, ls1, 2);
        l0 = l0 * csc0 + ls0;
        l1 = l1 * csc1 + ls1;

#pragma unroll
        for (int nj = 0; nj < 8; nj++) {
            o[nj][0] *= csc0; o[nj][1] *= csc0;
            o[nj][2] *= csc1; o[nj][3] *= csc1;
        }

        // ---- O += P V (paired ldmatrix.x4.trans for V) ----
#pragma unroll
        for (int ks = 0; ks < 4; ks++) {
            const float* t0 = sa[2 * ks];
            const float* t1 = sa[2 * ks + 1];
            uint32_t ah[4];
            ah[0] = packh2(t0[0], t0[1]);
            ah[1] = packh2(t0[2], t0[3]);
            ah[2] = packh2(t1[0], t1[1]);
            ah[3] = packh2(t1[2], t1[3]);
#pragma unroll
            for (int nj = 0; nj < 8; nj += 2) {
                uint32_t vr[4];
                ldsm_x4_t(vr, vb + ks * (16 * ATT_RS * 2) + nj * 16);
                uint32_t v0[2] = { vr[0], vr[1] };
                uint32_t v1[2] = { vr[2], vr[3] };
                mma_f16(o[nj + 0], ah, v0);
                mma_f16(o[nj + 1], ah, v1);
            }
        }
    }

    // ---- epilogue: gamma / l, write Ctx fp16 ----
    const float gsc = gamma[h];
    const float inv0 = gsc / l0;
    const float inv1 = gsc / l1;
    const int r0 = qt * 128 + warp * 16 + (lane >> 2);
    const size_t base0 = ((size_t)b * PS + r0) * PE + h * PD;
    const size_t base1 = base0 + (size_t)8 * PE;
#pragma unroll
    for (int nj = 0; nj < 8; nj++) {
        const int col = nj * 8 + (lane & 3) * 2;
        *(uint32_t*)&g_Ctx[base0 + col] = packh2(o[nj][0] * inv0, o[nj][1] * inv0);
        *(uint32_t*)&g_Ctx[base1 + col] = packh2(o[nj][2] * inv1, o[nj][3] * inv1);
    }
}

// ---------------------------------------------------------------------------
extern "C" void kernel_launch(void* const* d_in, const int* in_sizes, int n_in,
                              void* d_out, int out_size)
{
    const float* query = (const float*)d_in[0];
    const float* key   = (const float*)d_in[1];
    const float* value = (const float*)d_in[2];
    const unsigned char* mask = (const unsigned char*)d_in[3];
    const float* Wq = (const float*)d_in[4];
    const float* Wk = (const float*)d_in[5];
    const float* Wv = (const float*)d_in[6];
    const float* Wo = (const float*)d_in[7];
    const float* gamma = (const float*)d_in[8];

    cudaFuncSetAttribute(gemm_mma_kernel<false>,
                         cudaFuncAttributeMaxDynamicSharedMemorySize, GS_SMEM);
    cudaFuncSetAttribute(gemm_mma_kernel<true>,
                         cudaFuncAttributeMaxDynamicSharedMemorySize, GS_SMEM);
    cudaFuncSetAttribute(attn_mma_kernel,
                         cudaFuncAttributeMaxDynamicSharedMemorySize, ATT_SMEM);

    // prep: fp32 -> fp16 converts (2 launches)
    cvt_in_all_kernel<<<dim3(NEL / 4 / 256, 3), 256>>>(query, key, value);
    cvt_w_all_kernel<<<dim3(PE * PE / 4 / 256, 4), 256>>>(Wq, Wk, Wv, Wo);

    // fused Q/K/V projections: grid.x = 3 weights x 8 n-tiles
    gemm_mma_kernel<false><<<dim3(24, PM / 128), 256, GS_SMEM>>>(nullptr);

    attn_mma_kernel<<<dim3(PS / 128, PH, PB), 256, ATT_SMEM>>>(mask, gamma);

    gemm_mma_kernel<true><<<dim3(8, PM / 128), 256, GS_SMEM>>>((float*)d_out);
}